// round 1
// baseline (speedup 1.0000x reference)
#include <cuda_runtime.h>
#include <cuda_bf16.h>
#include <cstdint>

// Problem constants
#define N_USER 100000
#define N_ITEM 50000
#define NE     800000
#define H      128
#define NL     2
#define N_TGT  8192

// ---------------------------------------------------------------------------
// Static device scratch (no allocation allowed)
// ---------------------------------------------------------------------------
__device__ float g_xu[2][N_USER * H];      // user features after layer 0 / 1
__device__ float g_xi[2][N_ITEM * H];      // item features after layer 0 / 1
__device__ float g_mrev[N_USER * H];       // mean agg (rev_buys -> user)
__device__ float g_mfol[N_USER * H];       // mean agg (follows  -> user)
__device__ float g_mbuy[N_ITEM * H];       // mean agg (buys     -> item)
__device__ float g_wt[10 * H * H];         // pre-transposed / fused weights

__device__ int g_cnt[3][N_USER + 1];       // per-graph dst degree
__device__ int g_off[3][N_USER + 1];       // CSR offsets (exclusive scan)
__device__ int g_cur[3][N_USER];           // fill cursors
__device__ int g_csr[3][NE];               // CSR src indices

// graph ids: 0 = buys (dst=item, n=50000), 1 = rev (dst=user), 2 = fol (dst=user)

// ---------------------------------------------------------------------------
// CSR construction
// ---------------------------------------------------------------------------
__global__ void zero_cnt_kernel() {
    int i = blockIdx.x * blockDim.x + threadIdx.x;
    if (i < 3 * (N_USER + 1)) ((int*)g_cnt)[i] = 0;
}

__global__ void count_kernel(const int* __restrict__ dst, int g) {
    int i = blockIdx.x * blockDim.x + threadIdx.x;
    if (i < NE) atomicAdd(&g_cnt[g][dst[i]], 1);
}

// One block per graph; sequential 1024-chunk scan with warp shuffles.
__global__ void scan3_kernel() {
    int g = blockIdx.x;
    int n = (g == 0) ? N_ITEM : N_USER;
    const int* cnt = g_cnt[g];
    int* off = g_off[g];
    __shared__ int warp_sums[32];
    __shared__ int s_carry;
    if (threadIdx.x == 0) s_carry = 0;
    __syncthreads();
    int lane = threadIdx.x & 31, wid = threadIdx.x >> 5;
    for (int base = 0; base < n; base += 1024) {
        int i = base + (int)threadIdx.x;
        int v = (i < n) ? cnt[i] : 0;
        int x = v;
        #pragma unroll
        for (int s = 1; s < 32; s <<= 1) {
            int y = __shfl_up_sync(0xffffffffu, x, s);
            if (lane >= s) x += y;
        }
        if (lane == 31) warp_sums[wid] = x;
        __syncthreads();
        if (wid == 0) {
            int w = warp_sums[lane];
            int xw = w;
            #pragma unroll
            for (int s = 1; s < 32; s <<= 1) {
                int y = __shfl_up_sync(0xffffffffu, xw, s);
                if (lane >= s) xw += y;
            }
            warp_sums[lane] = xw - w;  // exclusive warp offsets
        }
        __syncthreads();
        int incl = x + warp_sums[wid];
        int carry = s_carry;
        __syncthreads();
        if (i < n) off[i] = carry + incl - v;
        if (threadIdx.x == 1023) s_carry = carry + incl;
        __syncthreads();
    }
    if (threadIdx.x == 0) off[n] = s_carry;
}

__global__ void cursor_init_kernel() {
    int i = blockIdx.x * blockDim.x + threadIdx.x;
    if (i < 3 * N_USER) {
        int g = i / N_USER, j = i % N_USER;
        g_cur[g][j] = g_off[g][j];
    }
}

__global__ void fill_kernel(const int* __restrict__ dst, const int* __restrict__ src, int g) {
    int i = blockIdx.x * blockDim.x + threadIdx.x;
    if (i < NE) {
        int d = dst[i];
        int pos = atomicAdd(&g_cur[g][d], 1);
        g_csr[g][pos] = src[i];
    }
}

// ---------------------------------------------------------------------------
// Weight prep: transpose Wl / Wr into [k][j] layout, fuse user's two Wr mats.
// slot s per layer: 0..2 = Wl(buys,rev,fol), 3 = Wr_item, 4 = Wr1+Wr2 (user)
// ---------------------------------------------------------------------------
__global__ void wprep_kernel(const float* __restrict__ Wl, const float* __restrict__ Wr) {
    int idx = blockIdx.x * blockDim.x + threadIdx.x;
    if (idx >= 10 * H * H) return;
    int slot = idx >> 14;          // /16384
    int kj = idx & 16383;
    int k = kj >> 7, j = kj & 127;
    int l = slot / 5, s = slot % 5;
    float v;
    if (s < 3)       v = Wl[(((l * 3 + s) * H) + j) * H + k];
    else if (s == 3) v = Wr[(((l * 3 + 0) * H) + j) * H + k];
    else             v = Wr[(((l * 3 + 1) * H) + j) * H + k] +
                         Wr[(((l * 3 + 2) * H) + j) * H + k];
    g_wt[idx] = v;
}

// ---------------------------------------------------------------------------
// Gather-side mean aggregation: one warp per dst node, float4 lanes.
// ---------------------------------------------------------------------------
__global__ void agg_kernel(const float* __restrict__ xsrc, int g,
                           float* __restrict__ mean, int ndst) {
    int warp = (blockIdx.x * blockDim.x + threadIdx.x) >> 5;
    int lane = threadIdx.x & 31;
    if (warp >= ndst) return;
    int s = g_off[g][warp], e = g_off[g][warp + 1];
    float4 acc = make_float4(0.f, 0.f, 0.f, 0.f);
    for (int i = s; i < e; i++) {
        int sid = g_csr[g][i];
        float4 v = *(const float4*)(xsrc + (size_t)sid * H + lane * 4);
        acc.x += v.x; acc.y += v.y; acc.z += v.z; acc.w += v.w;
    }
    float inv = (e > s) ? 1.0f / (float)(e - s) : 0.0f;
    *(float4*)(mean + (size_t)warp * H + lane * 4) =
        make_float4(acc.x * inv, acc.y * inv, acc.z * inv, acc.w * inv);
}

// ---------------------------------------------------------------------------
// SGEMM: out[n][j] = bias(j) + sum over up to 3 segments of A_s[n][:] . Wt_s[:][j]
// Tile: 64 rows x 128 cols, 256 threads, each thread 8 rows x 4 cols.
// Wt is pre-transposed: Wt[k*128 + j] = W[j][k].
// Dynamic smem: Wsm 64KB + Asm 32KB = 96KB -> 2 CTA/SM.
// ---------------------------------------------------------------------------
extern __shared__ float g_sm[];

__global__ void __launch_bounds__(256) gemm3_kernel(
    float* __restrict__ out,
    const float* __restrict__ A0, const float* __restrict__ Wt0,
    const float* __restrict__ A1, const float* __restrict__ Wt1,
    const float* __restrict__ A2, const float* __restrict__ Wt2,
    const float* __restrict__ bias0, const float* __restrict__ bias1,
    int nrows)
{
    float* Wsm = g_sm;            // 128*128
    float* Asm = g_sm + H * H;    // 64*128
    int t = threadIdx.x;
    int row0 = blockIdx.x * 64;
    int jc = (t & 31) * 4;        // 4 output cols
    int r0 = (t >> 5) * 8;        // 8 output rows

    float4 bv = *(const float4*)(bias0 + jc);
    if (bias1) {
        float4 b1v = *(const float4*)(bias1 + jc);
        bv.x += b1v.x; bv.y += b1v.y; bv.z += b1v.z; bv.w += b1v.w;
    }
    float4 acc[8];
    #pragma unroll
    for (int r = 0; r < 8; r++) acc[r] = bv;

    const float* As[3] = {A0, A1, A2};
    const float* Ws[3] = {Wt0, Wt1, Wt2};

    #pragma unroll
    for (int seg = 0; seg < 3; seg++) {
        const float* A = As[seg];
        if (A == nullptr) break;
        const float* Wt = Ws[seg];
        __syncthreads();
        // Load Wt tile: 4096 float4, 16 per thread (coalesced, conflict-free)
        #pragma unroll
        for (int i = 0; i < 16; i++) {
            int idx = t + 256 * i;
            ((float4*)Wsm)[idx] = ((const float4*)Wt)[idx];
        }
        // Load A tile: 2048 float4, 8 per thread
        #pragma unroll
        for (int i = 0; i < 8; i++) {
            int idx = t + 256 * i;
            int r = idx >> 5, c = idx & 31;
            float4 v = make_float4(0.f, 0.f, 0.f, 0.f);
            if (row0 + r < nrows)
                v = ((const float4*)(A + (size_t)(row0 + r) * H))[c];
            ((float4*)Asm)[idx] = v;
        }
        __syncthreads();
        #pragma unroll 4
        for (int k = 0; k < H; k++) {
            float4 w = *(float4*)(Wsm + k * H + jc);
            #pragma unroll
            for (int r = 0; r < 8; r++) {
                float a = Asm[(r0 + r) * H + k];
                acc[r].x += a * w.x; acc[r].y += a * w.y;
                acc[r].z += a * w.z; acc[r].w += a * w.w;
            }
        }
    }
    #pragma unroll
    for (int r = 0; r < 8; r++) {
        int row = row0 + r0 + r;
        if (row < nrows)
            *(float4*)(out + (size_t)row * H + jc) = acc[r];
    }
}

// ---------------------------------------------------------------------------
// LayerNorm + ReLU, in place, one warp per row.
// ---------------------------------------------------------------------------
__global__ void ln_relu_kernel(float* __restrict__ x,
                               const float* __restrict__ gam,
                               const float* __restrict__ bet, int n) {
    int row = (blockIdx.x * blockDim.x + threadIdx.x) >> 5;
    int lane = threadIdx.x & 31;
    if (row >= n) return;
    float4 v = *(float4*)(x + (size_t)row * H + lane * 4);
    float s1 = v.x + v.y + v.z + v.w;
    float s2 = v.x * v.x + v.y * v.y + v.z * v.z + v.w * v.w;
    #pragma unroll
    for (int o = 16; o; o >>= 1) {
        s1 += __shfl_xor_sync(0xffffffffu, s1, o);
        s2 += __shfl_xor_sync(0xffffffffu, s2, o);
    }
    float mu = s1 * (1.0f / H);
    float var = s2 * (1.0f / H) - mu * mu;
    float rs = rsqrtf(var + 1e-5f);
    float4 gg = *(const float4*)(gam + lane * 4);
    float4 bb = *(const float4*)(bet + lane * 4);
    v.x = fmaxf((v.x - mu) * rs * gg.x + bb.x, 0.f);
    v.y = fmaxf((v.y - mu) * rs * gg.y + bb.y, 0.f);
    v.z = fmaxf((v.z - mu) * rs * gg.z + bb.z, 0.f);
    v.w = fmaxf((v.w - mu) * rs * gg.w + bb.w, 0.f);
    *(float4*)(x + (size_t)row * H + lane * 4) = v;
}

// ---------------------------------------------------------------------------
// MLP head: one warp per target. h = relu(x@W1^T + b1); out = h@W2^T + b2.
// ---------------------------------------------------------------------------
__global__ void mlp_kernel(const float* __restrict__ xu,
                           const int* __restrict__ tgt,
                           const float* __restrict__ W1, const float* __restrict__ b1,
                           const float* __restrict__ W2, const float* __restrict__ b2,
                           float* __restrict__ out) {
    int warp = (blockIdx.x * blockDim.x + threadIdx.x) >> 5;
    int lane = threadIdx.x & 31;
    if (warp >= N_TGT) return;
    int t = tgt[warp];
    float4 xv = *(const float4*)(xu + (size_t)t * H + lane * 4);
    float acc = 0.f;
    #pragma unroll 4
    for (int j = 0; j < 64; j++) {
        float4 w = *(const float4*)(W1 + j * H + lane * 4);
        float p = xv.x * w.x + xv.y * w.y + xv.z * w.z + xv.w * w.w;
        #pragma unroll
        for (int o = 16; o; o >>= 1) p += __shfl_xor_sync(0xffffffffu, p, o);
        float h = fmaxf(p + b1[j], 0.f);
        acc += h * W2[j];
    }
    if (lane == 0) out[warp] = acc + b2[0];
}

// ---------------------------------------------------------------------------
// Launch
// ---------------------------------------------------------------------------
extern "C" void kernel_launch(void* const* d_in, const int* in_sizes, int n_in,
                              void* d_out, int out_size) {
    const float* emb_user = (const float*)d_in[0];
    const float* emb_item = (const float*)d_in[1];
    const float* Wl       = (const float*)d_in[2];
    const float* bl       = (const float*)d_in[3];
    const float* Wr       = (const float*)d_in[4];
    const float* ln_g     = (const float*)d_in[5];
    const float* ln_b     = (const float*)d_in[6];
    const float* W1       = (const float*)d_in[7];
    const float* b1       = (const float*)d_in[8];
    const float* W2       = (const float*)d_in[9];
    const float* b2       = (const float*)d_in[10];
    const int* src_buys   = (const int*)d_in[11];
    const int* dst_buys   = (const int*)d_in[12];
    const int* src_rev    = (const int*)d_in[13];
    const int* dst_rev    = (const int*)d_in[14];
    const int* src_fol    = (const int*)d_in[15];
    const int* dst_fol    = (const int*)d_in[16];
    const int* target_ids = (const int*)d_in[17];
    float* out = (float*)d_out;

    float *p_xu, *p_xi, *p_mrev, *p_mfol, *p_mbuy, *p_wt;
    cudaGetSymbolAddress((void**)&p_xu,  g_xu);
    cudaGetSymbolAddress((void**)&p_xi,  g_xi);
    cudaGetSymbolAddress((void**)&p_mrev, g_mrev);
    cudaGetSymbolAddress((void**)&p_mfol, g_mfol);
    cudaGetSymbolAddress((void**)&p_mbuy, g_mbuy);
    cudaGetSymbolAddress((void**)&p_wt,  g_wt);

    const int smem_bytes = (H * H + 64 * H) * sizeof(float);  // 96KB
    cudaFuncSetAttribute(gemm3_kernel,
                         cudaFuncAttributeMaxDynamicSharedMemorySize, smem_bytes);

    // --- CSR build (once; shared by both layers) ---
    zero_cnt_kernel<<<(3 * (N_USER + 1) + 255) / 256, 256>>>();
    count_kernel<<<(NE + 255) / 256, 256>>>(dst_buys, 0);
    count_kernel<<<(NE + 255) / 256, 256>>>(dst_rev, 1);
    count_kernel<<<(NE + 255) / 256, 256>>>(dst_fol, 2);
    scan3_kernel<<<3, 1024>>>();
    cursor_init_kernel<<<(3 * N_USER + 255) / 256, 256>>>();
    fill_kernel<<<(NE + 255) / 256, 256>>>(dst_buys, src_buys, 0);
    fill_kernel<<<(NE + 255) / 256, 256>>>(dst_rev, src_rev, 1);
    fill_kernel<<<(NE + 255) / 256, 256>>>(dst_fol, src_fol, 2);

    // --- weight prep ---
    wprep_kernel<<<(10 * H * H + 255) / 256, 256>>>(Wl, Wr);

    const float* xu_in = emb_user;
    const float* xi_in = emb_item;

    for (int l = 0; l < NL; l++) {
        float* xu_out = p_xu + (size_t)l * N_USER * H;
        float* xi_out = p_xi + (size_t)l * N_ITEM * H;
        const float* wt = p_wt + (size_t)l * 5 * H * H;

        // aggregation
        agg_kernel<<<(N_ITEM + 7) / 8, 256>>>(xu_in, 0, p_mbuy, N_ITEM);
        agg_kernel<<<(N_USER + 7) / 8, 256>>>(xi_in, 1, p_mrev, N_USER);
        agg_kernel<<<(N_USER + 7) / 8, 256>>>(xu_in, 2, p_mfol, N_USER);

        // item: mean_buys@Wl0^T + xi@Wr0^T + bl0
        gemm3_kernel<<<(N_ITEM + 63) / 64, 256, smem_bytes>>>(
            xi_out,
            p_mbuy, wt + 0 * H * H,
            xi_in,  wt + 3 * H * H,
            nullptr, nullptr,
            bl + (l * 3 + 0) * H, nullptr,
            N_ITEM);
        // user: mean_rev@Wl1^T + mean_fol@Wl2^T + xu@(Wr1+Wr2)^T + bl1 + bl2
        gemm3_kernel<<<(N_USER + 63) / 64, 256, smem_bytes>>>(
            xu_out,
            p_mrev, wt + 1 * H * H,
            p_mfol, wt + 2 * H * H,
            xu_in,  wt + 4 * H * H,
            bl + (l * 3 + 1) * H, bl + (l * 3 + 2) * H,
            N_USER);

        // LayerNorm + ReLU (in place)
        ln_relu_kernel<<<(N_USER * 32 + 255) / 256, 256>>>(
            xu_out, ln_g + (l * 2 + 0) * H, ln_b + (l * 2 + 0) * H, N_USER);
        ln_relu_kernel<<<(N_ITEM * 32 + 255) / 256, 256>>>(
            xi_out, ln_g + (l * 2 + 1) * H, ln_b + (l * 2 + 1) * H, N_ITEM);

        xu_in = xu_out;
        xi_in = xi_out;
    }

    // --- MLP head ---
    mlp_kernel<<<(N_TGT * 32 + 255) / 256, 256>>>(
        xu_in, target_ids, W1, b1, W2, b2, out);
}

// round 2
// speedup vs baseline: 1.6559x; 1.6559x over previous
#include <cuda_runtime.h>
#include <cuda_bf16.h>
#include <cstdint>

// Problem constants
#define N_USER 100000
#define N_ITEM 50000
#define NE     800000
#define H      128
#define NL     2
#define N_TGT  8192

// ---------------------------------------------------------------------------
// Static device scratch
// ---------------------------------------------------------------------------
__device__ float g_xu[2][N_USER * H];
__device__ float g_xi[2][N_ITEM * H];
__device__ float g_mrev[N_USER * H];
__device__ float g_mfol[N_USER * H];
__device__ float g_mbuy[N_ITEM * H];
__device__ unsigned g_wt[10 * H * H];      // pre-transposed weights, tf32 bits

__device__ int g_cnt[3][N_USER + 1];
__device__ int g_off[3][N_USER + 1];
__device__ int g_cur[3][N_USER];
__device__ int g_csr[3][NE];

// graph ids: 0 = buys (dst=item), 1 = rev (dst=user), 2 = fol (dst=user)

__device__ __forceinline__ unsigned f2tf32(float f) {
    unsigned r;
    asm("cvt.rna.tf32.f32 %0, %1;" : "=r"(r) : "f"(f));
    return r;
}

// ---------------------------------------------------------------------------
// CSR construction
// ---------------------------------------------------------------------------
__global__ void zero_cnt_kernel() {
    int i = blockIdx.x * blockDim.x + threadIdx.x;
    if (i < 3 * (N_USER + 1)) ((int*)g_cnt)[i] = 0;
}

__global__ void count_all_kernel(const int* __restrict__ d0,
                                 const int* __restrict__ d1,
                                 const int* __restrict__ d2) {
    int i = blockIdx.x * blockDim.x + threadIdx.x;
    if (i >= 3 * NE) return;
    int g = i / NE, j = i % NE;
    const int* d = (g == 0) ? d0 : (g == 1) ? d1 : d2;
    atomicAdd(&g_cnt[g][d[j]], 1);
}

__global__ void scan3_kernel() {
    int g = blockIdx.x;
    int n = (g == 0) ? N_ITEM : N_USER;
    const int* cnt = g_cnt[g];
    int* off = g_off[g];
    __shared__ int warp_sums[32];
    __shared__ int s_carry;
    if (threadIdx.x == 0) s_carry = 0;
    __syncthreads();
    int lane = threadIdx.x & 31, wid = threadIdx.x >> 5;
    for (int base = 0; base < n; base += 1024) {
        int i = base + (int)threadIdx.x;
        int v = (i < n) ? cnt[i] : 0;
        int x = v;
        #pragma unroll
        for (int s = 1; s < 32; s <<= 1) {
            int y = __shfl_up_sync(0xffffffffu, x, s);
            if (lane >= s) x += y;
        }
        if (lane == 31) warp_sums[wid] = x;
        __syncthreads();
        if (wid == 0) {
            int w = warp_sums[lane];
            int xw = w;
            #pragma unroll
            for (int s = 1; s < 32; s <<= 1) {
                int y = __shfl_up_sync(0xffffffffu, xw, s);
                if (lane >= s) xw += y;
            }
            warp_sums[lane] = xw - w;
        }
        __syncthreads();
        int incl = x + warp_sums[wid];
        int carry = s_carry;
        __syncthreads();
        if (i < n) off[i] = carry + incl - v;
        if (threadIdx.x == 1023) s_carry = carry + incl;
        __syncthreads();
    }
    if (threadIdx.x == 0) off[n] = s_carry;
}

__global__ void cursor_init_kernel() {
    int i = blockIdx.x * blockDim.x + threadIdx.x;
    if (i < 3 * N_USER) {
        int g = i / N_USER, j = i % N_USER;
        g_cur[g][j] = g_off[g][j];
    }
}

__global__ void fill_all_kernel(const int* __restrict__ d0, const int* __restrict__ s0,
                                const int* __restrict__ d1, const int* __restrict__ s1,
                                const int* __restrict__ d2, const int* __restrict__ s2) {
    int i = blockIdx.x * blockDim.x + threadIdx.x;
    if (i >= 3 * NE) return;
    int g = i / NE, j = i % NE;
    const int* d = (g == 0) ? d0 : (g == 1) ? d1 : d2;
    const int* s = (g == 0) ? s0 : (g == 1) ? s1 : s2;
    int dd = d[j];
    int pos = atomicAdd(&g_cur[g][dd], 1);
    g_csr[g][pos] = s[j];
}

// ---------------------------------------------------------------------------
// Weight prep: transpose to [k][j], fuse user's two Wr, convert to tf32 bits.
// slot s per layer: 0..2 = Wl(buys,rev,fol), 3 = Wr_item, 4 = Wr1+Wr2 (user)
// ---------------------------------------------------------------------------
__global__ void wprep_kernel(const float* __restrict__ Wl, const float* __restrict__ Wr) {
    int idx = blockIdx.x * blockDim.x + threadIdx.x;
    if (idx >= 10 * H * H) return;
    int slot = idx >> 14;
    int kj = idx & 16383;
    int k = kj >> 7, j = kj & 127;
    int l = slot / 5, s = slot % 5;
    float v;
    if (s < 3)       v = Wl[(((l * 3 + s) * H) + j) * H + k];
    else if (s == 3) v = Wr[(((l * 3 + 0) * H) + j) * H + k];
    else             v = Wr[(((l * 3 + 1) * H) + j) * H + k] +
                         Wr[(((l * 3 + 2) * H) + j) * H + k];
    g_wt[idx] = f2tf32(v);
}

// ---------------------------------------------------------------------------
// Gather-side mean aggregation: one warp per dst node, float4 lanes.
// ---------------------------------------------------------------------------
__global__ void agg_kernel(const float* __restrict__ xsrc, int g,
                           float* __restrict__ mean, int ndst) {
    int warp = (blockIdx.x * blockDim.x + threadIdx.x) >> 5;
    int lane = threadIdx.x & 31;
    if (warp >= ndst) return;
    int s = g_off[g][warp], e = g_off[g][warp + 1];
    float4 acc = make_float4(0.f, 0.f, 0.f, 0.f);
    for (int i = s; i < e; i++) {
        int sid = g_csr[g][i];
        float4 v = *(const float4*)(xsrc + (size_t)sid * H + lane * 4);
        acc.x += v.x; acc.y += v.y; acc.z += v.z; acc.w += v.w;
    }
    float inv = (e > s) ? 1.0f / (float)(e - s) : 0.0f;
    *(float4*)(mean + (size_t)warp * H + lane * 4) =
        make_float4(acc.x * inv, acc.y * inv, acc.z * inv, acc.w * inv);
}

// ---------------------------------------------------------------------------
// TF32 tensor-core GEMM + fused LayerNorm + ReLU epilogue.
//   out[n][j] = LNReLU( bias(j) + sum_seg A_s[n][:] . Wt_s[:][j] )
// CTA tile: 128 rows x 128 cols, 256 threads = 8 warps (4 m-warps x 2 n-warps).
// Warp tile: 32 rows x 64 cols = 2 x 8 m16n8k8 tiles. K chunked by 32.
// Smem (union): mainloop A(128x36 u32) + W(32x132 u32) = 35KB;
//               epilogue  O(128x132 f32) = 66KB. Dyn smem = 66KB.
// ---------------------------------------------------------------------------
#define ASTRIDE 36
#define WSTRIDE 132
#define OSTRIDE 132

extern __shared__ char g_smraw[];

__device__ __forceinline__ void mma_tf32(float c[4], const unsigned a[4], const unsigned b[2]) {
    asm volatile(
        "mma.sync.aligned.m16n8k8.row.col.f32.tf32.tf32.f32 "
        "{%0,%1,%2,%3}, {%4,%5,%6,%7}, {%8,%9}, {%0,%1,%2,%3};"
        : "+f"(c[0]), "+f"(c[1]), "+f"(c[2]), "+f"(c[3])
        : "r"(a[0]), "r"(a[1]), "r"(a[2]), "r"(a[3]), "r"(b[0]), "r"(b[1]));
}

__global__ void __launch_bounds__(256, 2) gemm_ln_kernel(
    float* __restrict__ out,
    const float* __restrict__ A0, const unsigned* __restrict__ Wt0,
    const float* __restrict__ A1, const unsigned* __restrict__ Wt1,
    const float* __restrict__ A2, const unsigned* __restrict__ Wt2,
    const float* __restrict__ bias0, const float* __restrict__ bias1,
    const float* __restrict__ gam, const float* __restrict__ bet,
    int nrows)
{
    unsigned* Asm = (unsigned*)g_smraw;                 // 128*36
    unsigned* Wsm = Asm + 128 * ASTRIDE;                // 32*132
    float*    Osm = (float*)g_smraw;                    // 128*132 (epilogue)

    int t = threadIdx.x;
    int lane = t & 31;
    int wid = t >> 5;
    int warp_m = wid & 3;          // 0..3 -> 32-row slice
    int warp_n = wid >> 2;         // 0..1 -> 64-col slice
    int gid = lane >> 2;           // 0..7
    int tig = lane & 3;            // 0..3
    int row0 = blockIdx.x * 128;

    // accumulators, init with bias
    float c[2][8][4];
    #pragma unroll
    for (int nt = 0; nt < 8; nt++) {
        int col = warp_n * 64 + nt * 8 + 2 * tig;
        float b0 = bias0[col], b1 = bias0[col + 1];
        if (bias1) { b0 += bias1[col]; b1 += bias1[col + 1]; }
        #pragma unroll
        for (int mt = 0; mt < 2; mt++) {
            c[mt][nt][0] = b0; c[mt][nt][1] = b1;
            c[mt][nt][2] = b0; c[mt][nt][3] = b1;
        }
    }

    const float*    As[3] = {A0, A1, A2};
    const unsigned* Ws[3] = {Wt0, Wt1, Wt2};

    for (int seg = 0; seg < 3; seg++) {
        const float* A = As[seg];
        if (A == nullptr) break;
        const unsigned* Wt = Ws[seg];

        for (int kb = 0; kb < 4; kb++) {         // K chunks of 32
            __syncthreads();
            // load A chunk: 128 rows x 32 k (8 float4/row), convert to tf32
            #pragma unroll
            for (int i = 0; i < 4; i++) {
                int idx = t + 256 * i;           // 0..1023
                int r = idx >> 3, c4 = idx & 7;
                float4 v = make_float4(0.f, 0.f, 0.f, 0.f);
                if (row0 + r < nrows)
                    v = ((const float4*)(A + (size_t)(row0 + r) * H + kb * 32))[c4];
                uint4 u = make_uint4(f2tf32(v.x), f2tf32(v.y), f2tf32(v.z), f2tf32(v.w));
                *(uint4*)(Asm + r * ASTRIDE + c4 * 4) = u;
            }
            // load W chunk: 32 k-rows x 128 j (already tf32)
            #pragma unroll
            for (int i = 0; i < 4; i++) {
                int idx = t + 256 * i;           // 0..1023
                int rr = idx >> 5, c4 = idx & 31;
                uint4 u = ((const uint4*)(Wt + (size_t)(kb * 32 + rr) * H))[c4];
                *(uint4*)(Wsm + rr * WSTRIDE + c4 * 4) = u;
            }
            __syncthreads();

            #pragma unroll
            for (int ks = 0; ks < 4; ks++) {     // 4 k-steps of 8
                int k0 = ks * 8;
                unsigned a[2][4];
                #pragma unroll
                for (int mt = 0; mt < 2; mt++) {
                    int r = warp_m * 32 + mt * 16 + gid;
                    a[mt][0] = Asm[r * ASTRIDE + k0 + tig];
                    a[mt][1] = Asm[(r + 8) * ASTRIDE + k0 + tig];
                    a[mt][2] = Asm[r * ASTRIDE + k0 + tig + 4];
                    a[mt][3] = Asm[(r + 8) * ASTRIDE + k0 + tig + 4];
                }
                unsigned b[8][2];
                #pragma unroll
                for (int nt = 0; nt < 8; nt++) {
                    int cc = warp_n * 64 + nt * 8 + gid;
                    b[nt][0] = Wsm[(k0 + tig) * WSTRIDE + cc];
                    b[nt][1] = Wsm[(k0 + tig + 4) * WSTRIDE + cc];
                }
                #pragma unroll
                for (int mt = 0; mt < 2; mt++)
                    #pragma unroll
                    for (int nt = 0; nt < 8; nt++)
                        mma_tf32(c[mt][nt], a[mt], b[nt]);
            }
        }
    }

    // ---- epilogue: stage to smem, fused LayerNorm + ReLU ----
    __syncthreads();   // mainloop smem reads done before Osm overwrite
    #pragma unroll
    for (int mt = 0; mt < 2; mt++) {
        #pragma unroll
        for (int nt = 0; nt < 8; nt++) {
            int col = warp_n * 64 + nt * 8 + 2 * tig;
            int r = warp_m * 32 + mt * 16 + gid;
            *(float2*)(Osm + r * OSTRIDE + col)       = make_float2(c[mt][nt][0], c[mt][nt][1]);
            *(float2*)(Osm + (r + 8) * OSTRIDE + col) = make_float2(c[mt][nt][2], c[mt][nt][3]);
        }
    }
    __syncthreads();

    float4 gg = *(const float4*)(gam + lane * 4);
    float4 bb = *(const float4*)(bet + lane * 4);
    #pragma unroll
    for (int i = 0; i < 16; i++) {
        int r = wid * 16 + i;
        if (row0 + r >= nrows) break;
        float4 v = *(float4*)(Osm + r * OSTRIDE + lane * 4);
        float s1 = v.x + v.y + v.z + v.w;
        float s2 = v.x * v.x + v.y * v.y + v.z * v.z + v.w * v.w;
        #pragma unroll
        for (int o = 16; o; o >>= 1) {
            s1 += __shfl_xor_sync(0xffffffffu, s1, o);
            s2 += __shfl_xor_sync(0xffffffffu, s2, o);
        }
        float mu = s1 * (1.0f / H);
        float var = s2 * (1.0f / H) - mu * mu;
        float rs = rsqrtf(var + 1e-5f);
        float4 o4;
        o4.x = fmaxf((v.x - mu) * rs * gg.x + bb.x, 0.f);
        o4.y = fmaxf((v.y - mu) * rs * gg.y + bb.y, 0.f);
        o4.z = fmaxf((v.z - mu) * rs * gg.z + bb.z, 0.f);
        o4.w = fmaxf((v.w - mu) * rs * gg.w + bb.w, 0.f);
        *(float4*)(out + (size_t)(row0 + r) * H + lane * 4) = o4;
    }
}

// ---------------------------------------------------------------------------
// MLP head: one warp per target.
// ---------------------------------------------------------------------------
__global__ void mlp_kernel(const float* __restrict__ xu,
                           const int* __restrict__ tgt,
                           const float* __restrict__ W1, const float* __restrict__ b1,
                           const float* __restrict__ W2, const float* __restrict__ b2,
                           float* __restrict__ out) {
    int warp = (blockIdx.x * blockDim.x + threadIdx.x) >> 5;
    int lane = threadIdx.x & 31;
    if (warp >= N_TGT) return;
    int t = tgt[warp];
    float4 xv = *(const float4*)(xu + (size_t)t * H + lane * 4);
    float acc = 0.f;
    #pragma unroll 4
    for (int j = 0; j < 64; j++) {
        float4 w = *(const float4*)(W1 + j * H + lane * 4);
        float p = xv.x * w.x + xv.y * w.y + xv.z * w.z + xv.w * w.w;
        #pragma unroll
        for (int o = 16; o; o >>= 1) p += __shfl_xor_sync(0xffffffffu, p, o);
        float h = fmaxf(p + b1[j], 0.f);
        acc += h * W2[j];
    }
    if (lane == 0) out[warp] = acc + b2[0];
}

// ---------------------------------------------------------------------------
// Launch
// ---------------------------------------------------------------------------
extern "C" void kernel_launch(void* const* d_in, const int* in_sizes, int n_in,
                              void* d_out, int out_size) {
    const float* emb_user = (const float*)d_in[0];
    const float* emb_item = (const float*)d_in[1];
    const float* Wl       = (const float*)d_in[2];
    const float* bl       = (const float*)d_in[3];
    const float* Wr       = (const float*)d_in[4];
    const float* ln_g     = (const float*)d_in[5];
    const float* ln_b     = (const float*)d_in[6];
    const float* W1       = (const float*)d_in[7];
    const float* b1       = (const float*)d_in[8];
    const float* W2       = (const float*)d_in[9];
    const float* b2       = (const float*)d_in[10];
    const int* src_buys   = (const int*)d_in[11];
    const int* dst_buys   = (const int*)d_in[12];
    const int* src_rev    = (const int*)d_in[13];
    const int* dst_rev    = (const int*)d_in[14];
    const int* src_fol    = (const int*)d_in[15];
    const int* dst_fol    = (const int*)d_in[16];
    const int* target_ids = (const int*)d_in[17];
    float* out = (float*)d_out;

    float *p_xu, *p_xi, *p_mrev, *p_mfol, *p_mbuy;
    unsigned* p_wt;
    cudaGetSymbolAddress((void**)&p_xu,  g_xu);
    cudaGetSymbolAddress((void**)&p_xi,  g_xi);
    cudaGetSymbolAddress((void**)&p_mrev, g_mrev);
    cudaGetSymbolAddress((void**)&p_mfol, g_mfol);
    cudaGetSymbolAddress((void**)&p_mbuy, g_mbuy);
    cudaGetSymbolAddress((void**)&p_wt,  g_wt);

    const int smem_bytes = 128 * OSTRIDE * sizeof(float);  // ~66KB
    static int smem_set = 0;
    if (!smem_set) {
        cudaFuncSetAttribute(gemm_ln_kernel,
                             cudaFuncAttributeMaxDynamicSharedMemorySize, smem_bytes);
        smem_set = 1;
    }

    // --- CSR build ---
    zero_cnt_kernel<<<(3 * (N_USER + 1) + 255) / 256, 256>>>();
    count_all_kernel<<<(3 * NE + 255) / 256, 256>>>(dst_buys, dst_rev, dst_fol);
    scan3_kernel<<<3, 1024>>>();
    cursor_init_kernel<<<(3 * N_USER + 255) / 256, 256>>>();
    fill_all_kernel<<<(3 * NE + 255) / 256, 256>>>(dst_buys, src_buys,
                                                   dst_rev, src_rev,
                                                   dst_fol, src_fol);
    // --- weight prep ---
    wprep_kernel<<<(10 * H * H + 255) / 256, 256>>>(Wl, Wr);

    const float* xu_in = emb_user;
    const float* xi_in = emb_item;

    for (int l = 0; l < NL; l++) {
        float* xu_out = p_xu + (size_t)l * N_USER * H;
        float* xi_out = p_xi + (size_t)l * N_ITEM * H;
        const unsigned* wt = p_wt + (size_t)l * 5 * H * H;

        agg_kernel<<<(N_ITEM + 7) / 8, 256>>>(xu_in, 0, p_mbuy, N_ITEM);
        agg_kernel<<<(N_USER + 7) / 8, 256>>>(xi_in, 1, p_mrev, N_USER);
        agg_kernel<<<(N_USER + 7) / 8, 256>>>(xu_in, 2, p_mfol, N_USER);

        // item: mean_buys@Wl0^T + xi@Wr0^T + bl0 -> LN -> ReLU
        gemm_ln_kernel<<<(N_ITEM + 127) / 128, 256, smem_bytes>>>(
            xi_out,
            p_mbuy, wt + 0 * H * H,
            xi_in,  wt + 3 * H * H,
            nullptr, nullptr,
            bl + (l * 3 + 0) * H, nullptr,
            ln_g + (l * 2 + 1) * H, ln_b + (l * 2 + 1) * H,
            N_ITEM);
        // user: mean_rev@Wl1^T + mean_fol@Wl2^T + xu@(Wr1+Wr2)^T + bl1+bl2 -> LN -> ReLU
        gemm_ln_kernel<<<(N_USER + 127) / 128, 256, smem_bytes>>>(
            xu_out,
            p_mrev, wt + 1 * H * H,
            p_mfol, wt + 2 * H * H,
            xu_in,  wt + 4 * H * H,
            bl + (l * 3 + 1) * H, bl + (l * 3 + 2) * H,
            ln_g + (l * 2 + 0) * H, ln_b + (l * 2 + 0) * H,
            N_USER);

        xu_in = xu_out;
        xi_in = xi_out;
    }

    mlp_kernel<<<(N_TGT * 32 + 255) / 256, 256>>>(
        xu_in, target_ids, W1, b1, W2, b2, out);
}

// round 3
// speedup vs baseline: 2.2648x; 1.3677x over previous
#include <cuda_runtime.h>
#include <cuda_bf16.h>
#include <cstdint>

#define N_USER 100000
#define N_ITEM 50000
#define NE     800000
#define H      128
#define N_TGT  8192

#define NBLK_U 98   // ceil(100000/1024)
#define NBLK_I 49   // ceil(50000/1024)

// ---------------------------------------------------------------------------
// Static device scratch
// ---------------------------------------------------------------------------
__device__ float g_xu0[N_USER * H];        // user features after layer 0
__device__ float g_xi0[N_ITEM * H];        // item features after layer 0
__device__ float g_xufin[N_USER * H];      // user features after layer 1
__device__ float g_aggU[N_USER * 256];     // [mrev | mfol]
__device__ float g_aggI[N_ITEM * H];       // mbuy
__device__ unsigned g_wt[(256 + 384 + 384) * H];   // K-major tf32 weights
__device__ float g_bias[3 * H];            // item / user0 / user1 fused biases

__device__ int g_cnt[3][N_USER + 1];
__device__ int g_off[3][N_USER + 1];
__device__ int g_cur[3][N_USER];
__device__ int g_csr[3][NE];
__device__ int g_bsum[3][128];
__device__ int g_bbase[3][128];

// graph ids: 0 = buys (dst=item), 1 = rev (dst=user), 2 = fol (dst=user)

__device__ __forceinline__ unsigned f2tf32(float f) {
    unsigned r;
    asm("cvt.rna.tf32.f32 %0, %1;" : "=r"(r) : "f"(f));
    return r;
}
__device__ __forceinline__ unsigned smem_u32(const void* p) {
    return (unsigned)__cvta_generic_to_shared(p);
}
#define CP16(dst, src, sz) \
    asm volatile("cp.async.cg.shared.global [%0], [%1], 16, %2;\n" \
                 :: "r"(dst), "l"(src), "r"(sz))

// ---------------------------------------------------------------------------
// CSR construction
// ---------------------------------------------------------------------------
__global__ void zero_cnt_kernel() {
    int i = blockIdx.x * blockDim.x + threadIdx.x;
    if (i < 3 * (N_USER + 1)) ((int*)g_cnt)[i] = 0;
}

__global__ void count_all_kernel(const int* __restrict__ d0,
                                 const int* __restrict__ d1,
                                 const int* __restrict__ d2) {
    int i = blockIdx.x * blockDim.x + threadIdx.x;
    if (i >= 3 * NE) return;
    int g = i / NE, j = i % NE;
    const int* d = (g == 0) ? d0 : (g == 1) ? d1 : d2;
    atomicAdd(&g_cnt[g][d[j]], 1);
}

// phase 1: per-block (1024) exclusive scan of counts; block sums out.
__global__ void scan_p1_kernel() {
    int g = blockIdx.y;
    int n = (g == 0) ? N_ITEM : N_USER;
    int base = blockIdx.x * 1024;
    if (base >= n) return;
    int i = base + (int)threadIdx.x;
    int v = (i < n) ? g_cnt[g][i] : 0;
    int lane = threadIdx.x & 31, wid = threadIdx.x >> 5;
    __shared__ int warp_sums[32];
    int x = v;
    #pragma unroll
    for (int s = 1; s < 32; s <<= 1) {
        int y = __shfl_up_sync(0xffffffffu, x, s);
        if (lane >= s) x += y;
    }
    if (lane == 31) warp_sums[wid] = x;
    __syncthreads();
    if (wid == 0) {
        int w = warp_sums[lane];
        int xw = w;
        #pragma unroll
        for (int s = 1; s < 32; s <<= 1) {
            int y = __shfl_up_sync(0xffffffffu, xw, s);
            if (lane >= s) xw += y;
        }
        warp_sums[lane] = xw - w;
    }
    __syncthreads();
    int incl = x + warp_sums[wid];
    if (i < n) g_off[g][i] = incl - v;      // exclusive within block
    if (threadIdx.x == 1023) g_bsum[g][blockIdx.x] = incl;
}

// phase 2: scan block sums (<=98 per graph), 3 graphs in one 384-thread block.
__global__ void scan_p2_kernel() {
    int g = threadIdx.x >> 7;
    int i = threadIdx.x & 127;
    int nb = (g == 0) ? NBLK_I : NBLK_U;
    int n  = (g == 0) ? N_ITEM : N_USER;
    int v = (i < nb) ? g_bsum[g][i] : 0;
    int lane = i & 31, w = i >> 5;
    int x = v;
    #pragma unroll
    for (int s = 1; s < 32; s <<= 1) {
        int y = __shfl_up_sync(0xffffffffu, x, s);
        if (lane >= s) x += y;
    }
    __shared__ int ws[3][4];
    if (lane == 31) ws[g][w] = x;
    __syncthreads();
    int add = 0;
    for (int k = 0; k < w; k++) add += ws[g][k];
    x += add;
    if (i < nb) g_bbase[g][i] = x - v;      // exclusive block base
    if (i == nb - 1) g_off[g][n] = x;       // grand total
}

// phase 3: add block bases; init cursors.
__global__ void scan_p3_kernel() {
    int g = blockIdx.y;
    int n = (g == 0) ? N_ITEM : N_USER;
    int i = blockIdx.x * 1024 + threadIdx.x;
    if (i >= n) return;
    int val = g_off[g][i] + g_bbase[g][blockIdx.x];
    g_off[g][i] = val;
    g_cur[g][i] = val;
}

__global__ void fill_all_kernel(const int* __restrict__ d0, const int* __restrict__ s0,
                                const int* __restrict__ d1, const int* __restrict__ s1,
                                const int* __restrict__ d2, const int* __restrict__ s2) {
    int i = blockIdx.x * blockDim.x + threadIdx.x;
    if (i >= 3 * NE) return;
    int g = i / NE, j = i % NE;
    const int* d = (g == 0) ? d0 : (g == 1) ? d1 : d2;
    const int* s = (g == 0) ? s0 : (g == 1) ? s1 : s2;
    int dd = d[j];
    int pos = atomicAdd(&g_cur[g][dd], 1);
    g_csr[g][pos] = s[j];
}

// ---------------------------------------------------------------------------
// Weight prep: K-major tf32 weights + fused biases.
// Layout: item [256x128] @0 ; user0 [384x128] @32768 ; user1 [384x128] @81920.
// item  rows: 0-127 Wr[0,0] ; 128-255 Wl[0,0]
// userL rows: 0-127 Wr[L,1]+Wr[L,2] ; 128-255 Wl[L,1] ; 256-383 Wl[L,2]
// ---------------------------------------------------------------------------
__global__ void wprep_kernel(const float* __restrict__ Wl, const float* __restrict__ Wr,
                             const float* __restrict__ bl) {
    int idx = blockIdx.x * blockDim.x + threadIdx.x;
    const int WTOT = (256 + 384 + 384) * H;   // 131072
    if (idx < WTOT) {
        float v;
        if (idx < 256 * H) {
            int k = idx >> 7, j = idx & 127;
            if (k < 128) v = Wr[(0 * H + j) * H + k];
            else         v = Wl[(0 * H + j) * H + (k - 128)];
        } else {
            int rel = idx - 256 * H;
            int l = (rel < 384 * H) ? 0 : 1;
            if (l == 1) rel -= 384 * H;
            int k = rel >> 7, j = rel & 127;
            if (k < 128)
                v = Wr[((l * 3 + 1) * H + j) * H + k] + Wr[((l * 3 + 2) * H + j) * H + k];
            else if (k < 256)
                v = Wl[((l * 3 + 1) * H + j) * H + (k - 128)];
            else
                v = Wl[((l * 3 + 2) * H + j) * H + (k - 256)];
        }
        g_wt[idx] = f2tf32(v);
    } else if (idx < WTOT + 3 * H) {
        int t = idx - WTOT;
        int slot = t >> 7, j = t & 127;
        float b;
        if (slot == 0)      b = bl[0 * H + j];
        else if (slot == 1) b = bl[1 * H + j] + bl[2 * H + j];
        else                b = bl[(3 + 1) * H + j] + bl[(3 + 2) * H + j];
        g_bias[t] = b;
    }
}

// ---------------------------------------------------------------------------
// Fused gather-mean aggregation: one warp per dst node, all graphs one launch.
// Unrolled by 4 for MLP. All src row strides are 128 floats.
// ---------------------------------------------------------------------------
__global__ void agg_fused_kernel(const float* __restrict__ srcBuys,
                                 const float* __restrict__ srcRev,
                                 const float* __restrict__ srcFol,
                                 int has_buys) {
    int warp = (blockIdx.x * blockDim.x + threadIdx.x) >> 5;
    int lane = threadIdx.x & 31;
    int g, node;
    const float* src;
    float* dst;
    int nbuys = has_buys ? N_ITEM : 0;
    if (warp < nbuys) {
        g = 0; node = warp; src = srcBuys;
        dst = g_aggI + (size_t)node * H;
    } else {
        int w2 = warp - nbuys;
        if (w2 < N_USER) {
            g = 1; node = w2; src = srcRev;
            dst = g_aggU + (size_t)node * 256;
        } else {
            w2 -= N_USER;
            if (w2 >= N_USER) return;
            g = 2; node = w2; src = srcFol;
            dst = g_aggU + (size_t)node * 256 + 128;
        }
    }
    int s = g_off[g][node], e = g_off[g][node + 1];
    const int* lst = g_csr[g];
    float4 acc = make_float4(0.f, 0.f, 0.f, 0.f);
    int i = s;
    for (; i + 4 <= e; i += 4) {
        int i0 = lst[i], i1 = lst[i + 1], i2 = lst[i + 2], i3 = lst[i + 3];
        float4 v0 = *(const float4*)(src + (size_t)i0 * H + lane * 4);
        float4 v1 = *(const float4*)(src + (size_t)i1 * H + lane * 4);
        float4 v2 = *(const float4*)(src + (size_t)i2 * H + lane * 4);
        float4 v3 = *(const float4*)(src + (size_t)i3 * H + lane * 4);
        acc.x += (v0.x + v1.x) + (v2.x + v3.x);
        acc.y += (v0.y + v1.y) + (v2.y + v3.y);
        acc.z += (v0.z + v1.z) + (v2.z + v3.z);
        acc.w += (v0.w + v1.w) + (v2.w + v3.w);
    }
    for (; i < e; i++) {
        int i0 = lst[i];
        float4 v0 = *(const float4*)(src + (size_t)i0 * H + lane * 4);
        acc.x += v0.x; acc.y += v0.y; acc.z += v0.z; acc.w += v0.w;
    }
    float inv = (e > s) ? 1.0f / (float)(e - s) : 0.0f;
    *(float4*)(dst + lane * 4) =
        make_float4(acc.x * inv, acc.y * inv, acc.z * inv, acc.w * inv);
}

// ---------------------------------------------------------------------------
// TF32 tensor-core GEMM (cp.async 3-stage pipeline) + fused LayerNorm + ReLU.
// A split into two row-major sources: A0 (chunks < k0c) and A1 (rest).
// CTA tile 128x128, 256 thr = 8 warps (4m x 2n), warp 32x64, K chunks of 32.
// Stage smem: A 128x36 f32 (18KB) + W 32x132 u32 (16.9KB) = 35328B; x3 stages.
// Epilogue reuses smem as O 128x132 f32 (union).
// ---------------------------------------------------------------------------
#define ASTRIDE 36
#define WSTRIDE 132
#define OSTRIDE 132
#define STAGEB  35328

extern __shared__ char g_smraw[];

__device__ __forceinline__ void mma_tf32(float c[4], const unsigned a[4], const unsigned b[2]) {
    asm volatile(
        "mma.sync.aligned.m16n8k8.row.col.f32.tf32.tf32.f32 "
        "{%0,%1,%2,%3}, {%4,%5,%6,%7}, {%8,%9}, {%0,%1,%2,%3};"
        : "+f"(c[0]), "+f"(c[1]), "+f"(c[2]), "+f"(c[3])
        : "r"(a[0]), "r"(a[1]), "r"(a[2]), "r"(a[3]), "r"(b[0]), "r"(b[1]));
}

__global__ void __launch_bounds__(256, 2) gemm_ln_kernel(
    float* __restrict__ out, int ldo,
    const float* __restrict__ A0, int lda0, int k0c,
    const float* __restrict__ A1, int lda1,
    int nchunk,
    const unsigned* __restrict__ Wt, const float* __restrict__ bias,
    const float* __restrict__ gam, const float* __restrict__ bet,
    int nrows)
{
    int t = threadIdx.x;
    int lane = t & 31;
    int wid = t >> 5;
    int warp_m = wid & 3;
    int warp_n = wid >> 2;
    int gid = lane >> 2;
    int tig = lane & 3;
    int row0 = blockIdx.x * 128;

    float c[2][8][4];
    #pragma unroll
    for (int nt = 0; nt < 8; nt++) {
        int col = warp_n * 64 + nt * 8 + 2 * tig;
        float b0 = bias[col], b1 = bias[col + 1];
        #pragma unroll
        for (int mt = 0; mt < 2; mt++) {
            c[mt][nt][0] = b0; c[mt][nt][1] = b1;
            c[mt][nt][2] = b0; c[mt][nt][3] = b1;
        }
    }

    auto load_chunk = [&](int ck, int st) {
        if (ck < nchunk) {
            const float* A; int lda, cb;
            if (ck < k0c) { A = A0; lda = lda0; cb = ck * 32; }
            else          { A = A1; lda = lda1; cb = (ck - k0c) * 32; }
            float* As = (float*)(g_smraw + st * STAGEB);
            #pragma unroll
            for (int i2 = 0; i2 < 4; i2++) {
                int idx = t + 256 * i2;
                int r = idx >> 3, c4 = idx & 7;
                int row = row0 + r;
                int ok = (row < nrows);
                if (!ok) row = 0;
                const float* src = A + (size_t)row * lda + cb + c4 * 4;
                CP16(smem_u32(As + r * ASTRIDE + c4 * 4), src, ok ? 16 : 0);
            }
            unsigned* Ws = (unsigned*)(g_smraw + st * STAGEB + 128 * ASTRIDE * 4);
            #pragma unroll
            for (int i2 = 0; i2 < 4; i2++) {
                int idx = t + 256 * i2;
                int rr = idx >> 5, c4 = idx & 31;
                const unsigned* src = Wt + (size_t)(ck * 32 + rr) * H + c4 * 4;
                CP16(smem_u32(Ws + rr * WSTRIDE + c4 * 4), src, 16);
            }
        }
        asm volatile("cp.async.commit_group;\n" ::);
    };

    load_chunk(0, 0);
    load_chunk(1, 1);

    for (int ck = 0; ck < nchunk; ck++) {
        asm volatile("cp.async.wait_group 1;\n" ::);
        __syncthreads();
        load_chunk(ck + 2, (ck + 2) % 3);

        int st = ck % 3;
        const float*    As = (const float*)(g_smraw + st * STAGEB);
        const unsigned* Ws = (const unsigned*)(g_smraw + st * STAGEB + 128 * ASTRIDE * 4);
        #pragma unroll
        for (int ks = 0; ks < 4; ks++) {
            int k0 = ks * 8;
            unsigned a[2][4];
            #pragma unroll
            for (int mt = 0; mt < 2; mt++) {
                int r = warp_m * 32 + mt * 16 + gid;
                a[mt][0] = f2tf32(As[r * ASTRIDE + k0 + tig]);
                a[mt][1] = f2tf32(As[(r + 8) * ASTRIDE + k0 + tig]);
                a[mt][2] = f2tf32(As[r * ASTRIDE + k0 + tig + 4]);
                a[mt][3] = f2tf32(As[(r + 8) * ASTRIDE + k0 + tig + 4]);
            }
            unsigned b[8][2];
            #pragma unroll
            for (int nt = 0; nt < 8; nt++) {
                int cc = warp_n * 64 + nt * 8 + gid;
                b[nt][0] = Ws[(k0 + tig) * WSTRIDE + cc];
                b[nt][1] = Ws[(k0 + tig + 4) * WSTRIDE + cc];
            }
            #pragma unroll
            for (int mt = 0; mt < 2; mt++)
                #pragma unroll
                for (int nt = 0; nt < 8; nt++)
                    mma_tf32(c[mt][nt], a[mt], b[nt]);
        }
    }

    // ---- epilogue: stage to smem, fused LayerNorm + ReLU ----
    asm volatile("cp.async.wait_group 0;\n" ::);
    __syncthreads();
    float* Osm = (float*)g_smraw;
    #pragma unroll
    for (int mt = 0; mt < 2; mt++) {
        #pragma unroll
        for (int nt = 0; nt < 8; nt++) {
            int col = warp_n * 64 + nt * 8 + 2 * tig;
            int r = warp_m * 32 + mt * 16 + gid;
            *(float2*)(Osm + r * OSTRIDE + col)       = make_float2(c[mt][nt][0], c[mt][nt][1]);
            *(float2*)(Osm + (r + 8) * OSTRIDE + col) = make_float2(c[mt][nt][2], c[mt][nt][3]);
        }
    }
    __syncthreads();

    float4 gg = *(const float4*)(gam + lane * 4);
    float4 bb = *(const float4*)(bet + lane * 4);
    #pragma unroll
    for (int i = 0; i < 16; i++) {
        int r = wid * 16 + i;
        if (row0 + r >= nrows) break;
        float4 v = *(float4*)(Osm + r * OSTRIDE + lane * 4);
        float s1 = v.x + v.y + v.z + v.w;
        float s2 = v.x * v.x + v.y * v.y + v.z * v.z + v.w * v.w;
        #pragma unroll
        for (int o = 16; o; o >>= 1) {
            s1 += __shfl_xor_sync(0xffffffffu, s1, o);
            s2 += __shfl_xor_sync(0xffffffffu, s2, o);
        }
        float mu = s1 * (1.0f / H);
        float var = s2 * (1.0f / H) - mu * mu;
        float rs = rsqrtf(var + 1e-5f);
        float4 o4;
        o4.x = fmaxf((v.x - mu) * rs * gg.x + bb.x, 0.f);
        o4.y = fmaxf((v.y - mu) * rs * gg.y + bb.y, 0.f);
        o4.z = fmaxf((v.z - mu) * rs * gg.z + bb.z, 0.f);
        o4.w = fmaxf((v.w - mu) * rs * gg.w + bb.w, 0.f);
        *(float4*)(out + (size_t)(row0 + r) * ldo + lane * 4) = o4;
    }
}

// ---------------------------------------------------------------------------
// MLP head: one warp per target.
// ---------------------------------------------------------------------------
__global__ void mlp_kernel(const float* __restrict__ xu,
                           const int* __restrict__ tgt,
                           const float* __restrict__ W1, const float* __restrict__ b1,
                           const float* __restrict__ W2, const float* __restrict__ b2,
                           float* __restrict__ out) {
    int warp = (blockIdx.x * blockDim.x + threadIdx.x) >> 5;
    int lane = threadIdx.x & 31;
    if (warp >= N_TGT) return;
    int t = tgt[warp];
    float4 xv = *(const float4*)(xu + (size_t)t * H + lane * 4);
    float acc = 0.f;
    #pragma unroll 4
    for (int j = 0; j < 64; j++) {
        float4 w = *(const float4*)(W1 + j * H + lane * 4);
        float p = xv.x * w.x + xv.y * w.y + xv.z * w.z + xv.w * w.w;
        #pragma unroll
        for (int o = 16; o; o >>= 1) p += __shfl_xor_sync(0xffffffffu, p, o);
        float h = fmaxf(p + b1[j], 0.f);
        acc += h * W2[j];
    }
    if (lane == 0) out[warp] = acc + b2[0];
}

// ---------------------------------------------------------------------------
// Launch
// ---------------------------------------------------------------------------
extern "C" void kernel_launch(void* const* d_in, const int* in_sizes, int n_in,
                              void* d_out, int out_size) {
    const float* emb_user = (const float*)d_in[0];
    const float* emb_item = (const float*)d_in[1];
    const float* Wl       = (const float*)d_in[2];
    const float* bl       = (const float*)d_in[3];
    const float* Wr       = (const float*)d_in[4];
    const float* ln_g     = (const float*)d_in[5];
    const float* ln_b     = (const float*)d_in[6];
    const float* W1       = (const float*)d_in[7];
    const float* b1       = (const float*)d_in[8];
    const float* W2       = (const float*)d_in[9];
    const float* b2       = (const float*)d_in[10];
    const int* src_buys   = (const int*)d_in[11];
    const int* dst_buys   = (const int*)d_in[12];
    const int* src_rev    = (const int*)d_in[13];
    const int* dst_rev    = (const int*)d_in[14];
    const int* src_fol    = (const int*)d_in[15];
    const int* dst_fol    = (const int*)d_in[16];
    const int* target_ids = (const int*)d_in[17];
    float* out = (float*)d_out;

    float *p_xu0, *p_xi0, *p_xufin;
    unsigned* p_wt;
    float* p_bias;
    cudaGetSymbolAddress((void**)&p_xu0,   g_xu0);
    cudaGetSymbolAddress((void**)&p_xi0,   g_xi0);
    cudaGetSymbolAddress((void**)&p_xufin, g_xufin);
    cudaGetSymbolAddress((void**)&p_wt,    g_wt);
    cudaGetSymbolAddress((void**)&p_bias,  g_bias);
    float *p_aggU, *p_aggI;
    cudaGetSymbolAddress((void**)&p_aggU, g_aggU);
    cudaGetSymbolAddress((void**)&p_aggI, g_aggI);

    const int smem_bytes = 3 * STAGEB;   // 105984
    cudaFuncSetAttribute(gemm_ln_kernel,
                         cudaFuncAttributeMaxDynamicSharedMemorySize, smem_bytes);

    // --- CSR build ---
    zero_cnt_kernel<<<(3 * (N_USER + 1) + 255) / 256, 256>>>();
    count_all_kernel<<<(3 * NE + 255) / 256, 256>>>(dst_buys, dst_rev, dst_fol);
    scan_p1_kernel<<<dim3(NBLK_U, 3), 1024>>>();
    scan_p2_kernel<<<1, 384>>>();
    scan_p3_kernel<<<dim3(NBLK_U, 3), 1024>>>();
    fill_all_kernel<<<(3 * NE + 255) / 256, 256>>>(dst_buys, src_buys,
                                                   dst_rev, src_rev,
                                                   dst_fol, src_fol);
    // --- weight prep ---
    wprep_kernel<<<((256 + 384 + 384) * H + 3 * H + 255) / 256, 256>>>(Wl, Wr, bl);

    // ===== layer 0 =====
    {
        int nwarp = N_ITEM + 2 * N_USER;
        agg_fused_kernel<<<(nwarp * 32 + 255) / 256, 256>>>(emb_user, emb_item, emb_user, 1);
        // item: xi = LNReLU(emb_item@Wr0 + mbuy@Wl0 + b)
        gemm_ln_kernel<<<(N_ITEM + 127) / 128, 256, smem_bytes>>>(
            p_xi0, H,
            emb_item, H, 4,
            p_aggI, H,
            8,
            p_wt + 0, p_bias + 0,
            ln_g + 1 * H, ln_b + 1 * H,
            N_ITEM);
        // user
        gemm_ln_kernel<<<(N_USER + 127) / 128, 256, smem_bytes>>>(
            p_xu0, H,
            emb_user, H, 4,
            p_aggU, 256,
            12,
            p_wt + 256 * H, p_bias + 1 * H,
            ln_g + 0 * H, ln_b + 0 * H,
            N_USER);
    }
    // ===== layer 1 (item branch dead -> skipped) =====
    {
        int nwarp = 2 * N_USER;
        agg_fused_kernel<<<(nwarp * 32 + 255) / 256, 256>>>(nullptr, p_xi0, p_xu0, 0);
        gemm_ln_kernel<<<(N_USER + 127) / 128, 256, smem_bytes>>>(
            p_xufin, H,
            p_xu0, H, 4,
            p_aggU, 256,
            12,
            p_wt + (256 + 384) * H, p_bias + 2 * H,
            ln_g + 2 * H, ln_b + 2 * H,
            N_USER);
    }

    mlp_kernel<<<(N_TGT * 32 + 255) / 256, 256>>>(
        p_xufin, target_ids, W1, b1, W2, b2, out);
}

// round 4
// speedup vs baseline: 2.8120x; 1.2416x over previous
#include <cuda_runtime.h>
#include <cuda_fp16.h>
#include <cstdint>

#define N_USER 100000
#define N_ITEM 50000
#define NE     800000
#define H      128
#define N_TGT  8192

#define NBLK_U 98   // ceil(100000/1024)
#define NBLK_I 49   // ceil(50000/1024)

// ---------------------------------------------------------------------------
// Static device scratch (fp16 feature world)
// ---------------------------------------------------------------------------
__device__ __half g_eu16[N_USER * H];       // emb_user in fp16
__device__ __half g_ei16[N_ITEM * H];       // emb_item in fp16
__device__ __half g_xu0h[N_USER * H];       // user feats after layer 0
__device__ __half g_xi0h[N_ITEM * H];       // item feats after layer 0
__device__ __half g_xufh[N_USER * H];       // user feats after layer 1
__device__ __half g_aggU[N_USER * 256];     // [mrev | mfol] fp16
__device__ __half g_aggI[N_ITEM * H];       // mbuy fp16
// fp16 K-major weights as half2-packed u32: item 128 k2-rows, user0/user1 192 each
__device__ unsigned g_wth[(128 + 192 + 192) * H];
__device__ float g_bias[3 * H];             // fused biases

__device__ int g_cnt[3][N_USER + 1];
__device__ int g_off[3][N_USER + 1];
__device__ int g_cur[3][N_USER];
__device__ int g_csr[3][NE];
__device__ int g_bsum[3][128];
__device__ int g_bbase[3][128];

// graph ids: 0 = buys (dst=item), 1 = rev (dst=user), 2 = fol (dst=user)

__device__ __forceinline__ unsigned smem_u32(const void* p) {
    return (unsigned)__cvta_generic_to_shared(p);
}
#define CP16(dst, src, sz) \
    asm volatile("cp.async.cg.shared.global [%0], [%1], 16, %2;\n" \
                 :: "r"(dst), "l"(src), "r"(sz))

// ---------------------------------------------------------------------------
// CSR construction
// ---------------------------------------------------------------------------
__global__ void zero_cnt_kernel() {
    int i = blockIdx.x * blockDim.x + threadIdx.x;
    if (i < 3 * (N_USER + 1)) ((int*)g_cnt)[i] = 0;
}

__global__ void count_all_kernel(const int* __restrict__ d0,
                                 const int* __restrict__ d1,
                                 const int* __restrict__ d2) {
    int i = blockIdx.x * blockDim.x + threadIdx.x;
    if (i >= 3 * NE) return;
    int g = i / NE, j = i % NE;
    const int* d = (g == 0) ? d0 : (g == 1) ? d1 : d2;
    atomicAdd(&g_cnt[g][d[j]], 1);
}

__global__ void scan_p1_kernel() {
    int g = blockIdx.y;
    int n = (g == 0) ? N_ITEM : N_USER;
    int base = blockIdx.x * 1024;
    if (base >= n) return;
    int i = base + (int)threadIdx.x;
    int v = (i < n) ? g_cnt[g][i] : 0;
    int lane = threadIdx.x & 31, wid = threadIdx.x >> 5;
    __shared__ int warp_sums[32];
    int x = v;
    #pragma unroll
    for (int s = 1; s < 32; s <<= 1) {
        int y = __shfl_up_sync(0xffffffffu, x, s);
        if (lane >= s) x += y;
    }
    if (lane == 31) warp_sums[wid] = x;
    __syncthreads();
    if (wid == 0) {
        int w = warp_sums[lane];
        int xw = w;
        #pragma unroll
        for (int s = 1; s < 32; s <<= 1) {
            int y = __shfl_up_sync(0xffffffffu, xw, s);
            if (lane >= s) xw += y;
        }
        warp_sums[lane] = xw - w;
    }
    __syncthreads();
    int incl = x + warp_sums[wid];
    if (i < n) g_off[g][i] = incl - v;
    if (threadIdx.x == 1023) g_bsum[g][blockIdx.x] = incl;
}

__global__ void scan_p2_kernel() {
    int g = threadIdx.x >> 7;
    int i = threadIdx.x & 127;
    int nb = (g == 0) ? NBLK_I : NBLK_U;
    int n  = (g == 0) ? N_ITEM : N_USER;
    int v = (i < nb) ? g_bsum[g][i] : 0;
    int lane = i & 31, w = i >> 5;
    int x = v;
    #pragma unroll
    for (int s = 1; s < 32; s <<= 1) {
        int y = __shfl_up_sync(0xffffffffu, x, s);
        if (lane >= s) x += y;
    }
    __shared__ int ws[3][4];
    if (lane == 31) ws[g][w] = x;
    __syncthreads();
    int add = 0;
    for (int k = 0; k < w; k++) add += ws[g][k];
    x += add;
    if (i < nb) g_bbase[g][i] = x - v;
    if (i == nb - 1) g_off[g][n] = x;
}

__global__ void scan_p3_kernel() {
    int g = blockIdx.y;
    int n = (g == 0) ? N_ITEM : N_USER;
    int i = blockIdx.x * 1024 + threadIdx.x;
    if (i >= n) return;
    int val = g_off[g][i] + g_bbase[g][blockIdx.x];
    g_off[g][i] = val;
    g_cur[g][i] = val;
}

__global__ void fill_all_kernel(const int* __restrict__ d0, const int* __restrict__ s0,
                                const int* __restrict__ d1, const int* __restrict__ s1,
                                const int* __restrict__ d2, const int* __restrict__ s2) {
    int i = blockIdx.x * blockDim.x + threadIdx.x;
    if (i >= 3 * NE) return;
    int g = i / NE, j = i % NE;
    const int* d = (g == 0) ? d0 : (g == 1) ? d1 : d2;
    const int* s = (g == 0) ? s0 : (g == 1) ? s1 : s2;
    int dd = d[j];
    int pos = atomicAdd(&g_cur[g][dd], 1);
    g_csr[g][pos] = s[j];
}

// ---------------------------------------------------------------------------
// Embedding -> fp16 conversion
// ---------------------------------------------------------------------------
__global__ void emb2h_kernel(const float* __restrict__ eu, const float* __restrict__ ei) {
    int i = blockIdx.x * blockDim.x + threadIdx.x;
    const int NU = N_USER * H;
    if (i < NU) g_eu16[i] = __float2half_rn(eu[i]);
    else if (i < NU + N_ITEM * H) g_ei16[i - NU] = __float2half_rn(ei[i - NU]);
}

// ---------------------------------------------------------------------------
// Weight prep: fp16 half2-packed, K-major pairs.
// u32 layout per GEMM: [k2][j], k2 = k/2.
// item  (k2 0..127):  k<128 -> Wr[0,0] ; else Wl[0,0]
// userL (k2 0..191):  k<128 -> Wr[L,1]+Wr[L,2] ; k<256 -> Wl[L,1] ; else Wl[L,2]
// ---------------------------------------------------------------------------
__device__ __forceinline__ float wval_item(const float* Wl, const float* Wr, int k, int j) {
    return (k < 128) ? Wr[(0 * H + j) * H + k] : Wl[(0 * H + j) * H + (k - 128)];
}
__device__ __forceinline__ float wval_user(const float* Wl, const float* Wr, int l, int k, int j) {
    if (k < 128) return Wr[((l * 3 + 1) * H + j) * H + k] + Wr[((l * 3 + 2) * H + j) * H + k];
    if (k < 256) return Wl[((l * 3 + 1) * H + j) * H + (k - 128)];
    return Wl[((l * 3 + 2) * H + j) * H + (k - 256)];
}

__global__ void wprep_kernel(const float* __restrict__ Wl, const float* __restrict__ Wr,
                             const float* __restrict__ bl) {
    int idx = blockIdx.x * blockDim.x + threadIdx.x;
    const int WTOT = (128 + 192 + 192) * H;   // 65536 u32
    if (idx < WTOT) {
        float v0, v1;
        if (idx < 128 * H) {
            int k2 = idx >> 7, j = idx & 127;
            v0 = wval_item(Wl, Wr, 2 * k2, j);
            v1 = wval_item(Wl, Wr, 2 * k2 + 1, j);
        } else {
            int rel = idx - 128 * H;
            int l = (rel < 192 * H) ? 0 : 1;
            if (l == 1) rel -= 192 * H;
            int k2 = rel >> 7, j = rel & 127;
            v0 = wval_user(Wl, Wr, l, 2 * k2, j);
            v1 = wval_user(Wl, Wr, l, 2 * k2 + 1, j);
        }
        __half2 h = __floats2half2_rn(v0, v1);
        g_wth[idx] = *(unsigned*)&h;
    } else if (idx < WTOT + 3 * H) {
        int t = idx - WTOT;
        int slot = t >> 7, j = t & 127;
        float b;
        if (slot == 0)      b = bl[0 * H + j];
        else if (slot == 1) b = bl[1 * H + j] + bl[2 * H + j];
        else                b = bl[(3 + 1) * H + j] + bl[(3 + 2) * H + j];
        g_bias[t] = b;
    }
}

// ---------------------------------------------------------------------------
// Fused gather-mean aggregation over fp16 rows: one warp per dst node.
// Each lane covers 4 halfs (uint2 = 8B); 32 lanes = 256B row. fp32 accumulate.
// ---------------------------------------------------------------------------
__device__ __forceinline__ void acc4(float4& a, uint2 u) {
    __half2 h0 = *(__half2*)&u.x, h1 = *(__half2*)&u.y;
    float2 f0 = __half22float2(h0), f1 = __half22float2(h1);
    a.x += f0.x; a.y += f0.y; a.z += f1.x; a.w += f1.y;
}

__global__ void agg_fused_kernel(const __half* __restrict__ srcBuys,
                                 const __half* __restrict__ srcRev,
                                 const __half* __restrict__ srcFol,
                                 int has_buys) {
    int warp = (blockIdx.x * blockDim.x + threadIdx.x) >> 5;
    int lane = threadIdx.x & 31;
    int g, node;
    const __half* src;
    __half* dst;
    int nbuys = has_buys ? N_ITEM : 0;
    if (warp < nbuys) {
        g = 0; node = warp; src = srcBuys;
        dst = g_aggI + (size_t)node * H;
    } else {
        int w2 = warp - nbuys;
        if (w2 < N_USER) {
            g = 1; node = w2; src = srcRev;
            dst = g_aggU + (size_t)node * 256;
        } else {
            w2 -= N_USER;
            if (w2 >= N_USER) return;
            g = 2; node = w2; src = srcFol;
            dst = g_aggU + (size_t)node * 256 + 128;
        }
    }
    int s = g_off[g][node], e = g_off[g][node + 1];
    const int* lst = g_csr[g];
    float4 acc = make_float4(0.f, 0.f, 0.f, 0.f);
    int i = s;
    for (; i + 4 <= e; i += 4) {
        int i0 = lst[i], i1 = lst[i + 1], i2 = lst[i + 2], i3 = lst[i + 3];
        uint2 v0 = *(const uint2*)(src + (size_t)i0 * H + lane * 4);
        uint2 v1 = *(const uint2*)(src + (size_t)i1 * H + lane * 4);
        uint2 v2 = *(const uint2*)(src + (size_t)i2 * H + lane * 4);
        uint2 v3 = *(const uint2*)(src + (size_t)i3 * H + lane * 4);
        acc4(acc, v0); acc4(acc, v1); acc4(acc, v2); acc4(acc, v3);
    }
    for (; i < e; i++) {
        uint2 v0 = *(const uint2*)(src + (size_t)lst[i] * H + lane * 4);
        acc4(acc, v0);
    }
    float inv = (e > s) ? 1.0f / (float)(e - s) : 0.0f;
    __half2 o0 = __floats2half2_rn(acc.x * inv, acc.y * inv);
    __half2 o1 = __floats2half2_rn(acc.z * inv, acc.w * inv);
    uint2 o; o.x = *(unsigned*)&o0; o.y = *(unsigned*)&o1;
    *(uint2*)(dst + lane * 4) = o;
}

// ---------------------------------------------------------------------------
// FP16 tensor-core GEMM (cp.async 3-stage) + fused LayerNorm + ReLU, fp16 out.
// A from two fp16 row-major sources (chunks < k0c from A0). K chunks of 64.
// CTA tile 128x128, 8 warps (4m x 2n). m16n8k16 mma, fp32 accum.
// Stage smem: A 128 x ASTRIDE(36) u32 + W 32 x WSTRIDE(136) u32 = 35840B; x3.
// Epilogue reuses smem as O 128x132 f32.
// ---------------------------------------------------------------------------
#define ASTRIDE 36
#define WSTRIDE 136
#define OSTRIDE 132
#define STAGEB  35840

extern __shared__ char g_smraw[];

__device__ __forceinline__ void mma_f16(float c[4], const unsigned a[4], const unsigned b[2]) {
    asm volatile(
        "mma.sync.aligned.m16n8k16.row.col.f32.f16.f16.f32 "
        "{%0,%1,%2,%3}, {%4,%5,%6,%7}, {%8,%9}, {%0,%1,%2,%3};"
        : "+f"(c[0]), "+f"(c[1]), "+f"(c[2]), "+f"(c[3])
        : "r"(a[0]), "r"(a[1]), "r"(a[2]), "r"(a[3]), "r"(b[0]), "r"(b[1]));
}

__global__ void __launch_bounds__(256, 2) gemm_ln_kernel(
    __half* __restrict__ out, int ldo,
    const __half* __restrict__ A0, int lda0, int k0c,
    const __half* __restrict__ A1, int lda1,
    int nchunk,
    const unsigned* __restrict__ Wt, const float* __restrict__ bias,
    const float* __restrict__ gam, const float* __restrict__ bet,
    int nrows)
{
    int t = threadIdx.x;
    int lane = t & 31;
    int wid = t >> 5;
    int warp_m = wid & 3;
    int warp_n = wid >> 2;
    int gid = lane >> 2;
    int tig = lane & 3;
    int row0 = blockIdx.x * 128;

    float c[2][8][4];
    #pragma unroll
    for (int nt = 0; nt < 8; nt++) {
        int col = warp_n * 64 + nt * 8 + 2 * tig;
        float b0 = bias[col], b1 = bias[col + 1];
        #pragma unroll
        for (int mt = 0; mt < 2; mt++) {
            c[mt][nt][0] = b0; c[mt][nt][1] = b1;
            c[mt][nt][2] = b0; c[mt][nt][3] = b1;
        }
    }

    auto load_chunk = [&](int ck, int st) {
        if (ck < nchunk) {
            const __half* A; int lda, cb;
            if (ck < k0c) { A = A0; lda = lda0; cb = ck * 64; }
            else          { A = A1; lda = lda1; cb = (ck - k0c) * 64; }
            unsigned* As = (unsigned*)(g_smraw + st * STAGEB);
            #pragma unroll
            for (int i2 = 0; i2 < 4; i2++) {
                int idx = t + 256 * i2;              // 0..1023
                int r = idx >> 3, u = idx & 7;       // row, 16B unit
                int row = row0 + r;
                int ok = (row < nrows);
                if (!ok) row = 0;
                const __half* src = A + (size_t)row * lda + cb + u * 8;
                CP16(smem_u32(As + r * ASTRIDE + u * 4), src, ok ? 16 : 0);
            }
            unsigned* Ws = (unsigned*)(g_smraw + st * STAGEB + 128 * ASTRIDE * 4);
            #pragma unroll
            for (int i2 = 0; i2 < 4; i2++) {
                int idx = t + 256 * i2;              // 0..1023
                int rr = idx >> 5, u = idx & 31;     // k2-row, 16B unit
                const unsigned* src = Wt + (size_t)(ck * 32 + rr) * H + u * 4;
                CP16(smem_u32(Ws + rr * WSTRIDE + u * 4), src, 16);
            }
        }
        asm volatile("cp.async.commit_group;\n" ::);
    };

    load_chunk(0, 0);
    load_chunk(1, 1);

    for (int ck = 0; ck < nchunk; ck++) {
        asm volatile("cp.async.wait_group 1;\n" ::);
        __syncthreads();
        load_chunk(ck + 2, (ck + 2) % 3);

        int st = ck % 3;
        const unsigned* As = (const unsigned*)(g_smraw + st * STAGEB);
        const unsigned* Ws = (const unsigned*)(g_smraw + st * STAGEB + 128 * ASTRIDE * 4);
        #pragma unroll
        for (int ks = 0; ks < 4; ks++) {             // 4 k16-steps per 64-chunk
            int k2 = ks * 8;
            unsigned a[2][4];
            #pragma unroll
            for (int mt = 0; mt < 2; mt++) {
                int r = warp_m * 32 + mt * 16 + gid;
                a[mt][0] = As[r * ASTRIDE + k2 + tig];
                a[mt][1] = As[(r + 8) * ASTRIDE + k2 + tig];
                a[mt][2] = As[r * ASTRIDE + k2 + tig + 4];
                a[mt][3] = As[(r + 8) * ASTRIDE + k2 + tig + 4];
            }
            unsigned b[8][2];
            #pragma unroll
            for (int nt = 0; nt < 8; nt++) {
                int cc = warp_n * 64 + nt * 8 + gid;
                b[nt][0] = Ws[(k2 + tig) * WSTRIDE + cc];
                b[nt][1] = Ws[(k2 + tig + 4) * WSTRIDE + cc];
            }
            #pragma unroll
            for (int mt = 0; mt < 2; mt++)
                #pragma unroll
                for (int nt = 0; nt < 8; nt++)
                    mma_f16(c[mt][nt], a[mt], b[nt]);
        }
    }

    // ---- epilogue: stage fp32 to smem, fused LayerNorm + ReLU, fp16 out ----
    asm volatile("cp.async.wait_group 0;\n" ::);
    __syncthreads();
    float* Osm = (float*)g_smraw;
    #pragma unroll
    for (int mt = 0; mt < 2; mt++) {
        #pragma unroll
        for (int nt = 0; nt < 8; nt++) {
            int col = warp_n * 64 + nt * 8 + 2 * tig;
            int r = warp_m * 32 + mt * 16 + gid;
            *(float2*)(Osm + r * OSTRIDE + col)       = make_float2(c[mt][nt][0], c[mt][nt][1]);
            *(float2*)(Osm + (r + 8) * OSTRIDE + col) = make_float2(c[mt][nt][2], c[mt][nt][3]);
        }
    }
    __syncthreads();

    float4 gg = *(const float4*)(gam + lane * 4);
    float4 bb = *(const float4*)(bet + lane * 4);
    #pragma unroll
    for (int i = 0; i < 16; i++) {
        int r = wid * 16 + i;
        if (row0 + r >= nrows) break;
        float4 v = *(float4*)(Osm + r * OSTRIDE + lane * 4);
        float s1 = v.x + v.y + v.z + v.w;
        float s2 = v.x * v.x + v.y * v.y + v.z * v.z + v.w * v.w;
        #pragma unroll
        for (int o = 16; o; o >>= 1) {
            s1 += __shfl_xor_sync(0xffffffffu, s1, o);
            s2 += __shfl_xor_sync(0xffffffffu, s2, o);
        }
        float mu = s1 * (1.0f / H);
        float var = s2 * (1.0f / H) - mu * mu;
        float rs = rsqrtf(var + 1e-5f);
        float ox = fmaxf((v.x - mu) * rs * gg.x + bb.x, 0.f);
        float oy = fmaxf((v.y - mu) * rs * gg.y + bb.y, 0.f);
        float oz = fmaxf((v.z - mu) * rs * gg.z + bb.z, 0.f);
        float ow = fmaxf((v.w - mu) * rs * gg.w + bb.w, 0.f);
        __half2 h0 = __floats2half2_rn(ox, oy);
        __half2 h1 = __floats2half2_rn(oz, ow);
        uint2 o; o.x = *(unsigned*)&h0; o.y = *(unsigned*)&h1;
        *(uint2*)(out + (size_t)(row0 + r) * ldo + lane * 4) = o;
    }
}

// ---------------------------------------------------------------------------
// MLP head: one warp per target; fp16 features, fp32 math.
// ---------------------------------------------------------------------------
__global__ void mlp_kernel(const __half* __restrict__ xu,
                           const int* __restrict__ tgt,
                           const float* __restrict__ W1, const float* __restrict__ b1,
                           const float* __restrict__ W2, const float* __restrict__ b2,
                           float* __restrict__ out) {
    int warp = (blockIdx.x * blockDim.x + threadIdx.x) >> 5;
    int lane = threadIdx.x & 31;
    if (warp >= N_TGT) return;
    int t = tgt[warp];
    uint2 xr = *(const uint2*)(xu + (size_t)t * H + lane * 4);
    float2 x0 = __half22float2(*(__half2*)&xr.x);
    float2 x1 = __half22float2(*(__half2*)&xr.y);
    float acc = 0.f;
    #pragma unroll 4
    for (int j = 0; j < 64; j++) {
        float4 w = *(const float4*)(W1 + j * H + lane * 4);
        float p = x0.x * w.x + x0.y * w.y + x1.x * w.z + x1.y * w.w;
        #pragma unroll
        for (int o = 16; o; o >>= 1) p += __shfl_xor_sync(0xffffffffu, p, o);
        float h = fmaxf(p + b1[j], 0.f);
        acc += h * W2[j];
    }
    if (lane == 0) out[warp] = acc + b2[0];
}

// ---------------------------------------------------------------------------
// Launch
// ---------------------------------------------------------------------------
extern "C" void kernel_launch(void* const* d_in, const int* in_sizes, int n_in,
                              void* d_out, int out_size) {
    const float* emb_user = (const float*)d_in[0];
    const float* emb_item = (const float*)d_in[1];
    const float* Wl       = (const float*)d_in[2];
    const float* bl       = (const float*)d_in[3];
    const float* Wr       = (const float*)d_in[4];
    const float* ln_g     = (const float*)d_in[5];
    const float* ln_b     = (const float*)d_in[6];
    const float* W1       = (const float*)d_in[7];
    const float* b1       = (const float*)d_in[8];
    const float* W2       = (const float*)d_in[9];
    const float* b2       = (const float*)d_in[10];
    const int* src_buys   = (const int*)d_in[11];
    const int* dst_buys   = (const int*)d_in[12];
    const int* src_rev    = (const int*)d_in[13];
    const int* dst_rev    = (const int*)d_in[14];
    const int* src_fol    = (const int*)d_in[15];
    const int* dst_fol    = (const int*)d_in[16];
    const int* target_ids = (const int*)d_in[17];
    float* out = (float*)d_out;

    __half *p_eu16, *p_ei16, *p_xu0h, *p_xi0h, *p_xufh, *p_aggU, *p_aggI;
    unsigned* p_wth;
    float* p_bias;
    cudaGetSymbolAddress((void**)&p_eu16, g_eu16);
    cudaGetSymbolAddress((void**)&p_ei16, g_ei16);
    cudaGetSymbolAddress((void**)&p_xu0h, g_xu0h);
    cudaGetSymbolAddress((void**)&p_xi0h, g_xi0h);
    cudaGetSymbolAddress((void**)&p_xufh, g_xufh);
    cudaGetSymbolAddress((void**)&p_aggU, g_aggU);
    cudaGetSymbolAddress((void**)&p_aggI, g_aggI);
    cudaGetSymbolAddress((void**)&p_wth,  g_wth);
    cudaGetSymbolAddress((void**)&p_bias, g_bias);

    const int smem_bytes = 3 * STAGEB;   // 107520
    cudaFuncSetAttribute(gemm_ln_kernel,
                         cudaFuncAttributeMaxDynamicSharedMemorySize, smem_bytes);

    // --- CSR build + prep (order-independent parts first) ---
    zero_cnt_kernel<<<(3 * (N_USER + 1) + 255) / 256, 256>>>();
    emb2h_kernel<<<((N_USER + N_ITEM) * H + 255) / 256, 256>>>(emb_user, emb_item);
    wprep_kernel<<<((128 + 192 + 192) * H + 3 * H + 255) / 256, 256>>>(Wl, Wr, bl);
    count_all_kernel<<<(3 * NE + 255) / 256, 256>>>(dst_buys, dst_rev, dst_fol);
    scan_p1_kernel<<<dim3(NBLK_U, 3), 1024>>>();
    scan_p2_kernel<<<1, 384>>>();
    scan_p3_kernel<<<dim3(NBLK_U, 3), 1024>>>();
    fill_all_kernel<<<(3 * NE + 255) / 256, 256>>>(dst_buys, src_buys,
                                                   dst_rev, src_rev,
                                                   dst_fol, src_fol);

    // ===== layer 0 =====
    {
        int nwarp = N_ITEM + 2 * N_USER;
        agg_fused_kernel<<<(nwarp * 32 + 255) / 256, 256>>>(p_eu16, p_ei16, p_eu16, 1);
        // item: xi0 = LNReLU(emb_item@Wr0 + mbuy@Wl0 + b)
        gemm_ln_kernel<<<(N_ITEM + 127) / 128, 256, smem_bytes>>>(
            p_xi0h, H,
            p_ei16, H, 2,
            p_aggI, H,
            4,
            p_wth + 0, p_bias + 0,
            ln_g + 1 * H, ln_b + 1 * H,
            N_ITEM);
        // user
        gemm_ln_kernel<<<(N_USER + 127) / 128, 256, smem_bytes>>>(
            p_xu0h, H,
            p_eu16, H, 2,
            p_aggU, 256,
            6,
            p_wth + 128 * H, p_bias + 1 * H,
            ln_g + 0 * H, ln_b + 0 * H,
            N_USER);
    }
    // ===== layer 1 (item branch dead -> skipped) =====
    {
        int nwarp = 2 * N_USER;
        agg_fused_kernel<<<(nwarp * 32 + 255) / 256, 256>>>(nullptr, p_xi0h, p_xu0h, 0);
        gemm_ln_kernel<<<(N_USER + 127) / 128, 256, smem_bytes>>>(
            p_xufh, H,
            p_xu0h, H, 2,
            p_aggU, 256,
            6,
            p_wth + (128 + 192) * H, p_bias + 2 * H,
            ln_g + 2 * H, ln_b + 2 * H,
            N_USER);
    }

    mlp_kernel<<<(N_TGT * 32 + 255) / 256, 256>>>(
        p_xufh, target_ids, W1, b1, W2, b2, out);
}

// round 5
// speedup vs baseline: 3.7149x; 1.3211x over previous
#include <cuda_runtime.h>
#include <cuda_fp16.h>
#include <cstdint>

#define N_USER 100000
#define N_ITEM 50000
#define NE     800000
#define H      128
#define N_TGT  8192

#define NBLK_U 98   // ceil(100000/1024)
#define NBLK_I 49   // ceil(50000/1024)

// ---------------------------------------------------------------------------
// Static device scratch (fp16 feature world)
// ---------------------------------------------------------------------------
__device__ __half g_eu16[N_USER * H];       // emb_user in fp16
__device__ __half g_ei16[N_ITEM * H];       // emb_item in fp16
__device__ __half g_xu0h[N_USER * H];       // user feats after layer 0
__device__ __half g_xi0h[N_ITEM * H];       // item feats after layer 0
__device__ __half g_xufh[N_TGT * H];        // compact target feats after layer 1
__device__ __half g_aggU[N_USER * 256];     // layer0: [mrev | mfol]; layer1 reuses first 8192 rows
__device__ __half g_aggI[N_ITEM * H];       // mbuy fp16
// fp16 K-major weights as half2-packed u32: item 128 k2-rows, user0/user1 192 each
__device__ unsigned g_wth[(128 + 192 + 192) * H];
__device__ float g_bias[3 * H];             // fused biases

__device__ int g_cnt[3][N_USER + 1];
__device__ int g_off[3][N_USER + 1];
__device__ int g_cur[3][N_USER];
__device__ int g_csr[3][NE];
__device__ int g_bsum[3][128];
__device__ int g_bbase[3][128];

// graph ids: 0 = buys (dst=item), 1 = rev (dst=user), 2 = fol (dst=user)

__device__ __forceinline__ unsigned smem_u32(const void* p) {
    return (unsigned)__cvta_generic_to_shared(p);
}
#define CP16(dst, src, sz) \
    asm volatile("cp.async.cg.shared.global [%0], [%1], 16, %2;\n" \
                 :: "r"(dst), "l"(src), "r"(sz))

// ---------------------------------------------------------------------------
// CSR construction
// ---------------------------------------------------------------------------
__global__ void zero_cnt_kernel() {
    int i = blockIdx.x * blockDim.x + threadIdx.x;
    if (i < 3 * (N_USER + 1)) ((int*)g_cnt)[i] = 0;
}

__global__ void count_all_kernel(const int* __restrict__ d0,
                                 const int* __restrict__ d1,
                                 const int* __restrict__ d2) {
    int i = blockIdx.x * blockDim.x + threadIdx.x;
    if (i >= 3 * NE) return;
    int g = i / NE, j = i % NE;
    const int* d = (g == 0) ? d0 : (g == 1) ? d1 : d2;
    atomicAdd(&g_cnt[g][d[j]], 1);
}

__global__ void scan_p1_kernel() {
    int g = blockIdx.y;
    int n = (g == 0) ? N_ITEM : N_USER;
    int base = blockIdx.x * 1024;
    if (base >= n) return;
    int i = base + (int)threadIdx.x;
    int v = (i < n) ? g_cnt[g][i] : 0;
    int lane = threadIdx.x & 31, wid = threadIdx.x >> 5;
    __shared__ int warp_sums[32];
    int x = v;
    #pragma unroll
    for (int s = 1; s < 32; s <<= 1) {
        int y = __shfl_up_sync(0xffffffffu, x, s);
        if (lane >= s) x += y;
    }
    if (lane == 31) warp_sums[wid] = x;
    __syncthreads();
    if (wid == 0) {
        int w = warp_sums[lane];
        int xw = w;
        #pragma unroll
        for (int s = 1; s < 32; s <<= 1) {
            int y = __shfl_up_sync(0xffffffffu, xw, s);
            if (lane >= s) xw += y;
        }
        warp_sums[lane] = xw - w;
    }
    __syncthreads();
    int incl = x + warp_sums[wid];
    if (i < n) g_off[g][i] = incl - v;
    if (threadIdx.x == 1023) g_bsum[g][blockIdx.x] = incl;
}

__global__ void scan_p2_kernel() {
    int g = threadIdx.x >> 7;
    int i = threadIdx.x & 127;
    int nb = (g == 0) ? NBLK_I : NBLK_U;
    int n  = (g == 0) ? N_ITEM : N_USER;
    int v = (i < nb) ? g_bsum[g][i] : 0;
    int lane = i & 31, w = i >> 5;
    int x = v;
    #pragma unroll
    for (int s = 1; s < 32; s <<= 1) {
        int y = __shfl_up_sync(0xffffffffu, x, s);
        if (lane >= s) x += y;
    }
    __shared__ int ws[3][4];
    if (lane == 31) ws[g][w] = x;
    __syncthreads();
    int add = 0;
    for (int k = 0; k < w; k++) add += ws[g][k];
    x += add;
    if (i < nb) g_bbase[g][i] = x - v;
    if (i == nb - 1) g_off[g][n] = x;
}

__global__ void scan_p3_kernel() {
    int g = blockIdx.y;
    int n = (g == 0) ? N_ITEM : N_USER;
    int i = blockIdx.x * 1024 + threadIdx.x;
    if (i >= n) return;
    int val = g_off[g][i] + g_bbase[g][blockIdx.x];
    g_off[g][i] = val;
    g_cur[g][i] = val;
}

__global__ void fill_all_kernel(const int* __restrict__ d0, const int* __restrict__ s0,
                                const int* __restrict__ d1, const int* __restrict__ s1,
                                const int* __restrict__ d2, const int* __restrict__ s2) {
    int i = blockIdx.x * blockDim.x + threadIdx.x;
    if (i >= 3 * NE) return;
    int g = i / NE, j = i % NE;
    const int* d = (g == 0) ? d0 : (g == 1) ? d1 : d2;
    const int* s = (g == 0) ? s0 : (g == 1) ? s1 : s2;
    int dd = d[j];
    int pos = atomicAdd(&g_cur[g][dd], 1);
    g_csr[g][pos] = s[j];
}

// ---------------------------------------------------------------------------
// Embedding -> fp16 conversion
// ---------------------------------------------------------------------------
__global__ void emb2h_kernel(const float* __restrict__ eu, const float* __restrict__ ei) {
    int i = blockIdx.x * blockDim.x + threadIdx.x;
    const int NU = N_USER * H;
    if (i < NU) g_eu16[i] = __float2half_rn(eu[i]);
    else if (i < NU + N_ITEM * H) g_ei16[i - NU] = __float2half_rn(ei[i - NU]);
}

// ---------------------------------------------------------------------------
// Weight prep: fp16 half2-packed, K-major pairs.
// ---------------------------------------------------------------------------
__device__ __forceinline__ float wval_item(const float* Wl, const float* Wr, int k, int j) {
    return (k < 128) ? Wr[(0 * H + j) * H + k] : Wl[(0 * H + j) * H + (k - 128)];
}
__device__ __forceinline__ float wval_user(const float* Wl, const float* Wr, int l, int k, int j) {
    if (k < 128) return Wr[((l * 3 + 1) * H + j) * H + k] + Wr[((l * 3 + 2) * H + j) * H + k];
    if (k < 256) return Wl[((l * 3 + 1) * H + j) * H + (k - 128)];
    return Wl[((l * 3 + 2) * H + j) * H + (k - 256)];
}

__global__ void wprep_kernel(const float* __restrict__ Wl, const float* __restrict__ Wr,
                             const float* __restrict__ bl) {
    int idx = blockIdx.x * blockDim.x + threadIdx.x;
    const int WTOT = (128 + 192 + 192) * H;   // 65536 u32
    if (idx < WTOT) {
        float v0, v1;
        if (idx < 128 * H) {
            int k2 = idx >> 7, j = idx & 127;
            v0 = wval_item(Wl, Wr, 2 * k2, j);
            v1 = wval_item(Wl, Wr, 2 * k2 + 1, j);
        } else {
            int rel = idx - 128 * H;
            int l = (rel < 192 * H) ? 0 : 1;
            if (l == 1) rel -= 192 * H;
            int k2 = rel >> 7, j = rel & 127;
            v0 = wval_user(Wl, Wr, l, 2 * k2, j);
            v1 = wval_user(Wl, Wr, l, 2 * k2 + 1, j);
        }
        __half2 h = __floats2half2_rn(v0, v1);
        g_wth[idx] = *(unsigned*)&h;
    } else if (idx < WTOT + 3 * H) {
        int t = idx - WTOT;
        int slot = t >> 7, j = t & 127;
        float b;
        if (slot == 0)      b = bl[0 * H + j];
        else if (slot == 1) b = bl[1 * H + j] + bl[2 * H + j];
        else                b = bl[(3 + 1) * H + j] + bl[(3 + 2) * H + j];
        g_bias[t] = b;
    }
}

// ---------------------------------------------------------------------------
// Gather-mean over fp16 rows (fp32 accumulate), shared body.
// ---------------------------------------------------------------------------
__device__ __forceinline__ void acc4(float4& a, uint2 u) {
    __half2 h0 = *(__half2*)&u.x, h1 = *(__half2*)&u.y;
    float2 f0 = __half22float2(h0), f1 = __half22float2(h1);
    a.x += f0.x; a.y += f0.y; a.z += f1.x; a.w += f1.y;
}

__device__ __forceinline__ void agg_one(int g, int node, int lane,
                                        const __half* __restrict__ src,
                                        __half* __restrict__ dst) {
    int s = g_off[g][node], e = g_off[g][node + 1];
    const int* lst = g_csr[g];
    float4 acc = make_float4(0.f, 0.f, 0.f, 0.f);
    int i = s;
    for (; i + 4 <= e; i += 4) {
        int i0 = lst[i], i1 = lst[i + 1], i2 = lst[i + 2], i3 = lst[i + 3];
        uint2 v0 = *(const uint2*)(src + (size_t)i0 * H + lane * 4);
        uint2 v1 = *(const uint2*)(src + (size_t)i1 * H + lane * 4);
        uint2 v2 = *(const uint2*)(src + (size_t)i2 * H + lane * 4);
        uint2 v3 = *(const uint2*)(src + (size_t)i3 * H + lane * 4);
        acc4(acc, v0); acc4(acc, v1); acc4(acc, v2); acc4(acc, v3);
    }
    for (; i < e; i++) {
        uint2 v0 = *(const uint2*)(src + (size_t)lst[i] * H + lane * 4);
        acc4(acc, v0);
    }
    float inv = (e > s) ? 1.0f / (float)(e - s) : 0.0f;
    __half2 o0 = __floats2half2_rn(acc.x * inv, acc.y * inv);
    __half2 o1 = __floats2half2_rn(acc.z * inv, acc.w * inv);
    uint2 o; o.x = *(unsigned*)&o0; o.y = *(unsigned*)&o1;
    *(uint2*)(dst + lane * 4) = o;
}

// Layer-0 aggregation: all dst nodes of all 3 graphs, one warp per node.
__global__ void agg_l0_kernel(const __half* __restrict__ eu,
                              const __half* __restrict__ ei) {
    int warp = (blockIdx.x * blockDim.x + threadIdx.x) >> 5;
    int lane = threadIdx.x & 31;
    if (warp < N_ITEM) {
        agg_one(0, warp, lane, eu, g_aggI + (size_t)warp * H);
    } else {
        int w2 = warp - N_ITEM;
        if (w2 < N_USER) {
            agg_one(1, w2, lane, ei, g_aggU + (size_t)w2 * 256);
        } else {
            w2 -= N_USER;
            if (w2 >= N_USER) return;
            agg_one(2, w2, lane, eu, g_aggU + (size_t)w2 * 256 + 128);
        }
    }
}

// Layer-1 aggregation: ONLY target users (compact rows 0..N_TGT-1).
__global__ void agg_tgt_kernel(const __half* __restrict__ xi0,
                               const __half* __restrict__ xu0,
                               const int* __restrict__ tgt) {
    int warp = (blockIdx.x * blockDim.x + threadIdx.x) >> 5;
    int lane = threadIdx.x & 31;
    if (warp >= 2 * N_TGT) return;
    int pos = warp & (N_TGT - 1);
    int node = tgt[pos];
    if (warp < N_TGT)
        agg_one(1, node, lane, xi0, g_aggU + (size_t)pos * 256);
    else
        agg_one(2, node, lane, xu0, g_aggU + (size_t)pos * 256 + 128);
}

// ---------------------------------------------------------------------------
// FP16 tensor-core GEMM (cp.async 3-stage) + fused LayerNorm + ReLU, fp16 out.
// Two jobs per launch (blockIdx split). A0 rows optionally indirected (ridx0).
// ---------------------------------------------------------------------------
#define ASTRIDE 36
#define WSTRIDE 136
#define OSTRIDE 132
#define STAGEB  35840

extern __shared__ char g_smraw[];

struct GemmJob {
    __half* out;
    const __half* A0;
    const __half* A1;
    const int* ridx0;        // optional row index for A0 (compact jobs)
    const unsigned* Wt;
    const float* bias;
    const float* gam;
    const float* bet;
    int lda0, lda1, k0c, nchunk, nrows;
};

__device__ __forceinline__ void mma_f16(float c[4], const unsigned a[4], const unsigned b[2]) {
    asm volatile(
        "mma.sync.aligned.m16n8k16.row.col.f32.f16.f16.f32 "
        "{%0,%1,%2,%3}, {%4,%5,%6,%7}, {%8,%9}, {%0,%1,%2,%3};"
        : "+f"(c[0]), "+f"(c[1]), "+f"(c[2]), "+f"(c[3])
        : "r"(a[0]), "r"(a[1]), "r"(a[2]), "r"(a[3]), "r"(b[0]), "r"(b[1]));
}

__global__ void __launch_bounds__(256, 2) gemm_ln_kernel(GemmJob j0, GemmJob j1, int split) {
    GemmJob J = (blockIdx.x < (unsigned)split) ? j0 : j1;
    int bid = (blockIdx.x < (unsigned)split) ? blockIdx.x : blockIdx.x - split;

    int t = threadIdx.x;
    int lane = t & 31;
    int wid = t >> 5;
    int warp_m = wid & 3;
    int warp_n = wid >> 2;
    int gid = lane >> 2;
    int tig = lane & 3;
    int row0 = bid * 128;

    float c[2][8][4];
    #pragma unroll
    for (int nt = 0; nt < 8; nt++) {
        int col = warp_n * 64 + nt * 8 + 2 * tig;
        float b0 = J.bias[col], b1 = J.bias[col + 1];
        #pragma unroll
        for (int mt = 0; mt < 2; mt++) {
            c[mt][nt][0] = b0; c[mt][nt][1] = b1;
            c[mt][nt][2] = b0; c[mt][nt][3] = b1;
        }
    }

    auto load_chunk = [&](int ck, int st) {
        if (ck < J.nchunk) {
            const __half* A; int lda, cb; bool ind;
            if (ck < J.k0c) { A = J.A0; lda = J.lda0; cb = ck * 64; ind = (J.ridx0 != nullptr); }
            else            { A = J.A1; lda = J.lda1; cb = (ck - J.k0c) * 64; ind = false; }
            unsigned* As = (unsigned*)(g_smraw + st * STAGEB);
            #pragma unroll
            for (int i2 = 0; i2 < 4; i2++) {
                int idx = t + 256 * i2;
                int r = idx >> 3, u = idx & 7;
                int row = row0 + r;
                int ok = (row < J.nrows);
                if (!ok) row = 0;
                if (ind) row = __ldg(J.ridx0 + row);
                const __half* src = A + (size_t)row * lda + cb + u * 8;
                CP16(smem_u32(As + r * ASTRIDE + u * 4), src, ok ? 16 : 0);
            }
            unsigned* Ws = (unsigned*)(g_smraw + st * STAGEB + 128 * ASTRIDE * 4);
            #pragma unroll
            for (int i2 = 0; i2 < 4; i2++) {
                int idx = t + 256 * i2;
                int rr = idx >> 5, u = idx & 31;
                const unsigned* src = J.Wt + (size_t)(ck * 32 + rr) * H + u * 4;
                CP16(smem_u32(Ws + rr * WSTRIDE + u * 4), src, 16);
            }
        }
        asm volatile("cp.async.commit_group;\n" ::);
    };

    load_chunk(0, 0);
    load_chunk(1, 1);

    for (int ck = 0; ck < J.nchunk; ck++) {
        asm volatile("cp.async.wait_group 1;\n" ::);
        __syncthreads();
        load_chunk(ck + 2, (ck + 2) % 3);

        int st = ck % 3;
        const unsigned* As = (const unsigned*)(g_smraw + st * STAGEB);
        const unsigned* Ws = (const unsigned*)(g_smraw + st * STAGEB + 128 * ASTRIDE * 4);
        #pragma unroll
        for (int ks = 0; ks < 4; ks++) {
            int k2 = ks * 8;
            unsigned a[2][4];
            #pragma unroll
            for (int mt = 0; mt < 2; mt++) {
                int r = warp_m * 32 + mt * 16 + gid;
                a[mt][0] = As[r * ASTRIDE + k2 + tig];
                a[mt][1] = As[(r + 8) * ASTRIDE + k2 + tig];
                a[mt][2] = As[r * ASTRIDE + k2 + tig + 4];
                a[mt][3] = As[(r + 8) * ASTRIDE + k2 + tig + 4];
            }
            unsigned b[8][2];
            #pragma unroll
            for (int nt = 0; nt < 8; nt++) {
                int cc = warp_n * 64 + nt * 8 + gid;
                b[nt][0] = Ws[(k2 + tig) * WSTRIDE + cc];
                b[nt][1] = Ws[(k2 + tig + 4) * WSTRIDE + cc];
            }
            #pragma unroll
            for (int mt = 0; mt < 2; mt++)
                #pragma unroll
                for (int nt = 0; nt < 8; nt++)
                    mma_f16(c[mt][nt], a[mt], b[nt]);
        }
    }

    // ---- epilogue: stage fp32 to smem, fused LayerNorm + ReLU, fp16 out ----
    asm volatile("cp.async.wait_group 0;\n" ::);
    __syncthreads();
    float* Osm = (float*)g_smraw;
    #pragma unroll
    for (int mt = 0; mt < 2; mt++) {
        #pragma unroll
        for (int nt = 0; nt < 8; nt++) {
            int col = warp_n * 64 + nt * 8 + 2 * tig;
            int r = warp_m * 32 + mt * 16 + gid;
            *(float2*)(Osm + r * OSTRIDE + col)       = make_float2(c[mt][nt][0], c[mt][nt][1]);
            *(float2*)(Osm + (r + 8) * OSTRIDE + col) = make_float2(c[mt][nt][2], c[mt][nt][3]);
        }
    }
    __syncthreads();

    float4 gg = *(const float4*)(J.gam + lane * 4);
    float4 bb = *(const float4*)(J.bet + lane * 4);
    #pragma unroll
    for (int i = 0; i < 16; i++) {
        int r = wid * 16 + i;
        if (row0 + r >= J.nrows) break;
        float4 v = *(float4*)(Osm + r * OSTRIDE + lane * 4);
        float s1 = v.x + v.y + v.z + v.w;
        float s2 = v.x * v.x + v.y * v.y + v.z * v.z + v.w * v.w;
        #pragma unroll
        for (int o = 16; o; o >>= 1) {
            s1 += __shfl_xor_sync(0xffffffffu, s1, o);
            s2 += __shfl_xor_sync(0xffffffffu, s2, o);
        }
        float mu = s1 * (1.0f / H);
        float var = s2 * (1.0f / H) - mu * mu;
        float rs = rsqrtf(var + 1e-5f);
        float ox = fmaxf((v.x - mu) * rs * gg.x + bb.x, 0.f);
        float oy = fmaxf((v.y - mu) * rs * gg.y + bb.y, 0.f);
        float oz = fmaxf((v.z - mu) * rs * gg.z + bb.z, 0.f);
        float ow = fmaxf((v.w - mu) * rs * gg.w + bb.w, 0.f);
        __half2 h0 = __floats2half2_rn(ox, oy);
        __half2 h1 = __floats2half2_rn(oz, ow);
        uint2 o; o.x = *(unsigned*)&h0; o.y = *(unsigned*)&h1;
        *(uint2*)(J.out + (size_t)(row0 + r) * H + lane * 4) = o;
    }
}

// ---------------------------------------------------------------------------
// MLP head on compact target features: one warp per target position.
// ---------------------------------------------------------------------------
__global__ void mlp_kernel(const __half* __restrict__ xuc,
                           const float* __restrict__ W1, const float* __restrict__ b1,
                           const float* __restrict__ W2, const float* __restrict__ b2,
                           float* __restrict__ out) {
    int warp = (blockIdx.x * blockDim.x + threadIdx.x) >> 5;
    int lane = threadIdx.x & 31;
    if (warp >= N_TGT) return;
    uint2 xr = *(const uint2*)(xuc + (size_t)warp * H + lane * 4);
    float2 x0 = __half22float2(*(__half2*)&xr.x);
    float2 x1 = __half22float2(*(__half2*)&xr.y);
    float acc = 0.f;
    #pragma unroll 4
    for (int j = 0; j < 64; j++) {
        float4 w = *(const float4*)(W1 + j * H + lane * 4);
        float p = x0.x * w.x + x0.y * w.y + x1.x * w.z + x1.y * w.w;
        #pragma unroll
        for (int o = 16; o; o >>= 1) p += __shfl_xor_sync(0xffffffffu, p, o);
        float h = fmaxf(p + b1[j], 0.f);
        acc += h * W2[j];
    }
    if (lane == 0) out[warp] = acc + b2[0];
}

// ---------------------------------------------------------------------------
// Launch
// ---------------------------------------------------------------------------
extern "C" void kernel_launch(void* const* d_in, const int* in_sizes, int n_in,
                              void* d_out, int out_size) {
    const float* emb_user = (const float*)d_in[0];
    const float* emb_item = (const float*)d_in[1];
    const float* Wl       = (const float*)d_in[2];
    const float* bl       = (const float*)d_in[3];
    const float* Wr       = (const float*)d_in[4];
    const float* ln_g     = (const float*)d_in[5];
    const float* ln_b     = (const float*)d_in[6];
    const float* W1       = (const float*)d_in[7];
    const float* b1       = (const float*)d_in[8];
    const float* W2       = (const float*)d_in[9];
    const float* b2       = (const float*)d_in[10];
    const int* src_buys   = (const int*)d_in[11];
    const int* dst_buys   = (const int*)d_in[12];
    const int* src_rev    = (const int*)d_in[13];
    const int* dst_rev    = (const int*)d_in[14];
    const int* src_fol    = (const int*)d_in[15];
    const int* dst_fol    = (const int*)d_in[16];
    const int* target_ids = (const int*)d_in[17];
    float* out = (float*)d_out;

    __half *p_eu16, *p_ei16, *p_xu0h, *p_xi0h, *p_xufh, *p_aggU, *p_aggI;
    unsigned* p_wth;
    float* p_bias;
    cudaGetSymbolAddress((void**)&p_eu16, g_eu16);
    cudaGetSymbolAddress((void**)&p_ei16, g_ei16);
    cudaGetSymbolAddress((void**)&p_xu0h, g_xu0h);
    cudaGetSymbolAddress((void**)&p_xi0h, g_xi0h);
    cudaGetSymbolAddress((void**)&p_xufh, g_xufh);
    cudaGetSymbolAddress((void**)&p_aggU, g_aggU);
    cudaGetSymbolAddress((void**)&p_aggI, g_aggI);
    cudaGetSymbolAddress((void**)&p_wth,  g_wth);
    cudaGetSymbolAddress((void**)&p_bias, g_bias);

    const int smem_bytes = 3 * STAGEB;   // 107520
    cudaFuncSetAttribute(gemm_ln_kernel,
                         cudaFuncAttributeMaxDynamicSharedMemorySize, smem_bytes);

    // --- CSR build + prep ---
    zero_cnt_kernel<<<(3 * (N_USER + 1) + 255) / 256, 256>>>();
    emb2h_kernel<<<((N_USER + N_ITEM) * H + 255) / 256, 256>>>(emb_user, emb_item);
    wprep_kernel<<<((128 + 192 + 192) * H + 3 * H + 255) / 256, 256>>>(Wl, Wr, bl);
    count_all_kernel<<<(3 * NE + 255) / 256, 256>>>(dst_buys, dst_rev, dst_fol);
    scan_p1_kernel<<<dim3(NBLK_U, 3), 1024>>>();
    scan_p2_kernel<<<1, 384>>>();
    scan_p3_kernel<<<dim3(NBLK_U, 3), 1024>>>();
    fill_all_kernel<<<(3 * NE + 255) / 256, 256>>>(dst_buys, src_buys,
                                                   dst_rev, src_rev,
                                                   dst_fol, src_fol);

    // ===== layer 0 =====
    {
        int nwarp = N_ITEM + 2 * N_USER;
        agg_l0_kernel<<<(nwarp * 32 + 255) / 256, 256>>>(p_eu16, p_ei16);

        GemmJob ji, ju;
        // item: xi0 = LNReLU(emb_item@Wr0 + mbuy@Wl0 + b)
        ji.out = p_xi0h; ji.A0 = p_ei16; ji.A1 = p_aggI; ji.ridx0 = nullptr;
        ji.Wt = p_wth; ji.bias = p_bias;
        ji.gam = ln_g + 1 * H; ji.bet = ln_b + 1 * H;
        ji.lda0 = H; ji.lda1 = H; ji.k0c = 2; ji.nchunk = 4; ji.nrows = N_ITEM;
        // user0
        ju.out = p_xu0h; ju.A0 = p_eu16; ju.A1 = p_aggU; ju.ridx0 = nullptr;
        ju.Wt = p_wth + 128 * H; ju.bias = p_bias + 1 * H;
        ju.gam = ln_g + 0 * H; ju.bet = ln_b + 0 * H;
        ju.lda0 = H; ju.lda1 = 256; ju.k0c = 2; ju.nchunk = 6; ju.nrows = N_USER;

        int nbi = (N_ITEM + 127) / 128;          // 391
        int nbu = (N_USER + 127) / 128;          // 782
        gemm_ln_kernel<<<nbi + nbu, 256, smem_bytes>>>(ji, ju, nbi);
    }
    // ===== layer 1: only target rows =====
    {
        agg_tgt_kernel<<<(2 * N_TGT * 32 + 255) / 256, 256>>>(p_xi0h, p_xu0h, target_ids);

        GemmJob jt;
        jt.out = p_xufh; jt.A0 = p_xu0h; jt.A1 = p_aggU; jt.ridx0 = target_ids;
        jt.Wt = p_wth + (128 + 192) * H; jt.bias = p_bias + 2 * H;
        jt.gam = ln_g + 2 * H; jt.bet = ln_b + 2 * H;
        jt.lda0 = H; jt.lda1 = 256; jt.k0c = 2; jt.nchunk = 6; jt.nrows = N_TGT;

        int nbt = N_TGT / 128;                   // 64
        gemm_ln_kernel<<<nbt, 256, smem_bytes>>>(jt, jt, nbt);
    }

    mlp_kernel<<<(N_TGT * 32 + 255) / 256, 256>>>(
        p_xufh, W1, b1, W2, b2, out);
}

// round 6
// speedup vs baseline: 4.6925x; 1.2632x over previous
#include <cuda_runtime.h>
#include <cuda_fp16.h>
#include <cstdint>

#define N_USER 100000
#define N_ITEM 50000
#define NE     800000
#define NE4    (NE / 4)
#define H      128
#define N_TGT  8192

#define NBLK_U 98   // ceil(100000/1024)
#define NBLK_I 49   // ceil(50000/1024)

// ---------------------------------------------------------------------------
// Static device scratch (fp16 feature world)
// ---------------------------------------------------------------------------
__device__ __half g_eu16[N_USER * H];       // emb_user in fp16
__device__ __half g_ei16[N_ITEM * H];       // emb_item in fp16
__device__ __half g_xu0h[N_USER * H];       // user feats after layer 0 (needed rows only)
__device__ __half g_xi0h[N_ITEM * H];       // item feats after layer 0 (needed rows only)
__device__ __half g_xufh[N_TGT * H];        // compact target feats after layer 1
__device__ __half g_aggU[N_USER * 256];     // layer0: [mrev|mfol] at node pos; layer1: compact rows
__device__ __half g_aggI[N_ITEM * H];       // mbuy fp16
__device__ unsigned g_wth[(128 + 192 + 192) * H];   // fp16 half2-packed K-major weights
__device__ float g_bias[3 * H];             // fused biases

// CSR + scan scratch. scan rows: 0..2 = graph degree counts, 3 = needU, 4 = needI
__device__ int g_cnt[3][N_USER + 1];
__device__ int g_off[5][N_USER + 1];
__device__ int g_cur[3][N_USER];
__device__ int g_csr[3][NE];
__device__ int g_bsum[5][128];
__device__ int g_bbase[5][128];

// pruning
__device__ int g_tflag[N_USER];             // is-target flag
__device__ int g_needU[N_USER];
__device__ int g_needI[N_ITEM];
__device__ int g_cmpU[N_USER];              // compact list of needed users
__device__ int g_cmpI[N_ITEM];              // compact list of needed items

// graph ids: 0 = buys (dst=item), 1 = rev (dst=user), 2 = fol (dst=user)

__device__ __forceinline__ unsigned smem_u32(const void* p) {
    return (unsigned)__cvta_generic_to_shared(p);
}
#define CP16(dst, src, sz) \
    asm volatile("cp.async.cg.shared.global [%0], [%1], 16, %2;\n" \
                 :: "r"(dst), "l"(src), "r"(sz))

// ---------------------------------------------------------------------------
// Zero + flag init
// ---------------------------------------------------------------------------
__global__ void zero_kernel() {
    int i = blockIdx.x * blockDim.x + threadIdx.x;
    if (i < 3 * (N_USER + 1)) ((int*)g_cnt)[i] = 0;
    if (i < N_USER) { g_needU[i] = 0; g_tflag[i] = 0; }
    if (i < N_ITEM) g_needI[i] = 0;
}

__global__ void flag_tgt_kernel(const int* __restrict__ tgt) {
    int i = blockIdx.x * blockDim.x + threadIdx.x;
    if (i < N_TGT) {
        int t = tgt[i];
        g_tflag[t] = 1;
        g_needU[t] = 1;
    }
}

// mark src nodes of fol/rev edges whose dst is a target
__global__ void flag_edges_kernel(const int* __restrict__ df, const int* __restrict__ sf,
                                  const int* __restrict__ dr, const int* __restrict__ sr) {
    int i = blockIdx.x * blockDim.x + threadIdx.x;
    if (i < NE4) {
        int4 d = ((const int4*)df)[i];
        int4 s = ((const int4*)sf)[i];
        if (g_tflag[d.x]) g_needU[s.x] = 1;
        if (g_tflag[d.y]) g_needU[s.y] = 1;
        if (g_tflag[d.z]) g_needU[s.z] = 1;
        if (g_tflag[d.w]) g_needU[s.w] = 1;
    } else if (i < 2 * NE4) {
        int j = i - NE4;
        int4 d = ((const int4*)dr)[j];
        int4 s = ((const int4*)sr)[j];
        if (g_tflag[d.x]) g_needI[s.x] = 1;
        if (g_tflag[d.y]) g_needI[s.y] = 1;
        if (g_tflag[d.z]) g_needI[s.z] = 1;
        if (g_tflag[d.w]) g_needI[s.w] = 1;
    }
}

// ---------------------------------------------------------------------------
// CSR construction (vectorized int4 edge reads)
// ---------------------------------------------------------------------------
__global__ void count_all_kernel(const int* __restrict__ d0,
                                 const int* __restrict__ d1,
                                 const int* __restrict__ d2) {
    int i = blockIdx.x * blockDim.x + threadIdx.x;
    if (i >= 3 * NE4) return;
    int g = i / NE4, j = i % NE4;
    const int* d = (g == 0) ? d0 : (g == 1) ? d1 : d2;
    int4 v = ((const int4*)d)[j];
    atomicAdd(&g_cnt[g][v.x], 1);
    atomicAdd(&g_cnt[g][v.y], 1);
    atomicAdd(&g_cnt[g][v.z], 1);
    atomicAdd(&g_cnt[g][v.w], 1);
}

__device__ __forceinline__ int scan_val(int g, int i) {
    if (g < 3) return g_cnt[g][i];
    if (g == 3) return g_needU[i];
    return g_needI[i];
}
__device__ __forceinline__ int scan_n(int g) {
    return (g == 0 || g == 4) ? N_ITEM : N_USER;
}

// phase 1: per-1024-block exclusive scan; block sums out.
__global__ void scan_p1_kernel() {
    int g = blockIdx.y;
    int n = scan_n(g);
    int base = blockIdx.x * 1024;
    if (base >= n) return;
    int i = base + (int)threadIdx.x;
    int v = (i < n) ? scan_val(g, i) : 0;
    int lane = threadIdx.x & 31, wid = threadIdx.x >> 5;
    __shared__ int warp_sums[32];
    int x = v;
    #pragma unroll
    for (int s = 1; s < 32; s <<= 1) {
        int y = __shfl_up_sync(0xffffffffu, x, s);
        if (lane >= s) x += y;
    }
    if (lane == 31) warp_sums[wid] = x;
    __syncthreads();
    if (wid == 0) {
        int w = warp_sums[lane];
        int xw = w;
        #pragma unroll
        for (int s = 1; s < 32; s <<= 1) {
            int y = __shfl_up_sync(0xffffffffu, xw, s);
            if (lane >= s) xw += y;
        }
        warp_sums[lane] = xw - w;
    }
    __syncthreads();
    int incl = x + warp_sums[wid];
    if (i < n) g_off[g][i] = incl - v;
    if (threadIdx.x == 1023) g_bsum[g][blockIdx.x] = incl;
}

// phase 2: scan block sums; 5 rows x 128 threads.
__global__ void scan_p2_kernel() {
    int g = threadIdx.x >> 7;
    int i = threadIdx.x & 127;
    int n = scan_n(g);
    int nb = (n + 1023) / 1024;
    int v = (i < nb) ? g_bsum[g][i] : 0;
    int lane = i & 31, w = i >> 5;
    int x = v;
    #pragma unroll
    for (int s = 1; s < 32; s <<= 1) {
        int y = __shfl_up_sync(0xffffffffu, x, s);
        if (lane >= s) x += y;
    }
    __shared__ int ws[5][4];
    if (lane == 31) ws[g][w] = x;
    __syncthreads();
    int add = 0;
    for (int k = 0; k < w; k++) add += ws[g][k];
    x += add;
    if (i < nb) g_bbase[g][i] = x - v;
    if (i == nb - 1) g_off[g][n] = x;   // total (CSR size / compact count)
}

// phase 3: add block bases; init cursors (g<3); compact lists (g>=3).
__global__ void scan_p3_kernel() {
    int g = blockIdx.y;
    int n = scan_n(g);
    int i = blockIdx.x * 1024 + threadIdx.x;
    if (i >= n) return;
    int val = g_off[g][i] + g_bbase[g][blockIdx.x];
    if (g < 3) {
        g_off[g][i] = val;
        g_cur[g][i] = val;
    } else if (g == 3) {
        if (g_needU[i]) g_cmpU[val] = i;
    } else {
        if (g_needI[i]) g_cmpI[val] = i;
    }
}

__global__ void fill_all_kernel(const int* __restrict__ d0, const int* __restrict__ s0,
                                const int* __restrict__ d1, const int* __restrict__ s1,
                                const int* __restrict__ d2, const int* __restrict__ s2) {
    int i = blockIdx.x * blockDim.x + threadIdx.x;
    if (i >= 3 * NE4) return;
    int g = i / NE4, j = i % NE4;
    const int* d = (g == 0) ? d0 : (g == 1) ? d1 : d2;
    const int* s = (g == 0) ? s0 : (g == 1) ? s1 : s2;
    int4 dv = ((const int4*)d)[j];
    int4 sv = ((const int4*)s)[j];
    g_csr[g][atomicAdd(&g_cur[g][dv.x], 1)] = sv.x;
    g_csr[g][atomicAdd(&g_cur[g][dv.y], 1)] = sv.y;
    g_csr[g][atomicAdd(&g_cur[g][dv.z], 1)] = sv.z;
    g_csr[g][atomicAdd(&g_cur[g][dv.w], 1)] = sv.w;
}

// ---------------------------------------------------------------------------
// Embedding -> fp16, 8 elements per thread
// ---------------------------------------------------------------------------
__device__ __forceinline__ uint4 pack8(float4 a, float4 b) {
    __half2 h0 = __floats2half2_rn(a.x, a.y);
    __half2 h1 = __floats2half2_rn(a.z, a.w);
    __half2 h2 = __floats2half2_rn(b.x, b.y);
    __half2 h3 = __floats2half2_rn(b.z, b.w);
    uint4 u;
    u.x = *(unsigned*)&h0; u.y = *(unsigned*)&h1;
    u.z = *(unsigned*)&h2; u.w = *(unsigned*)&h3;
    return u;
}

__global__ void emb2h_kernel(const float* __restrict__ eu, const float* __restrict__ ei) {
    int i = blockIdx.x * blockDim.x + threadIdx.x;
    const int NU8 = N_USER * H / 8;
    const int NI8 = N_ITEM * H / 8;
    if (i < NU8) {
        float4 a = ((const float4*)eu)[2 * i], b = ((const float4*)eu)[2 * i + 1];
        ((uint4*)g_eu16)[i] = pack8(a, b);
    } else if (i < NU8 + NI8) {
        int j = i - NU8;
        float4 a = ((const float4*)ei)[2 * j], b = ((const float4*)ei)[2 * j + 1];
        ((uint4*)g_ei16)[j] = pack8(a, b);
    }
}

// ---------------------------------------------------------------------------
// Weight prep: fp16 half2-packed, K-major pairs.
// ---------------------------------------------------------------------------
__device__ __forceinline__ float wval_item(const float* Wl, const float* Wr, int k, int j) {
    return (k < 128) ? Wr[(0 * H + j) * H + k] : Wl[(0 * H + j) * H + (k - 128)];
}
__device__ __forceinline__ float wval_user(const float* Wl, const float* Wr, int l, int k, int j) {
    if (k < 128) return Wr[((l * 3 + 1) * H + j) * H + k] + Wr[((l * 3 + 2) * H + j) * H + k];
    if (k < 256) return Wl[((l * 3 + 1) * H + j) * H + (k - 128)];
    return Wl[((l * 3 + 2) * H + j) * H + (k - 256)];
}

__global__ void wprep_kernel(const float* __restrict__ Wl, const float* __restrict__ Wr,
                             const float* __restrict__ bl) {
    int idx = blockIdx.x * blockDim.x + threadIdx.x;
    const int WTOT = (128 + 192 + 192) * H;   // 65536 u32
    if (idx < WTOT) {
        float v0, v1;
        if (idx < 128 * H) {
            int k2 = idx >> 7, j = idx & 127;
            v0 = wval_item(Wl, Wr, 2 * k2, j);
            v1 = wval_item(Wl, Wr, 2 * k2 + 1, j);
        } else {
            int rel = idx - 128 * H;
            int l = (rel < 192 * H) ? 0 : 1;
            if (l == 1) rel -= 192 * H;
            int k2 = rel >> 7, j = rel & 127;
            v0 = wval_user(Wl, Wr, l, 2 * k2, j);
            v1 = wval_user(Wl, Wr, l, 2 * k2 + 1, j);
        }
        __half2 h = __floats2half2_rn(v0, v1);
        g_wth[idx] = *(unsigned*)&h;
    } else if (idx < WTOT + 3 * H) {
        int t = idx - WTOT;
        int slot = t >> 7, j = t & 127;
        float b;
        if (slot == 0)      b = bl[0 * H + j];
        else if (slot == 1) b = bl[1 * H + j] + bl[2 * H + j];
        else                b = bl[(3 + 1) * H + j] + bl[(3 + 2) * H + j];
        g_bias[t] = b;
    }
}

// ---------------------------------------------------------------------------
// Gather-mean over fp16 rows (fp32 accumulate), shared body.
// ---------------------------------------------------------------------------
__device__ __forceinline__ void acc4(float4& a, uint2 u) {
    __half2 h0 = *(__half2*)&u.x, h1 = *(__half2*)&u.y;
    float2 f0 = __half22float2(h0), f1 = __half22float2(h1);
    a.x += f0.x; a.y += f0.y; a.z += f1.x; a.w += f1.y;
}

__device__ __forceinline__ void agg_one(int g, int node, int lane,
                                        const __half* __restrict__ src,
                                        __half* __restrict__ dst) {
    int s = g_off[g][node], e = g_off[g][node + 1];
    const int* lst = g_csr[g];
    float4 acc = make_float4(0.f, 0.f, 0.f, 0.f);
    int i = s;
    for (; i + 4 <= e; i += 4) {
        int i0 = lst[i], i1 = lst[i + 1], i2 = lst[i + 2], i3 = lst[i + 3];
        uint2 v0 = *(const uint2*)(src + (size_t)i0 * H + lane * 4);
        uint2 v1 = *(const uint2*)(src + (size_t)i1 * H + lane * 4);
        uint2 v2 = *(const uint2*)(src + (size_t)i2 * H + lane * 4);
        uint2 v3 = *(const uint2*)(src + (size_t)i3 * H + lane * 4);
        acc4(acc, v0); acc4(acc, v1); acc4(acc, v2); acc4(acc, v3);
    }
    for (; i < e; i++) {
        uint2 v0 = *(const uint2*)(src + (size_t)lst[i] * H + lane * 4);
        acc4(acc, v0);
    }
    float inv = (e > s) ? 1.0f / (float)(e - s) : 0.0f;
    __half2 o0 = __floats2half2_rn(acc.x * inv, acc.y * inv);
    __half2 o1 = __floats2half2_rn(acc.z * inv, acc.w * inv);
    uint2 o; o.x = *(unsigned*)&o0; o.y = *(unsigned*)&o1;
    *(uint2*)(dst + lane * 4) = o;
}

// Layer-0 aggregation, pruned: only needed items/users (compact lists).
__global__ void agg_l0_kernel(const __half* __restrict__ eu,
                              const __half* __restrict__ ei) {
    int warp = (blockIdx.x * blockDim.x + threadIdx.x) >> 5;
    int lane = threadIdx.x & 31;
    if (warp < N_ITEM) {
        int nI = __ldg(&g_off[4][N_ITEM]);
        if (warp >= nI) return;
        int node = g_cmpI[warp];
        agg_one(0, node, lane, eu, g_aggI + (size_t)node * H);
    } else {
        int w2 = warp - N_ITEM;
        int nU = __ldg(&g_off[3][N_USER]);
        if (w2 < N_USER) {
            if (w2 >= nU) return;
            int node = g_cmpU[w2];
            agg_one(1, node, lane, ei, g_aggU + (size_t)node * 256);
        } else {
            w2 -= N_USER;
            if (w2 >= N_USER || w2 >= nU) return;
            int node = g_cmpU[w2];
            agg_one(2, node, lane, eu, g_aggU + (size_t)node * 256 + 128);
        }
    }
}

// Layer-1 aggregation: ONLY target users (compact rows 0..N_TGT-1).
__global__ void agg_tgt_kernel(const __half* __restrict__ xi0,
                               const __half* __restrict__ xu0,
                               const int* __restrict__ tgt) {
    int warp = (blockIdx.x * blockDim.x + threadIdx.x) >> 5;
    int lane = threadIdx.x & 31;
    if (warp >= 2 * N_TGT) return;
    int pos = warp & (N_TGT - 1);
    int node = tgt[pos];
    if (warp < N_TGT)
        agg_one(1, node, lane, xi0, g_aggU + (size_t)pos * 256);
    else
        agg_one(2, node, lane, xu0, g_aggU + (size_t)pos * 256 + 128);
}

// ---------------------------------------------------------------------------
// FP16 tensor-core GEMM (cp.async 3-stage) + fused LayerNorm + ReLU, fp16 out.
// Two jobs per launch. Per-source + output row indirection; dynamic row count.
// ---------------------------------------------------------------------------
#define ASTRIDE 36
#define WSTRIDE 136
#define OSTRIDE 132
#define STAGEB  35840

extern __shared__ char g_smraw[];

struct GemmJob {
    __half* out;
    const __half* A0;
    const __half* A1;
    const int* ridx0;        // row index for A0 chunks (optional)
    const int* ridx1;        // row index for A1 chunks (optional)
    const int* ridxo;        // row index for output (optional)
    const int* cnt;          // dynamic row count (optional; else nrows)
    const unsigned* Wt;
    const float* bias;
    const float* gam;
    const float* bet;
    int lda0, lda1, k0c, nchunk, nrows;
};

__device__ __forceinline__ void mma_f16(float c[4], const unsigned a[4], const unsigned b[2]) {
    asm volatile(
        "mma.sync.aligned.m16n8k16.row.col.f32.f16.f16.f32 "
        "{%0,%1,%2,%3}, {%4,%5,%6,%7}, {%8,%9}, {%0,%1,%2,%3};"
        : "+f"(c[0]), "+f"(c[1]), "+f"(c[2]), "+f"(c[3])
        : "r"(a[0]), "r"(a[1]), "r"(a[2]), "r"(a[3]), "r"(b[0]), "r"(b[1]));
}

__global__ void __launch_bounds__(256, 2) gemm_ln_kernel(GemmJob j0, GemmJob j1, int split) {
    GemmJob J = (blockIdx.x < (unsigned)split) ? j0 : j1;
    int bid = (blockIdx.x < (unsigned)split) ? blockIdx.x : blockIdx.x - split;
    int row0 = bid * 128;

    int nrows = J.cnt ? __ldg(J.cnt) : J.nrows;
    if (row0 >= nrows) return;

    int t = threadIdx.x;
    int lane = t & 31;
    int wid = t >> 5;
    int warp_m = wid & 3;
    int warp_n = wid >> 2;
    int gid = lane >> 2;
    int tig = lane & 3;

    float c[2][8][4];
    #pragma unroll
    for (int nt = 0; nt < 8; nt++) {
        int col = warp_n * 64 + nt * 8 + 2 * tig;
        float b0 = J.bias[col], b1 = J.bias[col + 1];
        #pragma unroll
        for (int mt = 0; mt < 2; mt++) {
            c[mt][nt][0] = b0; c[mt][nt][1] = b1;
            c[mt][nt][2] = b0; c[mt][nt][3] = b1;
        }
    }

    auto load_chunk = [&](int ck, int st) {
        if (ck < J.nchunk) {
            const __half* A; int lda, cb; const int* ridx;
            if (ck < J.k0c) { A = J.A0; lda = J.lda0; cb = ck * 64; ridx = J.ridx0; }
            else            { A = J.A1; lda = J.lda1; cb = (ck - J.k0c) * 64; ridx = J.ridx1; }
            unsigned* As = (unsigned*)(g_smraw + st * STAGEB);
            #pragma unroll
            for (int i2 = 0; i2 < 4; i2++) {
                int idx = t + 256 * i2;
                int r = idx >> 3, u = idx & 7;
                int base = row0 + r;
                int ok = (base < nrows);
                if (!ok) base = row0;
                int row = ridx ? __ldg(ridx + base) : base;
                const __half* src = A + (size_t)row * lda + cb + u * 8;
                CP16(smem_u32(As + r * ASTRIDE + u * 4), src, ok ? 16 : 0);
            }
            unsigned* Ws = (unsigned*)(g_smraw + st * STAGEB + 128 * ASTRIDE * 4);
            #pragma unroll
            for (int i2 = 0; i2 < 4; i2++) {
                int idx = t + 256 * i2;
                int rr = idx >> 5, u = idx & 31;
                const unsigned* src = J.Wt + (size_t)(ck * 32 + rr) * H + u * 4;
                CP16(smem_u32(Ws + rr * WSTRIDE + u * 4), src, 16);
            }
        }
        asm volatile("cp.async.commit_group;\n" ::);
    };

    load_chunk(0, 0);
    load_chunk(1, 1);

    for (int ck = 0; ck < J.nchunk; ck++) {
        asm volatile("cp.async.wait_group 1;\n" ::);
        __syncthreads();
        load_chunk(ck + 2, (ck + 2) % 3);

        int st = ck % 3;
        const unsigned* As = (const unsigned*)(g_smraw + st * STAGEB);
        const unsigned* Ws = (const unsigned*)(g_smraw + st * STAGEB + 128 * ASTRIDE * 4);
        #pragma unroll
        for (int ks = 0; ks < 4; ks++) {
            int k2 = ks * 8;
            unsigned a[2][4];
            #pragma unroll
            for (int mt = 0; mt < 2; mt++) {
                int r = warp_m * 32 + mt * 16 + gid;
                a[mt][0] = As[r * ASTRIDE + k2 + tig];
                a[mt][1] = As[(r + 8) * ASTRIDE + k2 + tig];
                a[mt][2] = As[r * ASTRIDE + k2 + tig + 4];
                a[mt][3] = As[(r + 8) * ASTRIDE + k2 + tig + 4];
            }
            unsigned b[8][2];
            #pragma unroll
            for (int nt = 0; nt < 8; nt++) {
                int cc = warp_n * 64 + nt * 8 + gid;
                b[nt][0] = Ws[(k2 + tig) * WSTRIDE + cc];
                b[nt][1] = Ws[(k2 + tig + 4) * WSTRIDE + cc];
            }
            #pragma unroll
            for (int mt = 0; mt < 2; mt++)
                #pragma unroll
                for (int nt = 0; nt < 8; nt++)
                    mma_f16(c[mt][nt], a[mt], b[nt]);
        }
    }

    // ---- epilogue: stage fp32 to smem, fused LayerNorm + ReLU, fp16 out ----
    asm volatile("cp.async.wait_group 0;\n" ::);
    __syncthreads();
    float* Osm = (float*)g_smraw;
    #pragma unroll
    for (int mt = 0; mt < 2; mt++) {
        #pragma unroll
        for (int nt = 0; nt < 8; nt++) {
            int col = warp_n * 64 + nt * 8 + 2 * tig;
            int r = warp_m * 32 + mt * 16 + gid;
            *(float2*)(Osm + r * OSTRIDE + col)       = make_float2(c[mt][nt][0], c[mt][nt][1]);
            *(float2*)(Osm + (r + 8) * OSTRIDE + col) = make_float2(c[mt][nt][2], c[mt][nt][3]);
        }
    }
    __syncthreads();

    float4 gg = *(const float4*)(J.gam + lane * 4);
    float4 bb = *(const float4*)(J.bet + lane * 4);
    #pragma unroll
    for (int i = 0; i < 16; i++) {
        int r = wid * 16 + i;
        int base = row0 + r;
        if (base >= nrows) break;
        float4 v = *(float4*)(Osm + r * OSTRIDE + lane * 4);
        float s1 = v.x + v.y + v.z + v.w;
        float s2 = v.x * v.x + v.y * v.y + v.z * v.z + v.w * v.w;
        #pragma unroll
        for (int o = 16; o; o >>= 1) {
            s1 += __shfl_xor_sync(0xffffffffu, s1, o);
            s2 += __shfl_xor_sync(0xffffffffu, s2, o);
        }
        float mu = s1 * (1.0f / H);
        float var = s2 * (1.0f / H) - mu * mu;
        float rs = rsqrtf(var + 1e-5f);
        float ox = fmaxf((v.x - mu) * rs * gg.x + bb.x, 0.f);
        float oy = fmaxf((v.y - mu) * rs * gg.y + bb.y, 0.f);
        float oz = fmaxf((v.z - mu) * rs * gg.z + bb.z, 0.f);
        float ow = fmaxf((v.w - mu) * rs * gg.w + bb.w, 0.f);
        __half2 h0 = __floats2half2_rn(ox, oy);
        __half2 h1 = __floats2half2_rn(oz, ow);
        uint2 o; o.x = *(unsigned*)&h0; o.y = *(unsigned*)&h1;
        int orow = J.ridxo ? __ldg(J.ridxo + base) : base;
        *(uint2*)(J.out + (size_t)orow * H + lane * 4) = o;
    }
}

// ---------------------------------------------------------------------------
// MLP head on compact target features: one warp per target position.
// ---------------------------------------------------------------------------
__global__ void mlp_kernel(const __half* __restrict__ xuc,
                           const float* __restrict__ W1, const float* __restrict__ b1,
                           const float* __restrict__ W2, const float* __restrict__ b2,
                           float* __restrict__ out) {
    int warp = (blockIdx.x * blockDim.x + threadIdx.x) >> 5;
    int lane = threadIdx.x & 31;
    if (warp >= N_TGT) return;
    uint2 xr = *(const uint2*)(xuc + (size_t)warp * H + lane * 4);
    float2 x0 = __half22float2(*(__half2*)&xr.x);
    float2 x1 = __half22float2(*(__half2*)&xr.y);
    float acc = 0.f;
    #pragma unroll 4
    for (int j = 0; j < 64; j++) {
        float4 w = *(const float4*)(W1 + j * H + lane * 4);
        float p = x0.x * w.x + x0.y * w.y + x1.x * w.z + x1.y * w.w;
        #pragma unroll
        for (int o = 16; o; o >>= 1) p += __shfl_xor_sync(0xffffffffu, p, o);
        float h = fmaxf(p + b1[j], 0.f);
        acc += h * W2[j];
    }
    if (lane == 0) out[warp] = acc + b2[0];
}

// ---------------------------------------------------------------------------
// Launch
// ---------------------------------------------------------------------------
extern "C" void kernel_launch(void* const* d_in, const int* in_sizes, int n_in,
                              void* d_out, int out_size) {
    const float* emb_user = (const float*)d_in[0];
    const float* emb_item = (const float*)d_in[1];
    const float* Wl       = (const float*)d_in[2];
    const float* bl       = (const float*)d_in[3];
    const float* Wr       = (const float*)d_in[4];
    const float* ln_g     = (const float*)d_in[5];
    const float* ln_b     = (const float*)d_in[6];
    const float* W1       = (const float*)d_in[7];
    const float* b1       = (const float*)d_in[8];
    const float* W2       = (const float*)d_in[9];
    const float* b2       = (const float*)d_in[10];
    const int* src_buys   = (const int*)d_in[11];
    const int* dst_buys   = (const int*)d_in[12];
    const int* src_rev    = (const int*)d_in[13];
    const int* dst_rev    = (const int*)d_in[14];
    const int* src_fol    = (const int*)d_in[15];
    const int* dst_fol    = (const int*)d_in[16];
    const int* target_ids = (const int*)d_in[17];
    float* out = (float*)d_out;

    __half *p_eu16, *p_ei16, *p_xu0h, *p_xi0h, *p_xufh, *p_aggU, *p_aggI;
    unsigned* p_wth;
    float* p_bias;
    int *p_off, *p_cmpU, *p_cmpI;
    cudaGetSymbolAddress((void**)&p_eu16, g_eu16);
    cudaGetSymbolAddress((void**)&p_ei16, g_ei16);
    cudaGetSymbolAddress((void**)&p_xu0h, g_xu0h);
    cudaGetSymbolAddress((void**)&p_xi0h, g_xi0h);
    cudaGetSymbolAddress((void**)&p_xufh, g_xufh);
    cudaGetSymbolAddress((void**)&p_aggU, g_aggU);
    cudaGetSymbolAddress((void**)&p_aggI, g_aggI);
    cudaGetSymbolAddress((void**)&p_wth,  g_wth);
    cudaGetSymbolAddress((void**)&p_bias, g_bias);
    cudaGetSymbolAddress((void**)&p_off,  g_off);
    cudaGetSymbolAddress((void**)&p_cmpU, g_cmpU);
    cudaGetSymbolAddress((void**)&p_cmpI, g_cmpI);

    const int* p_cntU = p_off + 3 * (N_USER + 1) + N_USER;   // g_off[3][N_USER]
    const int* p_cntI = p_off + 4 * (N_USER + 1) + N_ITEM;   // g_off[4][N_ITEM]

    const int smem_bytes = 3 * STAGEB;   // 107520
    cudaFuncSetAttribute(gemm_ln_kernel,
                         cudaFuncAttributeMaxDynamicSharedMemorySize, smem_bytes);

    // --- prep + CSR + pruning flags ---
    zero_kernel<<<(3 * (N_USER + 1) + 255) / 256, 256>>>();
    emb2h_kernel<<<((N_USER + N_ITEM) * H / 8 + 255) / 256, 256>>>(emb_user, emb_item);
    wprep_kernel<<<((128 + 192 + 192) * H + 3 * H + 255) / 256, 256>>>(Wl, Wr, bl);
    flag_tgt_kernel<<<(N_TGT + 255) / 256, 256>>>(target_ids);
    flag_edges_kernel<<<(2 * NE4 + 255) / 256, 256>>>(dst_fol, src_fol, dst_rev, src_rev);
    count_all_kernel<<<(3 * NE4 + 255) / 256, 256>>>(dst_buys, dst_rev, dst_fol);
    scan_p1_kernel<<<dim3(NBLK_U, 5), 1024>>>();
    scan_p2_kernel<<<1, 640>>>();
    scan_p3_kernel<<<dim3(NBLK_U, 5), 1024>>>();
    fill_all_kernel<<<(3 * NE4 + 255) / 256, 256>>>(dst_buys, src_buys,
                                                    dst_rev, src_rev,
                                                    dst_fol, src_fol);

    // ===== layer 0 (pruned to needed nodes) =====
    {
        int nwarp = N_ITEM + 2 * N_USER;
        agg_l0_kernel<<<(nwarp * 32 + 255) / 256, 256>>>(p_eu16, p_ei16);

        GemmJob ji, ju;
        // item: xi0[cmpI] = LNReLU(emb_item@Wr0 + mbuy@Wl0 + b)
        ji.out = p_xi0h; ji.A0 = p_ei16; ji.A1 = p_aggI;
        ji.ridx0 = p_cmpI; ji.ridx1 = p_cmpI; ji.ridxo = p_cmpI; ji.cnt = p_cntI;
        ji.Wt = p_wth; ji.bias = p_bias;
        ji.gam = ln_g + 1 * H; ji.bet = ln_b + 1 * H;
        ji.lda0 = H; ji.lda1 = H; ji.k0c = 2; ji.nchunk = 4; ji.nrows = N_ITEM;
        // user0: xu0[cmpU] = ...
        ju.out = p_xu0h; ju.A0 = p_eu16; ju.A1 = p_aggU;
        ju.ridx0 = p_cmpU; ju.ridx1 = p_cmpU; ju.ridxo = p_cmpU; ju.cnt = p_cntU;
        ju.Wt = p_wth + 128 * H; ju.bias = p_bias + 1 * H;
        ju.gam = ln_g + 0 * H; ju.bet = ln_b + 0 * H;
        ju.lda0 = H; ju.lda1 = 256; ju.k0c = 2; ju.nchunk = 6; ju.nrows = N_USER;

        int nbi = (N_ITEM + 127) / 128;          // 391 (worst case)
        int nbu = (N_USER + 127) / 128;          // 782 (worst case)
        gemm_ln_kernel<<<nbi + nbu, 256, smem_bytes>>>(ji, ju, nbi);
    }
    // ===== layer 1: only target rows =====
    {
        agg_tgt_kernel<<<(2 * N_TGT * 32 + 255) / 256, 256>>>(p_xi0h, p_xu0h, target_ids);

        GemmJob jt;
        jt.out = p_xufh; jt.A0 = p_xu0h; jt.A1 = p_aggU;
        jt.ridx0 = target_ids; jt.ridx1 = nullptr; jt.ridxo = nullptr; jt.cnt = nullptr;
        jt.Wt = p_wth + (128 + 192) * H; jt.bias = p_bias + 2 * H;
        jt.gam = ln_g + 2 * H; jt.bet = ln_b + 2 * H;
        jt.lda0 = H; jt.lda1 = 256; jt.k0c = 2; jt.nchunk = 6; jt.nrows = N_TGT;

        int nbt = N_TGT / 128;                   // 64
        gemm_ln_kernel<<<nbt, 256, smem_bytes>>>(jt, jt, nbt);
    }

    mlp_kernel<<<(N_TGT * 32 + 255) / 256, 256>>>(
        p_xufh, W1, b1, W2, b2, out);
}

// round 7
// speedup vs baseline: 4.9116x; 1.0467x over previous
#include <cuda_runtime.h>
#include <cuda_fp16.h>
#include <cstdint>

#define N_USER 100000
#define N_ITEM 50000
#define NE     800000
#define NE4    (NE / 4)
#define H      128
#define N_TGT  8192

#define NBLK_U 98   // ceil(100000/1024)

// ---------------------------------------------------------------------------
// Static device scratch (fp16 feature world)
// ---------------------------------------------------------------------------
__device__ __half g_eu16[N_USER * H];       // emb_user in fp16
__device__ __half g_ei16[N_ITEM * H];       // emb_item in fp16
__device__ __half g_xu0h[N_USER * H];       // user feats after layer 0 (needed rows only)
__device__ __half g_xi0h[N_ITEM * H];       // item feats after layer 0 (needed rows only)
__device__ __half g_xufh[N_TGT * H];        // compact target feats after layer 1
__device__ __half g_aggU[N_USER * 256];     // layer0: [mrev|mfol] at node pos; layer1: compact rows
__device__ __half g_aggI[N_ITEM * H];       // mbuy fp16
__device__ unsigned g_wth[(128 + 192 + 192) * H];   // fp16 half2-packed K-major weights
__device__ float g_bias[3 * H];             // fused biases

// CSR + scan scratch. scan rows: 0..2 = graph degree counts, 3 = needU, 4 = needI
__device__ int g_cnt[3][N_USER + 1];
__device__ int g_off[5][N_USER + 1];
__device__ int g_cur[3][N_USER];
__device__ int g_csr[3][NE];
__device__ int g_bsum[5][128];
__device__ int g_bbase[5][128];

// pruning
__device__ int g_tflag[N_USER];             // is-target flag
__device__ int g_needU[N_USER];
__device__ int g_needI[N_ITEM];
__device__ int g_cmpU[N_USER];              // compact list of needed users
__device__ int g_cmpI[N_ITEM];              // compact list of needed items

// graph ids: 0 = buys (dst=item), 1 = rev (dst=user), 2 = fol (dst=user)

__device__ __forceinline__ unsigned smem_u32(const void* p) {
    return (unsigned)__cvta_generic_to_shared(p);
}
#define CP16(dst, src, sz) \
    asm volatile("cp.async.cg.shared.global [%0], [%1], 16, %2;\n" \
                 :: "r"(dst), "l"(src), "r"(sz))

// ---------------------------------------------------------------------------
// Fused prep: zero scratch + emb->fp16 + weight/bias prep (disjoint ranges)
// ---------------------------------------------------------------------------
#define NU8   (N_USER * H / 8)      // 1,600,000
#define NI8   (N_ITEM * H / 8)      //   800,000
#define ZCNT  (3 * (N_USER + 1))    //   300,003
#define WTOT  ((128 + 192 + 192) * H)  // 65,536
#define PREP_TOT (NU8 + NI8 + ZCNT + N_USER + N_ITEM + WTOT + 3 * H)

__device__ __forceinline__ uint4 pack8(float4 a, float4 b) {
    __half2 h0 = __floats2half2_rn(a.x, a.y);
    __half2 h1 = __floats2half2_rn(a.z, a.w);
    __half2 h2 = __floats2half2_rn(b.x, b.y);
    __half2 h3 = __floats2half2_rn(b.z, b.w);
    uint4 u;
    u.x = *(unsigned*)&h0; u.y = *(unsigned*)&h1;
    u.z = *(unsigned*)&h2; u.w = *(unsigned*)&h3;
    return u;
}

__device__ __forceinline__ float wval_item(const float* Wl, const float* Wr, int k, int j) {
    return (k < 128) ? Wr[(0 * H + j) * H + k] : Wl[(0 * H + j) * H + (k - 128)];
}
__device__ __forceinline__ float wval_user(const float* Wl, const float* Wr, int l, int k, int j) {
    if (k < 128) return Wr[((l * 3 + 1) * H + j) * H + k] + Wr[((l * 3 + 2) * H + j) * H + k];
    if (k < 256) return Wl[((l * 3 + 1) * H + j) * H + (k - 128)];
    return Wl[((l * 3 + 2) * H + j) * H + (k - 256)];
}

__global__ void prep_kernel(const float* __restrict__ eu, const float* __restrict__ ei,
                            const float* __restrict__ Wl, const float* __restrict__ Wr,
                            const float* __restrict__ bl) {
    int i = blockIdx.x * blockDim.x + threadIdx.x;
    if (i < NU8) {
        float4 a = ((const float4*)eu)[2 * i], b = ((const float4*)eu)[2 * i + 1];
        ((uint4*)g_eu16)[i] = pack8(a, b);
        return;
    }
    int j = i - NU8;
    if (j < NI8) {
        float4 a = ((const float4*)ei)[2 * j], b = ((const float4*)ei)[2 * j + 1];
        ((uint4*)g_ei16)[j] = pack8(a, b);
        return;
    }
    j -= NI8;
    if (j < ZCNT) { ((int*)g_cnt)[j] = 0; return; }
    j -= ZCNT;
    if (j < N_USER) { g_needU[j] = 0; g_tflag[j] = 0; return; }
    j -= N_USER;
    if (j < N_ITEM) { g_needI[j] = 0; return; }
    j -= N_ITEM;
    if (j < WTOT) {
        float v0, v1;
        if (j < 128 * H) {
            int k2 = j >> 7, c = j & 127;
            v0 = wval_item(Wl, Wr, 2 * k2, c);
            v1 = wval_item(Wl, Wr, 2 * k2 + 1, c);
        } else {
            int rel = j - 128 * H;
            int l = (rel < 192 * H) ? 0 : 1;
            if (l == 1) rel -= 192 * H;
            int k2 = rel >> 7, c = rel & 127;
            v0 = wval_user(Wl, Wr, l, 2 * k2, c);
            v1 = wval_user(Wl, Wr, l, 2 * k2 + 1, c);
        }
        __half2 h = __floats2half2_rn(v0, v1);
        g_wth[j] = *(unsigned*)&h;
        return;
    }
    j -= WTOT;
    if (j < 3 * H) {
        int slot = j >> 7, c = j & 127;
        float b;
        if (slot == 0)      b = bl[0 * H + c];
        else if (slot == 1) b = bl[1 * H + c] + bl[2 * H + c];
        else                b = bl[(3 + 1) * H + c] + bl[(3 + 2) * H + c];
        g_bias[j] = b;
    }
}

__global__ void flag_tgt_kernel(const int* __restrict__ tgt) {
    int i = blockIdx.x * blockDim.x + threadIdx.x;
    if (i < N_TGT) {
        int t = tgt[i];
        g_tflag[t] = 1;
        g_needU[t] = 1;
    }
}

// ---------------------------------------------------------------------------
// Fused degree count + need-flag marking (one pass over all edge lists)
// ---------------------------------------------------------------------------
__global__ void count_flag_kernel(const int* __restrict__ d0,
                                  const int* __restrict__ d1, const int* __restrict__ s1,
                                  const int* __restrict__ d2, const int* __restrict__ s2) {
    int i = blockIdx.x * blockDim.x + threadIdx.x;
    if (i >= 3 * NE4) return;
    int g = i / NE4, j = i % NE4;
    if (g == 0) {
        int4 v = ((const int4*)d0)[j];
        atomicAdd(&g_cnt[0][v.x], 1);
        atomicAdd(&g_cnt[0][v.y], 1);
        atomicAdd(&g_cnt[0][v.z], 1);
        atomicAdd(&g_cnt[0][v.w], 1);
    } else if (g == 1) {
        int4 d = ((const int4*)d1)[j];
        int4 s = ((const int4*)s1)[j];
        atomicAdd(&g_cnt[1][d.x], 1);
        atomicAdd(&g_cnt[1][d.y], 1);
        atomicAdd(&g_cnt[1][d.z], 1);
        atomicAdd(&g_cnt[1][d.w], 1);
        if (g_tflag[d.x]) g_needI[s.x] = 1;
        if (g_tflag[d.y]) g_needI[s.y] = 1;
        if (g_tflag[d.z]) g_needI[s.z] = 1;
        if (g_tflag[d.w]) g_needI[s.w] = 1;
    } else {
        int4 d = ((const int4*)d2)[j];
        int4 s = ((const int4*)s2)[j];
        atomicAdd(&g_cnt[2][d.x], 1);
        atomicAdd(&g_cnt[2][d.y], 1);
        atomicAdd(&g_cnt[2][d.z], 1);
        atomicAdd(&g_cnt[2][d.w], 1);
        if (g_tflag[d.x]) g_needU[s.x] = 1;
        if (g_tflag[d.y]) g_needU[s.y] = 1;
        if (g_tflag[d.z]) g_needU[s.z] = 1;
        if (g_tflag[d.w]) g_needU[s.w] = 1;
    }
}

// ---------------------------------------------------------------------------
// 3-phase parallel scan over 5 rows (3 degree rows, needU, needI)
// ---------------------------------------------------------------------------
__device__ __forceinline__ int scan_val(int g, int i) {
    if (g < 3) return g_cnt[g][i];
    if (g == 3) return g_needU[i];
    return g_needI[i];
}
__device__ __forceinline__ int scan_n(int g) {
    return (g == 0 || g == 4) ? N_ITEM : N_USER;
}

__global__ void scan_p1_kernel() {
    int g = blockIdx.y;
    int n = scan_n(g);
    int base = blockIdx.x * 1024;
    if (base >= n) return;
    int i = base + (int)threadIdx.x;
    int v = (i < n) ? scan_val(g, i) : 0;
    int lane = threadIdx.x & 31, wid = threadIdx.x >> 5;
    __shared__ int warp_sums[32];
    int x = v;
    #pragma unroll
    for (int s = 1; s < 32; s <<= 1) {
        int y = __shfl_up_sync(0xffffffffu, x, s);
        if (lane >= s) x += y;
    }
    if (lane == 31) warp_sums[wid] = x;
    __syncthreads();
    if (wid == 0) {
        int w = warp_sums[lane];
        int xw = w;
        #pragma unroll
        for (int s = 1; s < 32; s <<= 1) {
            int y = __shfl_up_sync(0xffffffffu, xw, s);
            if (lane >= s) xw += y;
        }
        warp_sums[lane] = xw - w;
    }
    __syncthreads();
    int incl = x + warp_sums[wid];
    if (i < n) g_off[g][i] = incl - v;
    if (threadIdx.x == 1023) g_bsum[g][blockIdx.x] = incl;
}

__global__ void scan_p2_kernel() {
    int g = threadIdx.x >> 7;
    int i = threadIdx.x & 127;
    int n = scan_n(g);
    int nb = (n + 1023) / 1024;
    int v = (i < nb) ? g_bsum[g][i] : 0;
    int lane = i & 31, w = i >> 5;
    int x = v;
    #pragma unroll
    for (int s = 1; s < 32; s <<= 1) {
        int y = __shfl_up_sync(0xffffffffu, x, s);
        if (lane >= s) x += y;
    }
    __shared__ int ws[5][4];
    if (lane == 31) ws[g][w] = x;
    __syncthreads();
    int add = 0;
    for (int k = 0; k < w; k++) add += ws[g][k];
    x += add;
    if (i < nb) g_bbase[g][i] = x - v;
    if (i == nb - 1) g_off[g][n] = x;   // total
}

__global__ void scan_p3_kernel() {
    int g = blockIdx.y;
    int n = scan_n(g);
    int i = blockIdx.x * 1024 + threadIdx.x;
    if (i >= n) return;
    int val = g_off[g][i] + g_bbase[g][blockIdx.x];
    if (g < 3) {
        g_off[g][i] = val;
        g_cur[g][i] = val;
    } else if (g == 3) {
        if (g_needU[i]) g_cmpU[val] = i;
    } else {
        if (g_needI[i]) g_cmpI[val] = i;
    }
}

// Filtered fill: only insert edges whose dst node is ever read downstream.
__global__ void fill_all_kernel(const int* __restrict__ d0, const int* __restrict__ s0,
                                const int* __restrict__ d1, const int* __restrict__ s1,
                                const int* __restrict__ d2, const int* __restrict__ s2) {
    int i = blockIdx.x * blockDim.x + threadIdx.x;
    if (i >= 3 * NE4) return;
    int g = i / NE4, j = i % NE4;
    const int* d = (g == 0) ? d0 : (g == 1) ? d1 : d2;
    const int* s = (g == 0) ? s0 : (g == 1) ? s1 : s2;
    const int* need = (g == 0) ? g_needI : g_needU;
    int4 dv = ((const int4*)d)[j];
    int4 sv = ((const int4*)s)[j];
    if (need[dv.x]) g_csr[g][atomicAdd(&g_cur[g][dv.x], 1)] = sv.x;
    if (need[dv.y]) g_csr[g][atomicAdd(&g_cur[g][dv.y], 1)] = sv.y;
    if (need[dv.z]) g_csr[g][atomicAdd(&g_cur[g][dv.z], 1)] = sv.z;
    if (need[dv.w]) g_csr[g][atomicAdd(&g_cur[g][dv.w], 1)] = sv.w;
}

// ---------------------------------------------------------------------------
// Gather-mean over fp16 rows (fp32 accumulate), shared body.
// ---------------------------------------------------------------------------
__device__ __forceinline__ void acc4(float4& a, uint2 u) {
    __half2 h0 = *(__half2*)&u.x, h1 = *(__half2*)&u.y;
    float2 f0 = __half22float2(h0), f1 = __half22float2(h1);
    a.x += f0.x; a.y += f0.y; a.z += f1.x; a.w += f1.y;
}

__device__ __forceinline__ void agg_one(int g, int node, int lane,
                                        const __half* __restrict__ src,
                                        __half* __restrict__ dst) {
    int s = g_off[g][node], e = g_off[g][node + 1];
    const int* lst = g_csr[g];
    float4 acc = make_float4(0.f, 0.f, 0.f, 0.f);
    int i = s;
    for (; i + 4 <= e; i += 4) {
        int i0 = lst[i], i1 = lst[i + 1], i2 = lst[i + 2], i3 = lst[i + 3];
        uint2 v0 = *(const uint2*)(src + (size_t)i0 * H + lane * 4);
        uint2 v1 = *(const uint2*)(src + (size_t)i1 * H + lane * 4);
        uint2 v2 = *(const uint2*)(src + (size_t)i2 * H + lane * 4);
        uint2 v3 = *(const uint2*)(src + (size_t)i3 * H + lane * 4);
        acc4(acc, v0); acc4(acc, v1); acc4(acc, v2); acc4(acc, v3);
    }
    for (; i < e; i++) {
        uint2 v0 = *(const uint2*)(src + (size_t)lst[i] * H + lane * 4);
        acc4(acc, v0);
    }
    float inv = (e > s) ? 1.0f / (float)(e - s) : 0.0f;
    __half2 o0 = __floats2half2_rn(acc.x * inv, acc.y * inv);
    __half2 o1 = __floats2half2_rn(acc.z * inv, acc.w * inv);
    uint2 o; o.x = *(unsigned*)&o0; o.y = *(unsigned*)&o1;
    *(uint2*)(dst + lane * 4) = o;
}

// Layer-0 aggregation, pruned: only needed items/users (compact lists).
__global__ void agg_l0_kernel(const __half* __restrict__ eu,
                              const __half* __restrict__ ei) {
    int warp = (blockIdx.x * blockDim.x + threadIdx.x) >> 5;
    int lane = threadIdx.x & 31;
    if (warp < N_ITEM) {
        int nI = __ldg(&g_off[4][N_ITEM]);
        if (warp >= nI) return;
        int node = g_cmpI[warp];
        agg_one(0, node, lane, eu, g_aggI + (size_t)node * H);
    } else {
        int w2 = warp - N_ITEM;
        int nU = __ldg(&g_off[3][N_USER]);
        if (w2 < N_USER) {
            if (w2 >= nU) return;
            int node = g_cmpU[w2];
            agg_one(1, node, lane, ei, g_aggU + (size_t)node * 256);
        } else {
            w2 -= N_USER;
            if (w2 >= N_USER || w2 >= nU) return;
            int node = g_cmpU[w2];
            agg_one(2, node, lane, eu, g_aggU + (size_t)node * 256 + 128);
        }
    }
}

// Layer-1 aggregation: ONLY target users (compact rows 0..N_TGT-1).
__global__ void agg_tgt_kernel(const __half* __restrict__ xi0,
                               const __half* __restrict__ xu0,
                               const int* __restrict__ tgt) {
    int warp = (blockIdx.x * blockDim.x + threadIdx.x) >> 5;
    int lane = threadIdx.x & 31;
    if (warp >= 2 * N_TGT) return;
    int pos = warp & (N_TGT - 1);
    int node = tgt[pos];
    if (warp < N_TGT)
        agg_one(1, node, lane, xi0, g_aggU + (size_t)pos * 256);
    else
        agg_one(2, node, lane, xu0, g_aggU + (size_t)pos * 256 + 128);
}

// ---------------------------------------------------------------------------
// FP16 tensor-core GEMM (cp.async 3-stage) + fused LayerNorm + ReLU, fp16 out.
// Two jobs per launch. Per-source + output row indirection; dynamic row count.
// ---------------------------------------------------------------------------
#define ASTRIDE 36
#define WSTRIDE 136
#define OSTRIDE 132
#define STAGEB  35840

extern __shared__ char g_smraw[];

struct GemmJob {
    __half* out;
    const __half* A0;
    const __half* A1;
    const int* ridx0;
    const int* ridx1;
    const int* ridxo;
    const int* cnt;
    const unsigned* Wt;
    const float* bias;
    const float* gam;
    const float* bet;
    int lda0, lda1, k0c, nchunk, nrows;
};

__device__ __forceinline__ void mma_f16(float c[4], const unsigned a[4], const unsigned b[2]) {
    asm volatile(
        "mma.sync.aligned.m16n8k16.row.col.f32.f16.f16.f32 "
        "{%0,%1,%2,%3}, {%4,%5,%6,%7}, {%8,%9}, {%0,%1,%2,%3};"
        : "+f"(c[0]), "+f"(c[1]), "+f"(c[2]), "+f"(c[3])
        : "r"(a[0]), "r"(a[1]), "r"(a[2]), "r"(a[3]), "r"(b[0]), "r"(b[1]));
}

__global__ void __launch_bounds__(256, 2) gemm_ln_kernel(GemmJob j0, GemmJob j1, int split) {
    GemmJob J = (blockIdx.x < (unsigned)split) ? j0 : j1;
    int bid = (blockIdx.x < (unsigned)split) ? blockIdx.x : blockIdx.x - split;
    int row0 = bid * 128;

    int nrows = J.cnt ? __ldg(J.cnt) : J.nrows;
    if (row0 >= nrows) return;

    int t = threadIdx.x;
    int lane = t & 31;
    int wid = t >> 5;
    int warp_m = wid & 3;
    int warp_n = wid >> 2;
    int gid = lane >> 2;
    int tig = lane & 3;

    float c[2][8][4];
    #pragma unroll
    for (int nt = 0; nt < 8; nt++) {
        int col = warp_n * 64 + nt * 8 + 2 * tig;
        float b0 = J.bias[col], b1 = J.bias[col + 1];
        #pragma unroll
        for (int mt = 0; mt < 2; mt++) {
            c[mt][nt][0] = b0; c[mt][nt][1] = b1;
            c[mt][nt][2] = b0; c[mt][nt][3] = b1;
        }
    }

    auto load_chunk = [&](int ck, int st) {
        if (ck < J.nchunk) {
            const __half* A; int lda, cb; const int* ridx;
            if (ck < J.k0c) { A = J.A0; lda = J.lda0; cb = ck * 64; ridx = J.ridx0; }
            else            { A = J.A1; lda = J.lda1; cb = (ck - J.k0c) * 64; ridx = J.ridx1; }
            unsigned* As = (unsigned*)(g_smraw + st * STAGEB);
            #pragma unroll
            for (int i2 = 0; i2 < 4; i2++) {
                int idx = t + 256 * i2;
                int r = idx >> 3, u = idx & 7;
                int base = row0 + r;
                int ok = (base < nrows);
                if (!ok) base = row0;
                int row = ridx ? __ldg(ridx + base) : base;
                const __half* src = A + (size_t)row * lda + cb + u * 8;
                CP16(smem_u32(As + r * ASTRIDE + u * 4), src, ok ? 16 : 0);
            }
            unsigned* Ws = (unsigned*)(g_smraw + st * STAGEB + 128 * ASTRIDE * 4);
            #pragma unroll
            for (int i2 = 0; i2 < 4; i2++) {
                int idx = t + 256 * i2;
                int rr = idx >> 5, u = idx & 31;
                const unsigned* src = J.Wt + (size_t)(ck * 32 + rr) * H + u * 4;
                CP16(smem_u32(Ws + rr * WSTRIDE + u * 4), src, 16);
            }
        }
        asm volatile("cp.async.commit_group;\n" ::);
    };

    load_chunk(0, 0);
    load_chunk(1, 1);

    for (int ck = 0; ck < J.nchunk; ck++) {
        asm volatile("cp.async.wait_group 1;\n" ::);
        __syncthreads();
        load_chunk(ck + 2, (ck + 2) % 3);

        int st = ck % 3;
        const unsigned* As = (const unsigned*)(g_smraw + st * STAGEB);
        const unsigned* Ws = (const unsigned*)(g_smraw + st * STAGEB + 128 * ASTRIDE * 4);
        #pragma unroll
        for (int ks = 0; ks < 4; ks++) {
            int k2 = ks * 8;
            unsigned a[2][4];
            #pragma unroll
            for (int mt = 0; mt < 2; mt++) {
                int r = warp_m * 32 + mt * 16 + gid;
                a[mt][0] = As[r * ASTRIDE + k2 + tig];
                a[mt][1] = As[(r + 8) * ASTRIDE + k2 + tig];
                a[mt][2] = As[r * ASTRIDE + k2 + tig + 4];
                a[mt][3] = As[(r + 8) * ASTRIDE + k2 + tig + 4];
            }
            unsigned b[8][2];
            #pragma unroll
            for (int nt = 0; nt < 8; nt++) {
                int cc = warp_n * 64 + nt * 8 + gid;
                b[nt][0] = Ws[(k2 + tig) * WSTRIDE + cc];
                b[nt][1] = Ws[(k2 + tig + 4) * WSTRIDE + cc];
            }
            #pragma unroll
            for (int mt = 0; mt < 2; mt++)
                #pragma unroll
                for (int nt = 0; nt < 8; nt++)
                    mma_f16(c[mt][nt], a[mt], b[nt]);
        }
    }

    // ---- epilogue: stage fp32 to smem, fused LayerNorm + ReLU, fp16 out ----
    asm volatile("cp.async.wait_group 0;\n" ::);
    __syncthreads();
    float* Osm = (float*)g_smraw;
    #pragma unroll
    for (int mt = 0; mt < 2; mt++) {
        #pragma unroll
        for (int nt = 0; nt < 8; nt++) {
            int col = warp_n * 64 + nt * 8 + 2 * tig;
            int r = warp_m * 32 + mt * 16 + gid;
            *(float2*)(Osm + r * OSTRIDE + col)       = make_float2(c[mt][nt][0], c[mt][nt][1]);
            *(float2*)(Osm + (r + 8) * OSTRIDE + col) = make_float2(c[mt][nt][2], c[mt][nt][3]);
        }
    }
    __syncthreads();

    float4 gg = *(const float4*)(J.gam + lane * 4);
    float4 bb = *(const float4*)(J.bet + lane * 4);
    #pragma unroll
    for (int i = 0; i < 16; i++) {
        int r = wid * 16 + i;
        int base = row0 + r;
        if (base >= nrows) break;
        float4 v = *(float4*)(Osm + r * OSTRIDE + lane * 4);
        float s1 = v.x + v.y + v.z + v.w;
        float s2 = v.x * v.x + v.y * v.y + v.z * v.z + v.w * v.w;
        #pragma unroll
        for (int o = 16; o; o >>= 1) {
            s1 += __shfl_xor_sync(0xffffffffu, s1, o);
            s2 += __shfl_xor_sync(0xffffffffu, s2, o);
        }
        float mu = s1 * (1.0f / H);
        float var = s2 * (1.0f / H) - mu * mu;
        float rs = rsqrtf(var + 1e-5f);
        float ox = fmaxf((v.x - mu) * rs * gg.x + bb.x, 0.f);
        float oy = fmaxf((v.y - mu) * rs * gg.y + bb.y, 0.f);
        float oz = fmaxf((v.z - mu) * rs * gg.z + bb.z, 0.f);
        float ow = fmaxf((v.w - mu) * rs * gg.w + bb.w, 0.f);
        __half2 h0 = __floats2half2_rn(ox, oy);
        __half2 h1 = __floats2half2_rn(oz, ow);
        uint2 o; o.x = *(unsigned*)&h0; o.y = *(unsigned*)&h1;
        int orow = J.ridxo ? __ldg(J.ridxo + base) : base;
        *(uint2*)(J.out + (size_t)orow * H + lane * 4) = o;
    }
}

// ---------------------------------------------------------------------------
// MLP head: one warp per TWO targets (halves W1 re-reads; same per-target math).
// ---------------------------------------------------------------------------
__global__ void mlp_kernel(const __half* __restrict__ xuc,
                           const float* __restrict__ W1, const float* __restrict__ b1,
                           const float* __restrict__ W2, const float* __restrict__ b2,
                           float* __restrict__ out) {
    int warp = (blockIdx.x * blockDim.x + threadIdx.x) >> 5;
    int lane = threadIdx.x & 31;
    int t0 = warp * 2;
    if (t0 >= N_TGT) return;
    uint2 xra = *(const uint2*)(xuc + (size_t)t0 * H + lane * 4);
    uint2 xrb = *(const uint2*)(xuc + (size_t)(t0 + 1) * H + lane * 4);
    float2 a0 = __half22float2(*(__half2*)&xra.x);
    float2 a1 = __half22float2(*(__half2*)&xra.y);
    float2 c0 = __half22float2(*(__half2*)&xrb.x);
    float2 c1 = __half22float2(*(__half2*)&xrb.y);
    float accA = 0.f, accB = 0.f;
    #pragma unroll 4
    for (int j = 0; j < 64; j++) {
        float4 w = *(const float4*)(W1 + j * H + lane * 4);
        float pA = a0.x * w.x + a0.y * w.y + a1.x * w.z + a1.y * w.w;
        float pB = c0.x * w.x + c0.y * w.y + c1.x * w.z + c1.y * w.w;
        #pragma unroll
        for (int o = 16; o; o >>= 1) {
            pA += __shfl_xor_sync(0xffffffffu, pA, o);
            pB += __shfl_xor_sync(0xffffffffu, pB, o);
        }
        float bj = b1[j], wj = W2[j];
        accA += fmaxf(pA + bj, 0.f) * wj;
        accB += fmaxf(pB + bj, 0.f) * wj;
    }
    if (lane == 0) {
        out[t0]     = accA + b2[0];
        out[t0 + 1] = accB + b2[0];
    }
}

// ---------------------------------------------------------------------------
// Launch
// ---------------------------------------------------------------------------
extern "C" void kernel_launch(void* const* d_in, const int* in_sizes, int n_in,
                              void* d_out, int out_size) {
    const float* emb_user = (const float*)d_in[0];
    const float* emb_item = (const float*)d_in[1];
    const float* Wl       = (const float*)d_in[2];
    const float* bl       = (const float*)d_in[3];
    const float* Wr       = (const float*)d_in[4];
    const float* ln_g     = (const float*)d_in[5];
    const float* ln_b     = (const float*)d_in[6];
    const float* W1       = (const float*)d_in[7];
    const float* b1       = (const float*)d_in[8];
    const float* W2       = (const float*)d_in[9];
    const float* b2       = (const float*)d_in[10];
    const int* src_buys   = (const int*)d_in[11];
    const int* dst_buys   = (const int*)d_in[12];
    const int* src_rev    = (const int*)d_in[13];
    const int* dst_rev    = (const int*)d_in[14];
    const int* src_fol    = (const int*)d_in[15];
    const int* dst_fol    = (const int*)d_in[16];
    const int* target_ids = (const int*)d_in[17];
    float* out = (float*)d_out;

    __half *p_eu16, *p_ei16, *p_xu0h, *p_xi0h, *p_xufh, *p_aggU, *p_aggI;
    unsigned* p_wth;
    float* p_bias;
    int *p_off, *p_cmpU, *p_cmpI;
    cudaGetSymbolAddress((void**)&p_eu16, g_eu16);
    cudaGetSymbolAddress((void**)&p_ei16, g_ei16);
    cudaGetSymbolAddress((void**)&p_xu0h, g_xu0h);
    cudaGetSymbolAddress((void**)&p_xi0h, g_xi0h);
    cudaGetSymbolAddress((void**)&p_xufh, g_xufh);
    cudaGetSymbolAddress((void**)&p_aggU, g_aggU);
    cudaGetSymbolAddress((void**)&p_aggI, g_aggI);
    cudaGetSymbolAddress((void**)&p_wth,  g_wth);
    cudaGetSymbolAddress((void**)&p_bias, g_bias);
    cudaGetSymbolAddress((void**)&p_off,  g_off);
    cudaGetSymbolAddress((void**)&p_cmpU, g_cmpU);
    cudaGetSymbolAddress((void**)&p_cmpI, g_cmpI);

    const int* p_cntU = p_off + 3 * (N_USER + 1) + N_USER;   // g_off[3][N_USER]
    const int* p_cntI = p_off + 4 * (N_USER + 1) + N_ITEM;   // g_off[4][N_ITEM]

    const int smem_bytes = 3 * STAGEB;   // 107520
    cudaFuncSetAttribute(gemm_ln_kernel,
                         cudaFuncAttributeMaxDynamicSharedMemorySize, smem_bytes);

    // --- fused prep, then CSR + pruning chain ---
    prep_kernel<<<(PREP_TOT + 255) / 256, 256>>>(emb_user, emb_item, Wl, Wr, bl);
    flag_tgt_kernel<<<(N_TGT + 255) / 256, 256>>>(target_ids);
    count_flag_kernel<<<(3 * NE4 + 255) / 256, 256>>>(dst_buys,
                                                      dst_rev, src_rev,
                                                      dst_fol, src_fol);
    scan_p1_kernel<<<dim3(NBLK_U, 5), 1024>>>();
    scan_p2_kernel<<<1, 640>>>();
    scan_p3_kernel<<<dim3(NBLK_U, 5), 1024>>>();
    fill_all_kernel<<<(3 * NE4 + 255) / 256, 256>>>(dst_buys, src_buys,
                                                    dst_rev, src_rev,
                                                    dst_fol, src_fol);

    // ===== layer 0 (pruned to needed nodes) =====
    {
        int nwarp = N_ITEM + 2 * N_USER;
        agg_l0_kernel<<<(nwarp * 32 + 255) / 256, 256>>>(p_eu16, p_ei16);

        GemmJob ji, ju;
        ji.out = p_xi0h; ji.A0 = p_ei16; ji.A1 = p_aggI;
        ji.ridx0 = p_cmpI; ji.ridx1 = p_cmpI; ji.ridxo = p_cmpI; ji.cnt = p_cntI;
        ji.Wt = p_wth; ji.bias = p_bias;
        ji.gam = ln_g + 1 * H; ji.bet = ln_b + 1 * H;
        ji.lda0 = H; ji.lda1 = H; ji.k0c = 2; ji.nchunk = 4; ji.nrows = N_ITEM;

        ju.out = p_xu0h; ju.A0 = p_eu16; ju.A1 = p_aggU;
        ju.ridx0 = p_cmpU; ju.ridx1 = p_cmpU; ju.ridxo = p_cmpU; ju.cnt = p_cntU;
        ju.Wt = p_wth + 128 * H; ju.bias = p_bias + 1 * H;
        ju.gam = ln_g + 0 * H; ju.bet = ln_b + 0 * H;
        ju.lda0 = H; ju.lda1 = 256; ju.k0c = 2; ju.nchunk = 6; ju.nrows = N_USER;

        int nbi = (N_ITEM + 127) / 128;
        int nbu = (N_USER + 127) / 128;
        gemm_ln_kernel<<<nbi + nbu, 256, smem_bytes>>>(ji, ju, nbi);
    }
    // ===== layer 1: only target rows =====
    {
        agg_tgt_kernel<<<(2 * N_TGT * 32 + 255) / 256, 256>>>(p_xi0h, p_xu0h, target_ids);

        GemmJob jt;
        jt.out = p_xufh; jt.A0 = p_xu0h; jt.A1 = p_aggU;
        jt.ridx0 = target_ids; jt.ridx1 = nullptr; jt.ridxo = nullptr; jt.cnt = nullptr;
        jt.Wt = p_wth + (128 + 192) * H; jt.bias = p_bias + 2 * H;
        jt.gam = ln_g + 2 * H; jt.bet = ln_b + 2 * H;
        jt.lda0 = H; jt.lda1 = 256; jt.k0c = 2; jt.nchunk = 6; jt.nrows = N_TGT;

        int nbt = N_TGT / 128;
        gemm_ln_kernel<<<nbt, 256, smem_bytes>>>(jt, jt, nbt);
    }

    mlp_kernel<<<(N_TGT / 2 * 32 + 255) / 256, 256>>>(
        p_xufh, W1, b1, W2, b2, out);
}

// round 8
// speedup vs baseline: 4.9821x; 1.0143x over previous
#include <cuda_runtime.h>
#include <cuda_fp16.h>
#include <cstdint>

#define N_USER 100000
#define N_ITEM 50000
#define NE     800000
#define NE4    (NE / 4)
#define H      128
#define N_TGT  8192

#define NBLK_U 98   // ceil(100000/1024)

// ---------------------------------------------------------------------------
// Static device scratch (fp16 feature world)
// ---------------------------------------------------------------------------
__device__ __half g_eu16[N_USER * H];
__device__ __half g_ei16[N_ITEM * H];
__device__ __half g_xu0h[N_USER * H];
__device__ __half g_xi0h[N_ITEM * H];
__device__ __half g_xufh[N_TGT * H];
__device__ __half g_aggU[N_USER * 256];     // layer0: [mrev|mfol]; layer1: compact rows
__device__ __half g_aggI[N_ITEM * H];
__device__ unsigned g_wth[(128 + 192 + 192) * H];
__device__ float g_bias[3 * H];

// CSR + scan scratch. scan rows: 0..2 = graph degree counts, 3 = needU, 4 = needI
__device__ int g_cnt[3][N_USER + 1];
__device__ int g_off[5][N_USER + 1];
__device__ int g_cur[3][N_USER];
__device__ int g_csr[3][NE];
__device__ int g_bsum[5][128];

// pruning
__device__ int g_tflag[N_USER];
__device__ int g_needU[N_USER];
__device__ int g_needI[N_ITEM];
__device__ int g_cmpU[N_USER];
__device__ int g_cmpI[N_ITEM];

// graph ids: 0 = buys (dst=item), 1 = rev (dst=user), 2 = fol (dst=user)

__device__ __forceinline__ unsigned smem_u32(const void* p) {
    return (unsigned)__cvta_generic_to_shared(p);
}
#define CP16(dst, src, sz) \
    asm volatile("cp.async.cg.shared.global [%0], [%1], 16, %2;\n" \
                 :: "r"(dst), "l"(src), "r"(sz))

// ---------------------------------------------------------------------------
// K1: zero scratch (counts + flags)
// ---------------------------------------------------------------------------
#define ZCNT  (3 * (N_USER + 1))
__global__ void zero_kernel() {
    int i = blockIdx.x * blockDim.x + threadIdx.x;
    if (i < ZCNT) ((int*)g_cnt)[i] = 0;
    if (i < N_USER) { g_needU[i] = 0; g_tflag[i] = 0; }
    if (i < N_ITEM) g_needI[i] = 0;
}

// K2: mark targets
__global__ void flag_tgt_kernel(const int* __restrict__ tgt) {
    int i = blockIdx.x * blockDim.x + threadIdx.x;
    if (i < N_TGT) {
        int t = tgt[i];
        g_tflag[t] = 1;
        g_needU[t] = 1;
    }
}

// ---------------------------------------------------------------------------
// K3: fused [degree count + need flags]  ++  [emb->fp16 + weight/bias prep]
// Block-range split: blocks [0, CBLK) = count/flag; [CBLK, ...) = prep.
// ---------------------------------------------------------------------------
#define NU8   (N_USER * H / 8)
#define NI8   (N_ITEM * H / 8)
#define WTOT  ((128 + 192 + 192) * H)
#define PREPN (NU8 + NI8 + WTOT + 3 * H)
#define CBLK  ((3 * NE4 + 255) / 256)
#define PBLK  ((PREPN + 255) / 256)

__device__ __forceinline__ uint4 pack8(float4 a, float4 b) {
    __half2 h0 = __floats2half2_rn(a.x, a.y);
    __half2 h1 = __floats2half2_rn(a.z, a.w);
    __half2 h2 = __floats2half2_rn(b.x, b.y);
    __half2 h3 = __floats2half2_rn(b.z, b.w);
    uint4 u;
    u.x = *(unsigned*)&h0; u.y = *(unsigned*)&h1;
    u.z = *(unsigned*)&h2; u.w = *(unsigned*)&h3;
    return u;
}
__device__ __forceinline__ float wval_item(const float* Wl, const float* Wr, int k, int j) {
    return (k < 128) ? Wr[(0 * H + j) * H + k] : Wl[(0 * H + j) * H + (k - 128)];
}
__device__ __forceinline__ float wval_user(const float* Wl, const float* Wr, int l, int k, int j) {
    if (k < 128) return Wr[((l * 3 + 1) * H + j) * H + k] + Wr[((l * 3 + 2) * H + j) * H + k];
    if (k < 256) return Wl[((l * 3 + 1) * H + j) * H + (k - 128)];
    return Wl[((l * 3 + 2) * H + j) * H + (k - 256)];
}

__global__ void count_prep_kernel(const int* __restrict__ d0,
                                  const int* __restrict__ d1, const int* __restrict__ s1,
                                  const int* __restrict__ d2, const int* __restrict__ s2,
                                  const float* __restrict__ eu, const float* __restrict__ ei,
                                  const float* __restrict__ Wl, const float* __restrict__ Wr,
                                  const float* __restrict__ bl) {
    if (blockIdx.x < CBLK) {
        int i = blockIdx.x * blockDim.x + threadIdx.x;
        if (i >= 3 * NE4) return;
        int g = i / NE4, j = i % NE4;
        if (g == 0) {
            int4 v = ((const int4*)d0)[j];
            atomicAdd(&g_cnt[0][v.x], 1);
            atomicAdd(&g_cnt[0][v.y], 1);
            atomicAdd(&g_cnt[0][v.z], 1);
            atomicAdd(&g_cnt[0][v.w], 1);
        } else if (g == 1) {
            int4 d = ((const int4*)d1)[j];
            int4 s = ((const int4*)s1)[j];
            atomicAdd(&g_cnt[1][d.x], 1);
            atomicAdd(&g_cnt[1][d.y], 1);
            atomicAdd(&g_cnt[1][d.z], 1);
            atomicAdd(&g_cnt[1][d.w], 1);
            if (g_tflag[d.x]) g_needI[s.x] = 1;
            if (g_tflag[d.y]) g_needI[s.y] = 1;
            if (g_tflag[d.z]) g_needI[s.z] = 1;
            if (g_tflag[d.w]) g_needI[s.w] = 1;
        } else {
            int4 d = ((const int4*)d2)[j];
            int4 s = ((const int4*)s2)[j];
            atomicAdd(&g_cnt[2][d.x], 1);
            atomicAdd(&g_cnt[2][d.y], 1);
            atomicAdd(&g_cnt[2][d.z], 1);
            atomicAdd(&g_cnt[2][d.w], 1);
            if (g_tflag[d.x]) g_needU[s.x] = 1;
            if (g_tflag[d.y]) g_needU[s.y] = 1;
            if (g_tflag[d.z]) g_needU[s.z] = 1;
            if (g_tflag[d.w]) g_needU[s.w] = 1;
        }
        return;
    }
    // ---- prep part ----
    int i = (blockIdx.x - CBLK) * blockDim.x + threadIdx.x;
    if (i < NU8) {
        float4 a = ((const float4*)eu)[2 * i], b = ((const float4*)eu)[2 * i + 1];
        ((uint4*)g_eu16)[i] = pack8(a, b);
        return;
    }
    int j = i - NU8;
    if (j < NI8) {
        float4 a = ((const float4*)ei)[2 * j], b = ((const float4*)ei)[2 * j + 1];
        ((uint4*)g_ei16)[j] = pack8(a, b);
        return;
    }
    j -= NI8;
    if (j < WTOT) {
        float v0, v1;
        if (j < 128 * H) {
            int k2 = j >> 7, c = j & 127;
            v0 = wval_item(Wl, Wr, 2 * k2, c);
            v1 = wval_item(Wl, Wr, 2 * k2 + 1, c);
        } else {
            int rel = j - 128 * H;
            int l = (rel < 192 * H) ? 0 : 1;
            if (l == 1) rel -= 192 * H;
            int k2 = rel >> 7, c = rel & 127;
            v0 = wval_user(Wl, Wr, l, 2 * k2, c);
            v1 = wval_user(Wl, Wr, l, 2 * k2 + 1, c);
        }
        __half2 h = __floats2half2_rn(v0, v1);
        g_wth[j] = *(unsigned*)&h;
        return;
    }
    j -= WTOT;
    if (j < 3 * H) {
        int slot = j >> 7, c = j & 127;
        float b;
        if (slot == 0)      b = bl[0 * H + c];
        else if (slot == 1) b = bl[1 * H + c] + bl[2 * H + c];
        else                b = bl[(3 + 1) * H + c] + bl[(3 + 2) * H + c];
        g_bias[j] = b;
    }
}

// ---------------------------------------------------------------------------
// 2-phase scan over 5 rows (3 degree rows, needU, needI)
// ---------------------------------------------------------------------------
__device__ __forceinline__ int scan_val(int g, int i) {
    if (g < 3) return g_cnt[g][i];
    if (g == 3) return g_needU[i];
    return g_needI[i];
}
__device__ __forceinline__ int scan_n(int g) {
    return (g == 0 || g == 4) ? N_ITEM : N_USER;
}

// phase 1: per-1024-block exclusive scan; block sums out.
__global__ void scan_p1_kernel() {
    int g = blockIdx.y;
    int n = scan_n(g);
    int base = blockIdx.x * 1024;
    if (base >= n) return;
    int i = base + (int)threadIdx.x;
    int v = (i < n) ? scan_val(g, i) : 0;
    int lane = threadIdx.x & 31, wid = threadIdx.x >> 5;
    __shared__ int warp_sums[32];
    int x = v;
    #pragma unroll
    for (int s = 1; s < 32; s <<= 1) {
        int y = __shfl_up_sync(0xffffffffu, x, s);
        if (lane >= s) x += y;
    }
    if (lane == 31) warp_sums[wid] = x;
    __syncthreads();
    if (wid == 0) {
        int w = warp_sums[lane];
        int xw = w;
        #pragma unroll
        for (int s = 1; s < 32; s <<= 1) {
            int y = __shfl_up_sync(0xffffffffu, xw, s);
            if (lane >= s) xw += y;
        }
        warp_sums[lane] = xw - w;
    }
    __syncthreads();
    int incl = x + warp_sums[wid];
    if (i < n) g_off[g][i] = incl - v;
    if (threadIdx.x == 1023) g_bsum[g][blockIdx.x] = incl;
}

// phase 2+3 fused: each block computes its own base from block sums, then
// applies it: write offsets + cursors (g<3) or compact lists (g>=3).
__global__ void scan_p23_kernel() {
    int g = blockIdx.y;
    int n = scan_n(g);
    if ((int)blockIdx.x * 1024 >= n) return;
    int nb = (n + 1023) / 1024;

    __shared__ int sw[4][2];
    __shared__ int s_base, s_tot;
    if (threadIdx.x < 128) {
        int k = threadIdx.x;
        int lane = k & 31, w = k >> 5;
        int v = (k < nb) ? g_bsum[g][k] : 0;
        int below = (k < (int)blockIdx.x) ? v : 0;
        #pragma unroll
        for (int o = 16; o; o >>= 1) {
            v += __shfl_xor_sync(0xffffffffu, v, o);
            below += __shfl_xor_sync(0xffffffffu, below, o);
        }
        if (lane == 0) { sw[w][0] = below; sw[w][1] = v; }
    }
    __syncthreads();
    if (threadIdx.x == 0) {
        s_base = sw[0][0] + sw[1][0] + sw[2][0] + sw[3][0];
        s_tot  = sw[0][1] + sw[1][1] + sw[2][1] + sw[3][1];
    }
    __syncthreads();

    int i = blockIdx.x * 1024 + threadIdx.x;
    if (i >= n) return;
    int val = g_off[g][i] + s_base;
    if (i == n - 1) g_off[g][n] = s_tot;
    if (g < 3) {
        g_off[g][i] = val;
        g_cur[g][i] = val;
    } else if (g == 3) {
        if (g_needU[i]) g_cmpU[val] = i;
    } else {
        if (g_needI[i]) g_cmpI[val] = i;
    }
}

// Filtered fill: only insert edges whose dst node is ever read downstream.
__global__ void fill_all_kernel(const int* __restrict__ d0, const int* __restrict__ s0,
                                const int* __restrict__ d1, const int* __restrict__ s1,
                                const int* __restrict__ d2, const int* __restrict__ s2) {
    int i = blockIdx.x * blockDim.x + threadIdx.x;
    if (i >= 3 * NE4) return;
    int g = i / NE4, j = i % NE4;
    const int* d = (g == 0) ? d0 : (g == 1) ? d1 : d2;
    const int* s = (g == 0) ? s0 : (g == 1) ? s1 : s2;
    const int* need = (g == 0) ? g_needI : g_needU;
    int4 dv = ((const int4*)d)[j];
    int4 sv = ((const int4*)s)[j];
    if (need[dv.x]) g_csr[g][atomicAdd(&g_cur[g][dv.x], 1)] = sv.x;
    if (need[dv.y]) g_csr[g][atomicAdd(&g_cur[g][dv.y], 1)] = sv.y;
    if (need[dv.z]) g_csr[g][atomicAdd(&g_cur[g][dv.z], 1)] = sv.z;
    if (need[dv.w]) g_csr[g][atomicAdd(&g_cur[g][dv.w], 1)] = sv.w;
}

// ---------------------------------------------------------------------------
// Gather-mean over fp16 rows (fp32 accumulate), shared body.
// ---------------------------------------------------------------------------
__device__ __forceinline__ void acc4(float4& a, uint2 u) {
    __half2 h0 = *(__half2*)&u.x, h1 = *(__half2*)&u.y;
    float2 f0 = __half22float2(h0), f1 = __half22float2(h1);
    a.x += f0.x; a.y += f0.y; a.z += f1.x; a.w += f1.y;
}

__device__ __forceinline__ void agg_one(int g, int node, int lane,
                                        const __half* __restrict__ src,
                                        __half* __restrict__ dst) {
    int s = g_off[g][node], e = g_off[g][node + 1];
    const int* lst = g_csr[g];
    float4 acc = make_float4(0.f, 0.f, 0.f, 0.f);
    int i = s;
    for (; i + 4 <= e; i += 4) {
        int i0 = lst[i], i1 = lst[i + 1], i2 = lst[i + 2], i3 = lst[i + 3];
        uint2 v0 = *(const uint2*)(src + (size_t)i0 * H + lane * 4);
        uint2 v1 = *(const uint2*)(src + (size_t)i1 * H + lane * 4);
        uint2 v2 = *(const uint2*)(src + (size_t)i2 * H + lane * 4);
        uint2 v3 = *(const uint2*)(src + (size_t)i3 * H + lane * 4);
        acc4(acc, v0); acc4(acc, v1); acc4(acc, v2); acc4(acc, v3);
    }
    for (; i < e; i++) {
        uint2 v0 = *(const uint2*)(src + (size_t)lst[i] * H + lane * 4);
        acc4(acc, v0);
    }
    float inv = (e > s) ? 1.0f / (float)(e - s) : 0.0f;
    __half2 o0 = __floats2half2_rn(acc.x * inv, acc.y * inv);
    __half2 o1 = __floats2half2_rn(acc.z * inv, acc.w * inv);
    uint2 o; o.x = *(unsigned*)&o0; o.y = *(unsigned*)&o1;
    *(uint2*)(dst + lane * 4) = o;
}

// Layer-0 aggregation, pruned: only needed items/users (compact lists).
__global__ void agg_l0_kernel(const __half* __restrict__ eu,
                              const __half* __restrict__ ei) {
    int warp = (blockIdx.x * blockDim.x + threadIdx.x) >> 5;
    int lane = threadIdx.x & 31;
    if (warp < N_ITEM) {
        int nI = __ldg(&g_off[4][N_ITEM]);
        if (warp >= nI) return;
        int node = g_cmpI[warp];
        agg_one(0, node, lane, eu, g_aggI + (size_t)node * H);
    } else {
        int w2 = warp - N_ITEM;
        int nU = __ldg(&g_off[3][N_USER]);
        if (w2 < N_USER) {
            if (w2 >= nU) return;
            int node = g_cmpU[w2];
            agg_one(1, node, lane, ei, g_aggU + (size_t)node * 256);
        } else {
            w2 -= N_USER;
            if (w2 >= N_USER || w2 >= nU) return;
            int node = g_cmpU[w2];
            agg_one(2, node, lane, eu, g_aggU + (size_t)node * 256 + 128);
        }
    }
}

// Layer-1 aggregation: ONLY target users (compact rows 0..N_TGT-1).
__global__ void agg_tgt_kernel(const __half* __restrict__ xi0,
                               const __half* __restrict__ xu0,
                               const int* __restrict__ tgt) {
    int warp = (blockIdx.x * blockDim.x + threadIdx.x) >> 5;
    int lane = threadIdx.x & 31;
    if (warp >= 2 * N_TGT) return;
    int pos = warp & (N_TGT - 1);
    int node = tgt[pos];
    if (warp < N_TGT)
        agg_one(1, node, lane, xi0, g_aggU + (size_t)pos * 256);
    else
        agg_one(2, node, lane, xu0, g_aggU + (size_t)pos * 256 + 128);
}

// ---------------------------------------------------------------------------
// FP16 tensor-core GEMM (cp.async 3-stage) + fused LayerNorm + ReLU, fp16 out.
// ---------------------------------------------------------------------------
#define ASTRIDE 36
#define WSTRIDE 136
#define OSTRIDE 132
#define STAGEB  35840

extern __shared__ char g_smraw[];

struct GemmJob {
    __half* out;
    const __half* A0;
    const __half* A1;
    const int* ridx0;
    const int* ridx1;
    const int* ridxo;
    const int* cnt;
    const unsigned* Wt;
    const float* bias;
    const float* gam;
    const float* bet;
    int lda0, lda1, k0c, nchunk, nrows;
};

__device__ __forceinline__ void mma_f16(float c[4], const unsigned a[4], const unsigned b[2]) {
    asm volatile(
        "mma.sync.aligned.m16n8k16.row.col.f32.f16.f16.f32 "
        "{%0,%1,%2,%3}, {%4,%5,%6,%7}, {%8,%9}, {%0,%1,%2,%3};"
        : "+f"(c[0]), "+f"(c[1]), "+f"(c[2]), "+f"(c[3])
        : "r"(a[0]), "r"(a[1]), "r"(a[2]), "r"(a[3]), "r"(b[0]), "r"(b[1]));
}

__global__ void __launch_bounds__(256, 2) gemm_ln_kernel(GemmJob j0, GemmJob j1, int split) {
    GemmJob J = (blockIdx.x < (unsigned)split) ? j0 : j1;
    int bid = (blockIdx.x < (unsigned)split) ? blockIdx.x : blockIdx.x - split;
    int row0 = bid * 128;

    int nrows = J.cnt ? __ldg(J.cnt) : J.nrows;
    if (row0 >= nrows) return;

    int t = threadIdx.x;
    int lane = t & 31;
    int wid = t >> 5;
    int warp_m = wid & 3;
    int warp_n = wid >> 2;
    int gid = lane >> 2;
    int tig = lane & 3;

    float c[2][8][4];
    #pragma unroll
    for (int nt = 0; nt < 8; nt++) {
        int col = warp_n * 64 + nt * 8 + 2 * tig;
        float b0 = J.bias[col], b1 = J.bias[col + 1];
        #pragma unroll
        for (int mt = 0; mt < 2; mt++) {
            c[mt][nt][0] = b0; c[mt][nt][1] = b1;
            c[mt][nt][2] = b0; c[mt][nt][3] = b1;
        }
    }

    auto load_chunk = [&](int ck, int st) {
        if (ck < J.nchunk) {
            const __half* A; int lda, cb; const int* ridx;
            if (ck < J.k0c) { A = J.A0; lda = J.lda0; cb = ck * 64; ridx = J.ridx0; }
            else            { A = J.A1; lda = J.lda1; cb = (ck - J.k0c) * 64; ridx = J.ridx1; }
            unsigned* As = (unsigned*)(g_smraw + st * STAGEB);
            #pragma unroll
            for (int i2 = 0; i2 < 4; i2++) {
                int idx = t + 256 * i2;
                int r = idx >> 3, u = idx & 7;
                int base = row0 + r;
                int ok = (base < nrows);
                if (!ok) base = row0;
                int row = ridx ? __ldg(ridx + base) : base;
                const __half* src = A + (size_t)row * lda + cb + u * 8;
                CP16(smem_u32(As + r * ASTRIDE + u * 4), src, ok ? 16 : 0);
            }
            unsigned* Ws = (unsigned*)(g_smraw + st * STAGEB + 128 * ASTRIDE * 4);
            #pragma unroll
            for (int i2 = 0; i2 < 4; i2++) {
                int idx = t + 256 * i2;
                int rr = idx >> 5, u = idx & 31;
                const unsigned* src = J.Wt + (size_t)(ck * 32 + rr) * H + u * 4;
                CP16(smem_u32(Ws + rr * WSTRIDE + u * 4), src, 16);
            }
        }
        asm volatile("cp.async.commit_group;\n" ::);
    };

    load_chunk(0, 0);
    load_chunk(1, 1);

    for (int ck = 0; ck < J.nchunk; ck++) {
        asm volatile("cp.async.wait_group 1;\n" ::);
        __syncthreads();
        load_chunk(ck + 2, (ck + 2) % 3);

        int st = ck % 3;
        const unsigned* As = (const unsigned*)(g_smraw + st * STAGEB);
        const unsigned* Ws = (const unsigned*)(g_smraw + st * STAGEB + 128 * ASTRIDE * 4);
        #pragma unroll
        for (int ks = 0; ks < 4; ks++) {
            int k2 = ks * 8;
            unsigned a[2][4];
            #pragma unroll
            for (int mt = 0; mt < 2; mt++) {
                int r = warp_m * 32 + mt * 16 + gid;
                a[mt][0] = As[r * ASTRIDE + k2 + tig];
                a[mt][1] = As[(r + 8) * ASTRIDE + k2 + tig];
                a[mt][2] = As[r * ASTRIDE + k2 + tig + 4];
                a[mt][3] = As[(r + 8) * ASTRIDE + k2 + tig + 4];
            }
            unsigned b[8][2];
            #pragma unroll
            for (int nt = 0; nt < 8; nt++) {
                int cc = warp_n * 64 + nt * 8 + gid;
                b[nt][0] = Ws[(k2 + tig) * WSTRIDE + cc];
                b[nt][1] = Ws[(k2 + tig + 4) * WSTRIDE + cc];
            }
            #pragma unroll
            for (int mt = 0; mt < 2; mt++)
                #pragma unroll
                for (int nt = 0; nt < 8; nt++)
                    mma_f16(c[mt][nt], a[mt], b[nt]);
        }
    }

    // ---- epilogue: stage fp32 to smem, fused LayerNorm + ReLU, fp16 out ----
    asm volatile("cp.async.wait_group 0;\n" ::);
    __syncthreads();
    float* Osm = (float*)g_smraw;
    #pragma unroll
    for (int mt = 0; mt < 2; mt++) {
        #pragma unroll
        for (int nt = 0; nt < 8; nt++) {
            int col = warp_n * 64 + nt * 8 + 2 * tig;
            int r = warp_m * 32 + mt * 16 + gid;
            *(float2*)(Osm + r * OSTRIDE + col)       = make_float2(c[mt][nt][0], c[mt][nt][1]);
            *(float2*)(Osm + (r + 8) * OSTRIDE + col) = make_float2(c[mt][nt][2], c[mt][nt][3]);
        }
    }
    __syncthreads();

    float4 gg = *(const float4*)(J.gam + lane * 4);
    float4 bb = *(const float4*)(J.bet + lane * 4);
    #pragma unroll
    for (int i = 0; i < 16; i++) {
        int r = wid * 16 + i;
        int base = row0 + r;
        if (base >= nrows) break;
        float4 v = *(float4*)(Osm + r * OSTRIDE + lane * 4);
        float s1 = v.x + v.y + v.z + v.w;
        float s2 = v.x * v.x + v.y * v.y + v.z * v.z + v.w * v.w;
        #pragma unroll
        for (int o = 16; o; o >>= 1) {
            s1 += __shfl_xor_sync(0xffffffffu, s1, o);
            s2 += __shfl_xor_sync(0xffffffffu, s2, o);
        }
        float mu = s1 * (1.0f / H);
        float var = s2 * (1.0f / H) - mu * mu;
        float rs = rsqrtf(var + 1e-5f);
        float ox = fmaxf((v.x - mu) * rs * gg.x + bb.x, 0.f);
        float oy = fmaxf((v.y - mu) * rs * gg.y + bb.y, 0.f);
        float oz = fmaxf((v.z - mu) * rs * gg.z + bb.z, 0.f);
        float ow = fmaxf((v.w - mu) * rs * gg.w + bb.w, 0.f);
        __half2 h0 = __floats2half2_rn(ox, oy);
        __half2 h1 = __floats2half2_rn(oz, ow);
        uint2 o; o.x = *(unsigned*)&h0; o.y = *(unsigned*)&h1;
        int orow = J.ridxo ? __ldg(J.ridxo + base) : base;
        *(uint2*)(J.out + (size_t)orow * H + lane * 4) = o;
    }
}

// ---------------------------------------------------------------------------
// MLP head: one warp per TWO targets.
// ---------------------------------------------------------------------------
__global__ void mlp_kernel(const __half* __restrict__ xuc,
                           const float* __restrict__ W1, const float* __restrict__ b1,
                           const float* __restrict__ W2, const float* __restrict__ b2,
                           float* __restrict__ out) {
    int warp = (blockIdx.x * blockDim.x + threadIdx.x) >> 5;
    int lane = threadIdx.x & 31;
    int t0 = warp * 2;
    if (t0 >= N_TGT) return;
    uint2 xra = *(const uint2*)(xuc + (size_t)t0 * H + lane * 4);
    uint2 xrb = *(const uint2*)(xuc + (size_t)(t0 + 1) * H + lane * 4);
    float2 a0 = __half22float2(*(__half2*)&xra.x);
    float2 a1 = __half22float2(*(__half2*)&xra.y);
    float2 c0 = __half22float2(*(__half2*)&xrb.x);
    float2 c1 = __half22float2(*(__half2*)&xrb.y);
    float accA = 0.f, accB = 0.f;
    #pragma unroll 4
    for (int j = 0; j < 64; j++) {
        float4 w = *(const float4*)(W1 + j * H + lane * 4);
        float pA = a0.x * w.x + a0.y * w.y + a1.x * w.z + a1.y * w.w;
        float pB = c0.x * w.x + c0.y * w.y + c1.x * w.z + c1.y * w.w;
        #pragma unroll
        for (int o = 16; o; o >>= 1) {
            pA += __shfl_xor_sync(0xffffffffu, pA, o);
            pB += __shfl_xor_sync(0xffffffffu, pB, o);
        }
        float bj = b1[j], wj = W2[j];
        accA += fmaxf(pA + bj, 0.f) * wj;
        accB += fmaxf(pB + bj, 0.f) * wj;
    }
    if (lane == 0) {
        out[t0]     = accA + b2[0];
        out[t0 + 1] = accB + b2[0];
    }
}

// ---------------------------------------------------------------------------
// Launch
// ---------------------------------------------------------------------------
extern "C" void kernel_launch(void* const* d_in, const int* in_sizes, int n_in,
                              void* d_out, int out_size) {
    const float* emb_user = (const float*)d_in[0];
    const float* emb_item = (const float*)d_in[1];
    const float* Wl       = (const float*)d_in[2];
    const float* bl       = (const float*)d_in[3];
    const float* Wr       = (const float*)d_in[4];
    const float* ln_g     = (const float*)d_in[5];
    const float* ln_b     = (const float*)d_in[6];
    const float* W1       = (const float*)d_in[7];
    const float* b1       = (const float*)d_in[8];
    const float* W2       = (const float*)d_in[9];
    const float* b2       = (const float*)d_in[10];
    const int* src_buys   = (const int*)d_in[11];
    const int* dst_buys   = (const int*)d_in[12];
    const int* src_rev    = (const int*)d_in[13];
    const int* dst_rev    = (const int*)d_in[14];
    const int* src_fol    = (const int*)d_in[15];
    const int* dst_fol    = (const int*)d_in[16];
    const int* target_ids = (const int*)d_in[17];
    float* out = (float*)d_out;

    __half *p_eu16, *p_ei16, *p_xu0h, *p_xi0h, *p_xufh, *p_aggU, *p_aggI;
    unsigned* p_wth;
    float* p_bias;
    int *p_off, *p_cmpU, *p_cmpI;
    cudaGetSymbolAddress((void**)&p_eu16, g_eu16);
    cudaGetSymbolAddress((void**)&p_ei16, g_ei16);
    cudaGetSymbolAddress((void**)&p_xu0h, g_xu0h);
    cudaGetSymbolAddress((void**)&p_xi0h, g_xi0h);
    cudaGetSymbolAddress((void**)&p_xufh, g_xufh);
    cudaGetSymbolAddress((void**)&p_aggU, g_aggU);
    cudaGetSymbolAddress((void**)&p_aggI, g_aggI);
    cudaGetSymbolAddress((void**)&p_wth,  g_wth);
    cudaGetSymbolAddress((void**)&p_bias, g_bias);
    cudaGetSymbolAddress((void**)&p_off,  g_off);
    cudaGetSymbolAddress((void**)&p_cmpU, g_cmpU);
    cudaGetSymbolAddress((void**)&p_cmpI, g_cmpI);

    const int* p_cntU = p_off + 3 * (N_USER + 1) + N_USER;   // g_off[3][N_USER]
    const int* p_cntI = p_off + 4 * (N_USER + 1) + N_ITEM;   // g_off[4][N_ITEM]

    const int smem_bytes = 3 * STAGEB;   // 107520
    cudaFuncSetAttribute(gemm_ln_kernel,
                         cudaFuncAttributeMaxDynamicSharedMemorySize, smem_bytes);

    // --- CSR + pruning chain, with prep fused into the count launch ---
    zero_kernel<<<(ZCNT + 255) / 256, 256>>>();
    flag_tgt_kernel<<<(N_TGT + 255) / 256, 256>>>(target_ids);
    count_prep_kernel<<<CBLK + PBLK, 256>>>(dst_buys,
                                            dst_rev, src_rev,
                                            dst_fol, src_fol,
                                            emb_user, emb_item, Wl, Wr, bl);
    scan_p1_kernel<<<dim3(NBLK_U, 5), 1024>>>();
    scan_p23_kernel<<<dim3(NBLK_U, 5), 1024>>>();
    fill_all_kernel<<<(3 * NE4 + 255) / 256, 256>>>(dst_buys, src_buys,
                                                    dst_rev, src_rev,
                                                    dst_fol, src_fol);

    // ===== layer 0 (pruned to needed nodes) =====
    {
        int nwarp = N_ITEM + 2 * N_USER;
        agg_l0_kernel<<<(nwarp * 32 + 255) / 256, 256>>>(p_eu16, p_ei16);

        GemmJob ji, ju;
        ji.out = p_xi0h; ji.A0 = p_ei16; ji.A1 = p_aggI;
        ji.ridx0 = p_cmpI; ji.ridx1 = p_cmpI; ji.ridxo = p_cmpI; ji.cnt = p_cntI;
        ji.Wt = p_wth; ji.bias = p_bias;
        ji.gam = ln_g + 1 * H; ji.bet = ln_b + 1 * H;
        ji.lda0 = H; ji.lda1 = H; ji.k0c = 2; ji.nchunk = 4; ji.nrows = N_ITEM;

        ju.out = p_xu0h; ju.A0 = p_eu16; ju.A1 = p_aggU;
        ju.ridx0 = p_cmpU; ju.ridx1 = p_cmpU; ju.ridxo = p_cmpU; ju.cnt = p_cntU;
        ju.Wt = p_wth + 128 * H; ju.bias = p_bias + 1 * H;
        ju.gam = ln_g + 0 * H; ju.bet = ln_b + 0 * H;
        ju.lda0 = H; ju.lda1 = 256; ju.k0c = 2; ju.nchunk = 6; ju.nrows = N_USER;

        int nbi = (N_ITEM + 127) / 128;
        int nbu = (N_USER + 127) / 128;
        gemm_ln_kernel<<<nbi + nbu, 256, smem_bytes>>>(ji, ju, nbi);
    }
    // ===== layer 1: only target rows =====
    {
        agg_tgt_kernel<<<(2 * N_TGT * 32 + 255) / 256, 256>>>(p_xi0h, p_xu0h, target_ids);

        GemmJob jt;
        jt.out = p_xufh; jt.A0 = p_xu0h; jt.A1 = p_aggU;
        jt.ridx0 = target_ids; jt.ridx1 = nullptr; jt.ridxo = nullptr; jt.cnt = nullptr;
        jt.Wt = p_wth + (128 + 192) * H; jt.bias = p_bias + 2 * H;
        jt.gam = ln_g + 2 * H; jt.bet = ln_b + 2 * H;
        jt.lda0 = H; jt.lda1 = 256; jt.k0c = 2; jt.nchunk = 6; jt.nrows = N_TGT;

        int nbt = N_TGT / 128;
        gemm_ln_kernel<<<nbt, 256, smem_bytes>>>(jt, jt, nbt);
    }

    mlp_kernel<<<(N_TGT / 2 * 32 + 255) / 256, 256>>>(
        p_xufh, W1, b1, W2, b2, out);
}

// round 9
// speedup vs baseline: 5.0068x; 1.0050x over previous
#include <cuda_runtime.h>
#include <cuda_fp16.h>
#include <cstdint>

#define N_USER 100000
#define N_ITEM 50000
#define NE     800000
#define NE4    (NE / 4)
#define H      128
#define N_TGT  8192

// ---------------------------------------------------------------------------
// Static device scratch (fp16 feature world)
// ---------------------------------------------------------------------------
__device__ __half g_eu16[N_USER * H];
__device__ __half g_ei16[N_ITEM * H];
__device__ __half g_xu0h[N_USER * H];
__device__ __half g_xi0h[N_ITEM * H];
__device__ __half g_xufh[N_TGT * H];
__device__ __half g_aggU[N_USER * 256];     // layer0: [mrev|mfol]; layer1: compact rows
__device__ __half g_aggI[N_ITEM * H];
__device__ unsigned g_wth[(128 + 192 + 192) * H];
__device__ float g_bias[3 * H];

// CSR + scan scratch. scan rows: 0..2 = graph degree counts, 3 = needU, 4 = needI
__device__ int g_cnt[3][N_USER + 1];
__device__ int g_off[5][N_USER + 1];
__device__ int g_cur[3][N_USER];
__device__ int g_csr[3][NE];
__device__ int g_bsum[5][128];
__device__ int g_bflag[5 * 128];
__device__ int g_ticket;

// pruning flags: store epoch value (== current call's E means set)
__device__ int g_epoch;                     // bumped once at end of each call
__device__ int g_tflag[N_USER];
__device__ int g_needU[N_USER];
__device__ int g_needI[N_ITEM];
__device__ int g_cmpU[N_USER];
__device__ int g_cmpI[N_ITEM];

// graph ids: 0 = buys (dst=item), 1 = rev (dst=user), 2 = fol (dst=user)

__device__ __forceinline__ unsigned smem_u32(const void* p) {
    return (unsigned)__cvta_generic_to_shared(p);
}
#define CP16(dst, src, sz) \
    asm volatile("cp.async.cg.shared.global [%0], [%1], 16, %2;\n" \
                 :: "r"(dst), "l"(src), "r"(sz))

// ---------------------------------------------------------------------------
// K1: zero counts/scan-scratch + flag targets with epoch (disjoint ranges)
// ---------------------------------------------------------------------------
#define ZCNT  (3 * (N_USER + 1))
#define ZF_TOT (ZCNT + 5 * 128 + 1 + N_TGT)

__global__ void zeroflag_kernel(const int* __restrict__ tgt) {
    int i = blockIdx.x * blockDim.x + threadIdx.x;
    if (i < ZCNT) { ((int*)g_cnt)[i] = 0; return; }
    int j = i - ZCNT;
    if (j < 5 * 128) { g_bflag[j] = 0; return; }
    j -= 5 * 128;
    if (j < 1) { g_ticket = 0; return; }
    j -= 1;
    if (j < N_TGT) {
        int E = __ldg(&g_epoch) + 1;
        int t = tgt[j];
        g_tflag[t] = E;
        g_needU[t] = E;
    }
}

// ---------------------------------------------------------------------------
// K2: fused [degree count + need flags] ++ [emb->fp16 + weight/bias prep]
// ---------------------------------------------------------------------------
#define NU8   (N_USER * H / 8)
#define NI8   (N_ITEM * H / 8)
#define WTOT  ((128 + 192 + 192) * H)
#define PREPN (NU8 + NI8 + WTOT + 3 * H)
#define CBLK  ((3 * NE4 + 255) / 256)
#define PBLK  ((PREPN + 255) / 256)

__device__ __forceinline__ uint4 pack8(float4 a, float4 b) {
    __half2 h0 = __floats2half2_rn(a.x, a.y);
    __half2 h1 = __floats2half2_rn(a.z, a.w);
    __half2 h2 = __floats2half2_rn(b.x, b.y);
    __half2 h3 = __floats2half2_rn(b.z, b.w);
    uint4 u;
    u.x = *(unsigned*)&h0; u.y = *(unsigned*)&h1;
    u.z = *(unsigned*)&h2; u.w = *(unsigned*)&h3;
    return u;
}
__device__ __forceinline__ float wval_item(const float* Wl, const float* Wr, int k, int j) {
    return (k < 128) ? Wr[(0 * H + j) * H + k] : Wl[(0 * H + j) * H + (k - 128)];
}
__device__ __forceinline__ float wval_user(const float* Wl, const float* Wr, int l, int k, int j) {
    if (k < 128) return Wr[((l * 3 + 1) * H + j) * H + k] + Wr[((l * 3 + 2) * H + j) * H + k];
    if (k < 256) return Wl[((l * 3 + 1) * H + j) * H + (k - 128)];
    return Wl[((l * 3 + 2) * H + j) * H + (k - 256)];
}

__global__ void count_prep_kernel(const int* __restrict__ d0,
                                  const int* __restrict__ d1, const int* __restrict__ s1,
                                  const int* __restrict__ d2, const int* __restrict__ s2,
                                  const float* __restrict__ eu, const float* __restrict__ ei,
                                  const float* __restrict__ Wl, const float* __restrict__ Wr,
                                  const float* __restrict__ bl) {
    if (blockIdx.x < CBLK) {
        int i = blockIdx.x * blockDim.x + threadIdx.x;
        if (i >= 3 * NE4) return;
        int E = __ldg(&g_epoch) + 1;
        int g = i / NE4, j = i % NE4;
        if (g == 0) {
            int4 v = ((const int4*)d0)[j];
            atomicAdd(&g_cnt[0][v.x], 1);
            atomicAdd(&g_cnt[0][v.y], 1);
            atomicAdd(&g_cnt[0][v.z], 1);
            atomicAdd(&g_cnt[0][v.w], 1);
        } else if (g == 1) {
            int4 d = ((const int4*)d1)[j];
            int4 s = ((const int4*)s1)[j];
            atomicAdd(&g_cnt[1][d.x], 1);
            atomicAdd(&g_cnt[1][d.y], 1);
            atomicAdd(&g_cnt[1][d.z], 1);
            atomicAdd(&g_cnt[1][d.w], 1);
            if (g_tflag[d.x] == E) g_needI[s.x] = E;
            if (g_tflag[d.y] == E) g_needI[s.y] = E;
            if (g_tflag[d.z] == E) g_needI[s.z] = E;
            if (g_tflag[d.w] == E) g_needI[s.w] = E;
        } else {
            int4 d = ((const int4*)d2)[j];
            int4 s = ((const int4*)s2)[j];
            atomicAdd(&g_cnt[2][d.x], 1);
            atomicAdd(&g_cnt[2][d.y], 1);
            atomicAdd(&g_cnt[2][d.z], 1);
            atomicAdd(&g_cnt[2][d.w], 1);
            if (g_tflag[d.x] == E) g_needU[s.x] = E;
            if (g_tflag[d.y] == E) g_needU[s.y] = E;
            if (g_tflag[d.z] == E) g_needU[s.z] = E;
            if (g_tflag[d.w] == E) g_needU[s.w] = E;
        }
        return;
    }
    // ---- prep part ----
    int i = (blockIdx.x - CBLK) * blockDim.x + threadIdx.x;
    if (i < NU8) {
        float4 a = ((const float4*)eu)[2 * i], b = ((const float4*)eu)[2 * i + 1];
        ((uint4*)g_eu16)[i] = pack8(a, b);
        return;
    }
    int j = i - NU8;
    if (j < NI8) {
        float4 a = ((const float4*)ei)[2 * j], b = ((const float4*)ei)[2 * j + 1];
        ((uint4*)g_ei16)[j] = pack8(a, b);
        return;
    }
    j -= NI8;
    if (j < WTOT) {
        float v0, v1;
        if (j < 128 * H) {
            int k2 = j >> 7, c = j & 127;
            v0 = wval_item(Wl, Wr, 2 * k2, c);
            v1 = wval_item(Wl, Wr, 2 * k2 + 1, c);
        } else {
            int rel = j - 128 * H;
            int l = (rel < 192 * H) ? 0 : 1;
            if (l == 1) rel -= 192 * H;
            int k2 = rel >> 7, c = rel & 127;
            v0 = wval_user(Wl, Wr, l, 2 * k2, c);
            v1 = wval_user(Wl, Wr, l, 2 * k2 + 1, c);
        }
        __half2 h = __floats2half2_rn(v0, v1);
        g_wth[j] = *(unsigned*)&h;
        return;
    }
    j -= WTOT;
    if (j < 3 * H) {
        int slot = j >> 7, c = j & 127;
        float b;
        if (slot == 0)      b = bl[0 * H + c];
        else if (slot == 1) b = bl[1 * H + c] + bl[2 * H + c];
        else                b = bl[(3 + 1) * H + c] + bl[(3 + 2) * H + c];
        g_bias[j] = b;
    }
}

// ---------------------------------------------------------------------------
// K3: single-pass scan over 5 rows (3 degree rows, needU, needI) with
// ticket-ordered parallel lookback. Applies offsets/cursors/compaction inline.
// Row block counts: g0:49, g1:98, g2:98, g3:98, g4:49  -> 392 blocks.
// ---------------------------------------------------------------------------
#define NB_I 49
#define NB_U 98
#define SCAN_BLOCKS (NB_I + NB_U + NB_U + NB_U + NB_I)

__device__ __forceinline__ int scan_n(int g) {
    return (g == 0 || g == 4) ? N_ITEM : N_USER;
}

__global__ void scan_kernel() {
    __shared__ int s_g, s_b;
    __shared__ int warp_sums[32];
    __shared__ int sw[4];
    __shared__ int s_base;

    if (threadIdx.x == 0) {
        int v = atomicAdd(&g_ticket, 1);
        int g, b;
        if (v < NB_I)                         { g = 0; b = v; }
        else if (v < NB_I + NB_U)             { g = 1; b = v - NB_I; }
        else if (v < NB_I + 2 * NB_U)         { g = 2; b = v - NB_I - NB_U; }
        else if (v < NB_I + 3 * NB_U)         { g = 3; b = v - NB_I - 2 * NB_U; }
        else                                  { g = 4; b = v - NB_I - 3 * NB_U; }
        s_g = g; s_b = b;
    }
    __syncthreads();
    int g = s_g, b = s_b;
    int n = scan_n(g);
    int nb = (g == 0 || g == 4) ? NB_I : NB_U;
    int E = __ldg(&g_epoch) + 1;

    int i = b * 1024 + (int)threadIdx.x;
    int v;
    if (i >= n) v = 0;
    else if (g < 3) v = g_cnt[g][i];
    else if (g == 3) v = (g_needU[i] == E) ? 1 : 0;
    else v = (g_needI[i] == E) ? 1 : 0;

    // local inclusive scan
    int lane = threadIdx.x & 31, wid = threadIdx.x >> 5;
    int x = v;
    #pragma unroll
    for (int s = 1; s < 32; s <<= 1) {
        int y = __shfl_up_sync(0xffffffffu, x, s);
        if (lane >= s) x += y;
    }
    if (lane == 31) warp_sums[wid] = x;
    __syncthreads();
    if (wid == 0) {
        int w = warp_sums[lane];
        int xw = w;
        #pragma unroll
        for (int s = 1; s < 32; s <<= 1) {
            int y = __shfl_up_sync(0xffffffffu, xw, s);
            if (lane >= s) xw += y;
        }
        warp_sums[lane] = xw - w;
    }
    __syncthreads();
    int incl = x + warp_sums[wid];

    // publish block aggregate (thread 1023 holds block total)
    if (threadIdx.x == 1023) {
        g_bsum[g][b] = incl;
        __threadfence();
        atomicExch(&g_bflag[g * 128 + b], 1);
    }

    // parallel lookback: threads 0..127 each wait on one predecessor
    if (threadIdx.x < 128) {
        int j = threadIdx.x;
        int pv = 0;
        if (j < b) {
            while (atomicAdd(&g_bflag[g * 128 + j], 0) == 0) { }
            pv = g_bsum[g][j];
        }
        #pragma unroll
        for (int o = 16; o; o >>= 1) pv += __shfl_xor_sync(0xffffffffu, pv, o);
        if (lane == 0) sw[j >> 5] = pv;
    }
    __syncthreads();
    if (threadIdx.x == 0) s_base = sw[0] + sw[1] + sw[2] + sw[3];
    __syncthreads();
    int base = s_base;

    if (threadIdx.x == 1023 && b == nb - 1) g_off[g][n] = base + incl;
    if (i >= n) return;
    int val = base + incl - v;   // global exclusive
    if (g < 3) {
        g_off[g][i] = val;
        g_cur[g][i] = val;
    } else if (g == 3) {
        if (g_needU[i] == E) g_cmpU[val] = i;
    } else {
        if (g_needI[i] == E) g_cmpI[val] = i;
    }
}

// ---------------------------------------------------------------------------
// K4: filtered fill — only edges whose dst node is ever read downstream.
// ---------------------------------------------------------------------------
__global__ void fill_all_kernel(const int* __restrict__ d0, const int* __restrict__ s0,
                                const int* __restrict__ d1, const int* __restrict__ s1,
                                const int* __restrict__ d2, const int* __restrict__ s2) {
    int i = blockIdx.x * blockDim.x + threadIdx.x;
    if (i >= 3 * NE4) return;
    int E = __ldg(&g_epoch) + 1;
    int g = i / NE4, j = i % NE4;
    const int* d = (g == 0) ? d0 : (g == 1) ? d1 : d2;
    const int* s = (g == 0) ? s0 : (g == 1) ? s1 : s2;
    const int* need = (g == 0) ? g_needI : g_needU;
    int4 dv = ((const int4*)d)[j];
    int4 sv = ((const int4*)s)[j];
    if (need[dv.x] == E) g_csr[g][atomicAdd(&g_cur[g][dv.x], 1)] = sv.x;
    if (need[dv.y] == E) g_csr[g][atomicAdd(&g_cur[g][dv.y], 1)] = sv.y;
    if (need[dv.z] == E) g_csr[g][atomicAdd(&g_cur[g][dv.z], 1)] = sv.z;
    if (need[dv.w] == E) g_csr[g][atomicAdd(&g_cur[g][dv.w], 1)] = sv.w;
}

// ---------------------------------------------------------------------------
// Gather-mean over fp16 rows (fp32 accumulate, strict index order).
// ---------------------------------------------------------------------------
__device__ __forceinline__ void acc4(float4& a, uint2 u) {
    __half2 h0 = *(__half2*)&u.x, h1 = *(__half2*)&u.y;
    float2 f0 = __half22float2(h0), f1 = __half22float2(h1);
    a.x += f0.x; a.y += f0.y; a.z += f1.x; a.w += f1.y;
}

__device__ __forceinline__ void agg_one(int g, int node, int lane,
                                        const __half* __restrict__ src,
                                        __half* __restrict__ dst) {
    int s = g_off[g][node], e = g_off[g][node + 1];
    const int* lst = g_csr[g];
    float4 acc = make_float4(0.f, 0.f, 0.f, 0.f);
    int i = s;
    for (; i + 8 <= e; i += 8) {
        uint2 v0 = *(const uint2*)(src + (size_t)lst[i]     * H + lane * 4);
        uint2 v1 = *(const uint2*)(src + (size_t)lst[i + 1] * H + lane * 4);
        uint2 v2 = *(const uint2*)(src + (size_t)lst[i + 2] * H + lane * 4);
        uint2 v3 = *(const uint2*)(src + (size_t)lst[i + 3] * H + lane * 4);
        uint2 v4 = *(const uint2*)(src + (size_t)lst[i + 4] * H + lane * 4);
        uint2 v5 = *(const uint2*)(src + (size_t)lst[i + 5] * H + lane * 4);
        uint2 v6 = *(const uint2*)(src + (size_t)lst[i + 6] * H + lane * 4);
        uint2 v7 = *(const uint2*)(src + (size_t)lst[i + 7] * H + lane * 4);
        acc4(acc, v0); acc4(acc, v1); acc4(acc, v2); acc4(acc, v3);
        acc4(acc, v4); acc4(acc, v5); acc4(acc, v6); acc4(acc, v7);
    }
    for (; i + 4 <= e; i += 4) {
        uint2 v0 = *(const uint2*)(src + (size_t)lst[i]     * H + lane * 4);
        uint2 v1 = *(const uint2*)(src + (size_t)lst[i + 1] * H + lane * 4);
        uint2 v2 = *(const uint2*)(src + (size_t)lst[i + 2] * H + lane * 4);
        uint2 v3 = *(const uint2*)(src + (size_t)lst[i + 3] * H + lane * 4);
        acc4(acc, v0); acc4(acc, v1); acc4(acc, v2); acc4(acc, v3);
    }
    for (; i < e; i++) {
        uint2 v0 = *(const uint2*)(src + (size_t)lst[i] * H + lane * 4);
        acc4(acc, v0);
    }
    float inv = (e > s) ? 1.0f / (float)(e - s) : 0.0f;
    __half2 o0 = __floats2half2_rn(acc.x * inv, acc.y * inv);
    __half2 o1 = __floats2half2_rn(acc.z * inv, acc.w * inv);
    uint2 o; o.x = *(unsigned*)&o0; o.y = *(unsigned*)&o1;
    *(uint2*)(dst + lane * 4) = o;
}

// Layer-0 aggregation, pruned: only needed items/users (compact lists).
__global__ void agg_l0_kernel(const __half* __restrict__ eu,
                              const __half* __restrict__ ei) {
    int warp = (blockIdx.x * blockDim.x + threadIdx.x) >> 5;
    int lane = threadIdx.x & 31;
    if (warp < N_ITEM) {
        int nI = __ldg(&g_off[4][N_ITEM]);
        if (warp >= nI) return;
        int node = g_cmpI[warp];
        agg_one(0, node, lane, eu, g_aggI + (size_t)node * H);
    } else {
        int w2 = warp - N_ITEM;
        int nU = __ldg(&g_off[3][N_USER]);
        if (w2 < N_USER) {
            if (w2 >= nU) return;
            int node = g_cmpU[w2];
            agg_one(1, node, lane, ei, g_aggU + (size_t)node * 256);
        } else {
            w2 -= N_USER;
            if (w2 >= N_USER || w2 >= nU) return;
            int node = g_cmpU[w2];
            agg_one(2, node, lane, eu, g_aggU + (size_t)node * 256 + 128);
        }
    }
}

// Layer-1 aggregation: ONLY target users (compact rows 0..N_TGT-1).
__global__ void agg_tgt_kernel(const __half* __restrict__ xi0,
                               const __half* __restrict__ xu0,
                               const int* __restrict__ tgt) {
    int warp = (blockIdx.x * blockDim.x + threadIdx.x) >> 5;
    int lane = threadIdx.x & 31;
    if (warp >= 2 * N_TGT) return;
    int pos = warp & (N_TGT - 1);
    int node = tgt[pos];
    if (warp < N_TGT)
        agg_one(1, node, lane, xi0, g_aggU + (size_t)pos * 256);
    else
        agg_one(2, node, lane, xu0, g_aggU + (size_t)pos * 256 + 128);
}

// ---------------------------------------------------------------------------
// FP16 tensor-core GEMM (cp.async 3-stage) + fused LayerNorm + ReLU, fp16 out.
// ---------------------------------------------------------------------------
#define ASTRIDE 36
#define WSTRIDE 136
#define OSTRIDE 132
#define STAGEB  35840

extern __shared__ char g_smraw[];

struct GemmJob {
    __half* out;
    const __half* A0;
    const __half* A1;
    const int* ridx0;
    const int* ridx1;
    const int* ridxo;
    const int* cnt;
    const unsigned* Wt;
    const float* bias;
    const float* gam;
    const float* bet;
    int lda0, lda1, k0c, nchunk, nrows;
};

__device__ __forceinline__ void mma_f16(float c[4], const unsigned a[4], const unsigned b[2]) {
    asm volatile(
        "mma.sync.aligned.m16n8k16.row.col.f32.f16.f16.f32 "
        "{%0,%1,%2,%3}, {%4,%5,%6,%7}, {%8,%9}, {%0,%1,%2,%3};"
        : "+f"(c[0]), "+f"(c[1]), "+f"(c[2]), "+f"(c[3])
        : "r"(a[0]), "r"(a[1]), "r"(a[2]), "r"(a[3]), "r"(b[0]), "r"(b[1]));
}

__global__ void __launch_bounds__(256, 2) gemm_ln_kernel(GemmJob j0, GemmJob j1, int split) {
    GemmJob J = (blockIdx.x < (unsigned)split) ? j0 : j1;
    int bid = (blockIdx.x < (unsigned)split) ? blockIdx.x : blockIdx.x - split;
    int row0 = bid * 128;

    int nrows = J.cnt ? __ldg(J.cnt) : J.nrows;
    if (row0 >= nrows) return;

    int t = threadIdx.x;
    int lane = t & 31;
    int wid = t >> 5;
    int warp_m = wid & 3;
    int warp_n = wid >> 2;
    int gid = lane >> 2;
    int tig = lane & 3;

    float c[2][8][4];
    #pragma unroll
    for (int nt = 0; nt < 8; nt++) {
        int col = warp_n * 64 + nt * 8 + 2 * tig;
        float b0 = J.bias[col], b1 = J.bias[col + 1];
        #pragma unroll
        for (int mt = 0; mt < 2; mt++) {
            c[mt][nt][0] = b0; c[mt][nt][1] = b1;
            c[mt][nt][2] = b0; c[mt][nt][3] = b1;
        }
    }

    auto load_chunk = [&](int ck, int st) {
        if (ck < J.nchunk) {
            const __half* A; int lda, cb; const int* ridx;
            if (ck < J.k0c) { A = J.A0; lda = J.lda0; cb = ck * 64; ridx = J.ridx0; }
            else            { A = J.A1; lda = J.lda1; cb = (ck - J.k0c) * 64; ridx = J.ridx1; }
            unsigned* As = (unsigned*)(g_smraw + st * STAGEB);
            #pragma unroll
            for (int i2 = 0; i2 < 4; i2++) {
                int idx = t + 256 * i2;
                int r = idx >> 3, u = idx & 7;
                int base = row0 + r;
                int ok = (base < nrows);
                if (!ok) base = row0;
                int row = ridx ? __ldg(ridx + base) : base;
                const __half* src = A + (size_t)row * lda + cb + u * 8;
                CP16(smem_u32(As + r * ASTRIDE + u * 4), src, ok ? 16 : 0);
            }
            unsigned* Ws = (unsigned*)(g_smraw + st * STAGEB + 128 * ASTRIDE * 4);
            #pragma unroll
            for (int i2 = 0; i2 < 4; i2++) {
                int idx = t + 256 * i2;
                int rr = idx >> 5, u = idx & 31;
                const unsigned* src = J.Wt + (size_t)(ck * 32 + rr) * H + u * 4;
                CP16(smem_u32(Ws + rr * WSTRIDE + u * 4), src, 16);
            }
        }
        asm volatile("cp.async.commit_group;\n" ::);
    };

    load_chunk(0, 0);
    load_chunk(1, 1);

    for (int ck = 0; ck < J.nchunk; ck++) {
        asm volatile("cp.async.wait_group 1;\n" ::);
        __syncthreads();
        load_chunk(ck + 2, (ck + 2) % 3);

        int st = ck % 3;
        const unsigned* As = (const unsigned*)(g_smraw + st * STAGEB);
        const unsigned* Ws = (const unsigned*)(g_smraw + st * STAGEB + 128 * ASTRIDE * 4);
        #pragma unroll
        for (int ks = 0; ks < 4; ks++) {
            int k2 = ks * 8;
            unsigned a[2][4];
            #pragma unroll
            for (int mt = 0; mt < 2; mt++) {
                int r = warp_m * 32 + mt * 16 + gid;
                a[mt][0] = As[r * ASTRIDE + k2 + tig];
                a[mt][1] = As[(r + 8) * ASTRIDE + k2 + tig];
                a[mt][2] = As[r * ASTRIDE + k2 + tig + 4];
                a[mt][3] = As[(r + 8) * ASTRIDE + k2 + tig + 4];
            }
            unsigned b[8][2];
            #pragma unroll
            for (int nt = 0; nt < 8; nt++) {
                int cc = warp_n * 64 + nt * 8 + gid;
                b[nt][0] = Ws[(k2 + tig) * WSTRIDE + cc];
                b[nt][1] = Ws[(k2 + tig + 4) * WSTRIDE + cc];
            }
            #pragma unroll
            for (int mt = 0; mt < 2; mt++)
                #pragma unroll
                for (int nt = 0; nt < 8; nt++)
                    mma_f16(c[mt][nt], a[mt], b[nt]);
        }
    }

    // ---- epilogue: stage fp32 to smem, fused LayerNorm + ReLU, fp16 out ----
    asm volatile("cp.async.wait_group 0;\n" ::);
    __syncthreads();
    float* Osm = (float*)g_smraw;
    #pragma unroll
    for (int mt = 0; mt < 2; mt++) {
        #pragma unroll
        for (int nt = 0; nt < 8; nt++) {
            int col = warp_n * 64 + nt * 8 + 2 * tig;
            int r = warp_m * 32 + mt * 16 + gid;
            *(float2*)(Osm + r * OSTRIDE + col)       = make_float2(c[mt][nt][0], c[mt][nt][1]);
            *(float2*)(Osm + (r + 8) * OSTRIDE + col) = make_float2(c[mt][nt][2], c[mt][nt][3]);
        }
    }
    __syncthreads();

    float4 gg = *(const float4*)(J.gam + lane * 4);
    float4 bb = *(const float4*)(J.bet + lane * 4);
    #pragma unroll
    for (int i = 0; i < 16; i++) {
        int r = wid * 16 + i;
        int base = row0 + r;
        if (base >= nrows) break;
        float4 v = *(float4*)(Osm + r * OSTRIDE + lane * 4);
        float s1 = v.x + v.y + v.z + v.w;
        float s2 = v.x * v.x + v.y * v.y + v.z * v.z + v.w * v.w;
        #pragma unroll
        for (int o = 16; o; o >>= 1) {
            s1 += __shfl_xor_sync(0xffffffffu, s1, o);
            s2 += __shfl_xor_sync(0xffffffffu, s2, o);
        }
        float mu = s1 * (1.0f / H);
        float var = s2 * (1.0f / H) - mu * mu;
        float rs = rsqrtf(var + 1e-5f);
        float ox = fmaxf((v.x - mu) * rs * gg.x + bb.x, 0.f);
        float oy = fmaxf((v.y - mu) * rs * gg.y + bb.y, 0.f);
        float oz = fmaxf((v.z - mu) * rs * gg.z + bb.z, 0.f);
        float ow = fmaxf((v.w - mu) * rs * gg.w + bb.w, 0.f);
        __half2 h0 = __floats2half2_rn(ox, oy);
        __half2 h1 = __floats2half2_rn(oz, ow);
        uint2 o; o.x = *(unsigned*)&h0; o.y = *(unsigned*)&h1;
        int orow = J.ridxo ? __ldg(J.ridxo + base) : base;
        *(uint2*)(J.out + (size_t)orow * H + lane * 4) = o;
    }
}

// ---------------------------------------------------------------------------
// MLP head: one warp per TWO targets. Bumps epoch at the very end.
// ---------------------------------------------------------------------------
__global__ void mlp_kernel(const __half* __restrict__ xuc,
                           const float* __restrict__ W1, const float* __restrict__ b1,
                           const float* __restrict__ W2, const float* __restrict__ b2,
                           float* __restrict__ out) {
    int warp = (blockIdx.x * blockDim.x + threadIdx.x) >> 5;
    int lane = threadIdx.x & 31;
    int t0 = warp * 2;
    if (t0 >= N_TGT) {
        return;
    }
    uint2 xra = *(const uint2*)(xuc + (size_t)t0 * H + lane * 4);
    uint2 xrb = *(const uint2*)(xuc + (size_t)(t0 + 1) * H + lane * 4);
    float2 a0 = __half22float2(*(__half2*)&xra.x);
    float2 a1 = __half22float2(*(__half2*)&xra.y);
    float2 c0 = __half22float2(*(__half2*)&xrb.x);
    float2 c1 = __half22float2(*(__half2*)&xrb.y);
    float accA = 0.f, accB = 0.f;
    #pragma unroll 4
    for (int j = 0; j < 64; j++) {
        float4 w = *(const float4*)(W1 + j * H + lane * 4);
        float pA = a0.x * w.x + a0.y * w.y + a1.x * w.z + a1.y * w.w;
        float pB = c0.x * w.x + c0.y * w.y + c1.x * w.z + c1.y * w.w;
        #pragma unroll
        for (int o = 16; o; o >>= 1) {
            pA += __shfl_xor_sync(0xffffffffu, pA, o);
            pB += __shfl_xor_sync(0xffffffffu, pB, o);
        }
        float bj = b1[j], wj = W2[j];
        accA += fmaxf(pA + bj, 0.f) * wj;
        accB += fmaxf(pB + bj, 0.f) * wj;
    }
    if (lane == 0) {
        out[t0]     = accA + b2[0];
        out[t0 + 1] = accB + b2[0];
    }
    // epoch bump (one thread, after all flag consumers in this call)
    if (blockIdx.x == 0 && threadIdx.x == 0) g_epoch = g_epoch + 1;
}

// ---------------------------------------------------------------------------
// Launch
// ---------------------------------------------------------------------------
extern "C" void kernel_launch(void* const* d_in, const int* in_sizes, int n_in,
                              void* d_out, int out_size) {
    const float* emb_user = (const float*)d_in[0];
    const float* emb_item = (const float*)d_in[1];
    const float* Wl       = (const float*)d_in[2];
    const float* bl       = (const float*)d_in[3];
    const float* Wr       = (const float*)d_in[4];
    const float* ln_g     = (const float*)d_in[5];
    const float* ln_b     = (const float*)d_in[6];
    const float* W1       = (const float*)d_in[7];
    const float* b1       = (const float*)d_in[8];
    const float* W2       = (const float*)d_in[9];
    const float* b2       = (const float*)d_in[10];
    const int* src_buys   = (const int*)d_in[11];
    const int* dst_buys   = (const int*)d_in[12];
    const int* src_rev    = (const int*)d_in[13];
    const int* dst_rev    = (const int*)d_in[14];
    const int* src_fol    = (const int*)d_in[15];
    const int* dst_fol    = (const int*)d_in[16];
    const int* target_ids = (const int*)d_in[17];
    float* out = (float*)d_out;

    __half *p_eu16, *p_ei16, *p_xu0h, *p_xi0h, *p_xufh, *p_aggU, *p_aggI;
    unsigned* p_wth;
    float* p_bias;
    int *p_off, *p_cmpU, *p_cmpI;
    cudaGetSymbolAddress((void**)&p_eu16, g_eu16);
    cudaGetSymbolAddress((void**)&p_ei16, g_ei16);
    cudaGetSymbolAddress((void**)&p_xu0h, g_xu0h);
    cudaGetSymbolAddress((void**)&p_xi0h, g_xi0h);
    cudaGetSymbolAddress((void**)&p_xufh, g_xufh);
    cudaGetSymbolAddress((void**)&p_aggU, g_aggU);
    cudaGetSymbolAddress((void**)&p_aggI, g_aggI);
    cudaGetSymbolAddress((void**)&p_wth,  g_wth);
    cudaGetSymbolAddress((void**)&p_bias, g_bias);
    cudaGetSymbolAddress((void**)&p_off,  g_off);
    cudaGetSymbolAddress((void**)&p_cmpU, g_cmpU);
    cudaGetSymbolAddress((void**)&p_cmpI, g_cmpI);

    const int* p_cntU = p_off + 3 * (N_USER + 1) + N_USER;   // g_off[3][N_USER]
    const int* p_cntI = p_off + 4 * (N_USER + 1) + N_ITEM;   // g_off[4][N_ITEM]

    const int smem_bytes = 3 * STAGEB;   // 107520
    cudaFuncSetAttribute(gemm_ln_kernel,
                         cudaFuncAttributeMaxDynamicSharedMemorySize, smem_bytes);

    // --- CSR + pruning chain ---
    zeroflag_kernel<<<(ZF_TOT + 255) / 256, 256>>>(target_ids);
    count_prep_kernel<<<CBLK + PBLK, 256>>>(dst_buys,
                                            dst_rev, src_rev,
                                            dst_fol, src_fol,
                                            emb_user, emb_item, Wl, Wr, bl);
    scan_kernel<<<SCAN_BLOCKS, 1024>>>();
    fill_all_kernel<<<(3 * NE4 + 255) / 256, 256>>>(dst_buys, src_buys,
                                                    dst_rev, src_rev,
                                                    dst_fol, src_fol);

    // ===== layer 0 (pruned to needed nodes) =====
    {
        int nwarp = N_ITEM + 2 * N_USER;
        agg_l0_kernel<<<(nwarp * 32 + 255) / 256, 256>>>(p_eu16, p_ei16);

        GemmJob ji, ju;
        ji.out = p_xi0h; ji.A0 = p_ei16; ji.A1 = p_aggI;
        ji.ridx0 = p_cmpI; ji.ridx1 = p_cmpI; ji.ridxo = p_cmpI; ji.cnt = p_cntI;
        ji.Wt = p_wth; ji.bias = p_bias;
        ji.gam = ln_g + 1 * H; ji.bet = ln_b + 1 * H;
        ji.lda0 = H; ji.lda1 = H; ji.k0c = 2; ji.nchunk = 4; ji.nrows = N_ITEM;

        ju.out = p_xu0h; ju.A0 = p_eu16; ju.A1 = p_aggU;
        ju.ridx0 = p_cmpU; ju.ridx1 = p_cmpU; ju.ridxo = p_cmpU; ju.cnt = p_cntU;
        ju.Wt = p_wth + 128 * H; ju.bias = p_bias + 1 * H;
        ju.gam = ln_g + 0 * H; ju.bet = ln_b + 0 * H;
        ju.lda0 = H; ju.lda1 = 256; ju.k0c = 2; ju.nchunk = 6; ju.nrows = N_USER;

        int nbi = (N_ITEM + 127) / 128;
        int nbu = (N_USER + 127) / 128;
        gemm_ln_kernel<<<nbi + nbu, 256, smem_bytes>>>(ji, ju, nbi);
    }
    // ===== layer 1: only target rows =====
    {
        agg_tgt_kernel<<<(2 * N_TGT * 32 + 255) / 256, 256>>>(p_xi0h, p_xu0h, target_ids);

        GemmJob jt;
        jt.out = p_xufh; jt.A0 = p_xu0h; jt.A1 = p_aggU;
        jt.ridx0 = target_ids; jt.ridx1 = nullptr; jt.ridxo = nullptr; jt.cnt = nullptr;
        jt.Wt = p_wth + (128 + 192) * H; jt.bias = p_bias + 2 * H;
        jt.gam = ln_g + 2 * H; jt.bet = ln_b + 2 * H;
        jt.lda0 = H; jt.lda1 = 256; jt.k0c = 2; jt.nchunk = 6; jt.nrows = N_TGT;

        int nbt = N_TGT / 128;
        gemm_ln_kernel<<<nbt, 256, smem_bytes>>>(jt, jt, nbt);
    }

    mlp_kernel<<<(N_TGT / 2 * 32 + 255) / 256, 256>>>(
        p_xufh, W1, b1, W2, b2, out);
}

// round 10
// speedup vs baseline: 5.1466x; 1.0279x over previous
#include <cuda_runtime.h>
#include <cuda_fp16.h>
#include <cstdint>

#define N_USER 100000
#define N_ITEM 50000
#define NE     800000
#define NE4    (NE / 4)
#define H      128
#define N_TGT  8192

// ---------------------------------------------------------------------------
// Static device scratch (fp16 feature world)
// ---------------------------------------------------------------------------
__device__ __half g_eu16[N_USER * H];
__device__ __half g_ei16[N_ITEM * H];
__device__ __half g_xu0h[N_USER * H];
__device__ __half g_xi0h[N_ITEM * H];
__device__ __half g_xufh[N_TGT * H];
__device__ __half g_aggU[N_USER * 256];     // layer0: [mrev|mfol]; layer1: compact rows
__device__ __half g_aggI[N_ITEM * H];
__device__ unsigned g_wth[(128 + 192 + 192) * H];
__device__ float g_bias[3 * H];

// CSR + scan scratch. scan rows: 0..2 = graph degree counts, 3 = needU, 4 = needI
// INVARIANT: g_cnt / g_bflag / g_ticket are ZERO at entry of every call
// (zero-initialized at load; re-zeroed by tail blocks of mlp each call).
__device__ int g_cnt[3][N_USER + 1];
__device__ int g_off[5][N_USER + 1];
__device__ int g_cur[3][N_USER];
__device__ int g_csr[3][NE];
__device__ int g_bsum[5][128];
__device__ int g_bflag[5 * 128];
__device__ int g_ticket;

// pruning flags: store epoch value (== current call's E means set)
__device__ int g_epoch;                     // bumped once at end of each call
__device__ int g_tflag[N_USER];
__device__ int g_needU[N_USER];
__device__ int g_needI[N_ITEM];
__device__ int g_cmpU[N_USER];
__device__ int g_cmpI[N_ITEM];

// graph ids: 0 = buys (dst=item), 1 = rev (dst=user), 2 = fol (dst=user)

__device__ __forceinline__ unsigned smem_u32(const void* p) {
    return (unsigned)__cvta_generic_to_shared(p);
}
#define CP16(dst, src, sz) \
    asm volatile("cp.async.cg.shared.global [%0], [%1], 16, %2;\n" \
                 :: "r"(dst), "l"(src), "r"(sz))

// ---------------------------------------------------------------------------
// K1: flag targets with epoch (tiny)
// ---------------------------------------------------------------------------
__global__ void flag_kernel(const int* __restrict__ tgt) {
    int i = blockIdx.x * blockDim.x + threadIdx.x;
    if (i < N_TGT) {
        int E = __ldg(&g_epoch) + 1;
        int t = tgt[i];
        g_tflag[t] = E;
        g_needU[t] = E;
    }
}

// ---------------------------------------------------------------------------
// K2: fused [degree count + need flags] ++ [emb->fp16 + weight/bias prep]
// ---------------------------------------------------------------------------
#define NU8   (N_USER * H / 8)
#define NI8   (N_ITEM * H / 8)
#define WTOT  ((128 + 192 + 192) * H)
#define PREPN (NU8 + NI8 + WTOT + 3 * H)
#define CBLK  ((3 * NE4 + 255) / 256)
#define PBLK  ((PREPN + 255) / 256)

__device__ __forceinline__ uint4 pack8(float4 a, float4 b) {
    __half2 h0 = __floats2half2_rn(a.x, a.y);
    __half2 h1 = __floats2half2_rn(a.z, a.w);
    __half2 h2 = __floats2half2_rn(b.x, b.y);
    __half2 h3 = __floats2half2_rn(b.z, b.w);
    uint4 u;
    u.x = *(unsigned*)&h0; u.y = *(unsigned*)&h1;
    u.z = *(unsigned*)&h2; u.w = *(unsigned*)&h3;
    return u;
}
__device__ __forceinline__ float wval_item(const float* Wl, const float* Wr, int k, int j) {
    return (k < 128) ? Wr[(0 * H + j) * H + k] : Wl[(0 * H + j) * H + (k - 128)];
}
__device__ __forceinline__ float wval_user(const float* Wl, const float* Wr, int l, int k, int j) {
    if (k < 128) return Wr[((l * 3 + 1) * H + j) * H + k] + Wr[((l * 3 + 2) * H + j) * H + k];
    if (k < 256) return Wl[((l * 3 + 1) * H + j) * H + (k - 128)];
    return Wl[((l * 3 + 2) * H + j) * H + (k - 256)];
}

__global__ void count_prep_kernel(const int* __restrict__ d0,
                                  const int* __restrict__ d1, const int* __restrict__ s1,
                                  const int* __restrict__ d2, const int* __restrict__ s2,
                                  const float* __restrict__ eu, const float* __restrict__ ei,
                                  const float* __restrict__ Wl, const float* __restrict__ Wr,
                                  const float* __restrict__ bl) {
    if (blockIdx.x < CBLK) {
        int i = blockIdx.x * blockDim.x + threadIdx.x;
        if (i >= 3 * NE4) return;
        int E = __ldg(&g_epoch) + 1;
        int g = i / NE4, j = i % NE4;
        if (g == 0) {
            int4 v = ((const int4*)d0)[j];
            atomicAdd(&g_cnt[0][v.x], 1);
            atomicAdd(&g_cnt[0][v.y], 1);
            atomicAdd(&g_cnt[0][v.z], 1);
            atomicAdd(&g_cnt[0][v.w], 1);
        } else if (g == 1) {
            int4 d = ((const int4*)d1)[j];
            int4 s = ((const int4*)s1)[j];
            atomicAdd(&g_cnt[1][d.x], 1);
            atomicAdd(&g_cnt[1][d.y], 1);
            atomicAdd(&g_cnt[1][d.z], 1);
            atomicAdd(&g_cnt[1][d.w], 1);
            if (g_tflag[d.x] == E) g_needI[s.x] = E;
            if (g_tflag[d.y] == E) g_needI[s.y] = E;
            if (g_tflag[d.z] == E) g_needI[s.z] = E;
            if (g_tflag[d.w] == E) g_needI[s.w] = E;
        } else {
            int4 d = ((const int4*)d2)[j];
            int4 s = ((const int4*)s2)[j];
            atomicAdd(&g_cnt[2][d.x], 1);
            atomicAdd(&g_cnt[2][d.y], 1);
            atomicAdd(&g_cnt[2][d.z], 1);
            atomicAdd(&g_cnt[2][d.w], 1);
            if (g_tflag[d.x] == E) g_needU[s.x] = E;
            if (g_tflag[d.y] == E) g_needU[s.y] = E;
            if (g_tflag[d.z] == E) g_needU[s.z] = E;
            if (g_tflag[d.w] == E) g_needU[s.w] = E;
        }
        return;
    }
    // ---- prep part ----
    int i = (blockIdx.x - CBLK) * blockDim.x + threadIdx.x;
    if (i < NU8) {
        float4 a = ((const float4*)eu)[2 * i], b = ((const float4*)eu)[2 * i + 1];
        ((uint4*)g_eu16)[i] = pack8(a, b);
        return;
    }
    int j = i - NU8;
    if (j < NI8) {
        float4 a = ((const float4*)ei)[2 * j], b = ((const float4*)ei)[2 * j + 1];
        ((uint4*)g_ei16)[j] = pack8(a, b);
        return;
    }
    j -= NI8;
    if (j < WTOT) {
        float v0, v1;
        if (j < 128 * H) {
            int k2 = j >> 7, c = j & 127;
            v0 = wval_item(Wl, Wr, 2 * k2, c);
            v1 = wval_item(Wl, Wr, 2 * k2 + 1, c);
        } else {
            int rel = j - 128 * H;
            int l = (rel < 192 * H) ? 0 : 1;
            if (l == 1) rel -= 192 * H;
            int k2 = rel >> 7, c = rel & 127;
            v0 = wval_user(Wl, Wr, l, 2 * k2, c);
            v1 = wval_user(Wl, Wr, l, 2 * k2 + 1, c);
        }
        __half2 h = __floats2half2_rn(v0, v1);
        g_wth[j] = *(unsigned*)&h;
        return;
    }
    j -= WTOT;
    if (j < 3 * H) {
        int slot = j >> 7, c = j & 127;
        float b;
        if (slot == 0)      b = bl[0 * H + c];
        else if (slot == 1) b = bl[1 * H + c] + bl[2 * H + c];
        else                b = bl[(3 + 1) * H + c] + bl[(3 + 2) * H + c];
        g_bias[j] = b;
    }
}

// ---------------------------------------------------------------------------
// K3: single-pass scan over 5 rows with ticket-ordered parallel lookback.
// ---------------------------------------------------------------------------
#define NB_I 49
#define NB_U 98
#define SCAN_BLOCKS (NB_I + NB_U + NB_U + NB_U + NB_I)

__device__ __forceinline__ int scan_n(int g) {
    return (g == 0 || g == 4) ? N_ITEM : N_USER;
}

__global__ void scan_kernel() {
    __shared__ int s_g, s_b;
    __shared__ int warp_sums[32];
    __shared__ int sw[4];
    __shared__ int s_base;

    if (threadIdx.x == 0) {
        int v = atomicAdd(&g_ticket, 1);
        int g, b;
        if (v < NB_I)                         { g = 0; b = v; }
        else if (v < NB_I + NB_U)             { g = 1; b = v - NB_I; }
        else if (v < NB_I + 2 * NB_U)         { g = 2; b = v - NB_I - NB_U; }
        else if (v < NB_I + 3 * NB_U)         { g = 3; b = v - NB_I - 2 * NB_U; }
        else                                  { g = 4; b = v - NB_I - 3 * NB_U; }
        s_g = g; s_b = b;
    }
    __syncthreads();
    int g = s_g, b = s_b;
    int n = scan_n(g);
    int nb = (g == 0 || g == 4) ? NB_I : NB_U;
    int E = __ldg(&g_epoch) + 1;

    int i = b * 1024 + (int)threadIdx.x;
    int v;
    if (i >= n) v = 0;
    else if (g < 3) v = g_cnt[g][i];
    else if (g == 3) v = (g_needU[i] == E) ? 1 : 0;
    else v = (g_needI[i] == E) ? 1 : 0;

    int lane = threadIdx.x & 31, wid = threadIdx.x >> 5;
    int x = v;
    #pragma unroll
    for (int s = 1; s < 32; s <<= 1) {
        int y = __shfl_up_sync(0xffffffffu, x, s);
        if (lane >= s) x += y;
    }
    if (lane == 31) warp_sums[wid] = x;
    __syncthreads();
    if (wid == 0) {
        int w = warp_sums[lane];
        int xw = w;
        #pragma unroll
        for (int s = 1; s < 32; s <<= 1) {
            int y = __shfl_up_sync(0xffffffffu, xw, s);
            if (lane >= s) xw += y;
        }
        warp_sums[lane] = xw - w;
    }
    __syncthreads();
    int incl = x + warp_sums[wid];

    if (threadIdx.x == 1023) {
        g_bsum[g][b] = incl;
        __threadfence();
        atomicExch(&g_bflag[g * 128 + b], 1);
    }

    if (threadIdx.x < 128) {
        int j = threadIdx.x;
        int pv = 0;
        if (j < b) {
            while (atomicAdd(&g_bflag[g * 128 + j], 0) == 0) { }
            pv = g_bsum[g][j];
        }
        #pragma unroll
        for (int o = 16; o; o >>= 1) pv += __shfl_xor_sync(0xffffffffu, pv, o);
        if (lane == 0) sw[j >> 5] = pv;
    }
    __syncthreads();
    if (threadIdx.x == 0) s_base = sw[0] + sw[1] + sw[2] + sw[3];
    __syncthreads();
    int base = s_base;

    if (threadIdx.x == 1023 && b == nb - 1) g_off[g][n] = base + incl;
    if (i >= n) return;
    int val = base + incl - v;
    if (g < 3) {
        g_off[g][i] = val;
        g_cur[g][i] = val;
    } else if (g == 3) {
        if (g_needU[i] == E) g_cmpU[val] = i;
    } else {
        if (g_needI[i] == E) g_cmpI[val] = i;
    }
}

// ---------------------------------------------------------------------------
// K4: filtered fill — only edges whose dst node is ever read downstream.
// ---------------------------------------------------------------------------
__global__ void fill_all_kernel(const int* __restrict__ d0, const int* __restrict__ s0,
                                const int* __restrict__ d1, const int* __restrict__ s1,
                                const int* __restrict__ d2, const int* __restrict__ s2) {
    int i = blockIdx.x * blockDim.x + threadIdx.x;
    if (i >= 3 * NE4) return;
    int E = __ldg(&g_epoch) + 1;
    int g = i / NE4, j = i % NE4;
    const int* d = (g == 0) ? d0 : (g == 1) ? d1 : d2;
    const int* s = (g == 0) ? s0 : (g == 1) ? s1 : s2;
    const int* need = (g == 0) ? g_needI : g_needU;
    int4 dv = ((const int4*)d)[j];
    int4 sv = ((const int4*)s)[j];
    if (need[dv.x] == E) g_csr[g][atomicAdd(&g_cur[g][dv.x], 1)] = sv.x;
    if (need[dv.y] == E) g_csr[g][atomicAdd(&g_cur[g][dv.y], 1)] = sv.y;
    if (need[dv.z] == E) g_csr[g][atomicAdd(&g_cur[g][dv.z], 1)] = sv.z;
    if (need[dv.w] == E) g_csr[g][atomicAdd(&g_cur[g][dv.w], 1)] = sv.w;
}

// ---------------------------------------------------------------------------
// Gather-mean over fp16 rows (fp32 accumulate, strict index order).
// ---------------------------------------------------------------------------
__device__ __forceinline__ void acc4(float4& a, uint2 u) {
    __half2 h0 = *(__half2*)&u.x, h1 = *(__half2*)&u.y;
    float2 f0 = __half22float2(h0), f1 = __half22float2(h1);
    a.x += f0.x; a.y += f0.y; a.z += f1.x; a.w += f1.y;
}

__device__ __forceinline__ void agg_one(int g, int node, int lane,
                                        const __half* __restrict__ src,
                                        __half* __restrict__ dst) {
    int s = g_off[g][node], e = g_off[g][node + 1];
    const int* lst = g_csr[g];
    float4 acc = make_float4(0.f, 0.f, 0.f, 0.f);
    int i = s;
    for (; i + 8 <= e; i += 8) {
        uint2 v0 = *(const uint2*)(src + (size_t)lst[i]     * H + lane * 4);
        uint2 v1 = *(const uint2*)(src + (size_t)lst[i + 1] * H + lane * 4);
        uint2 v2 = *(const uint2*)(src + (size_t)lst[i + 2] * H + lane * 4);
        uint2 v3 = *(const uint2*)(src + (size_t)lst[i + 3] * H + lane * 4);
        uint2 v4 = *(const uint2*)(src + (size_t)lst[i + 4] * H + lane * 4);
        uint2 v5 = *(const uint2*)(src + (size_t)lst[i + 5] * H + lane * 4);
        uint2 v6 = *(const uint2*)(src + (size_t)lst[i + 6] * H + lane * 4);
        uint2 v7 = *(const uint2*)(src + (size_t)lst[i + 7] * H + lane * 4);
        acc4(acc, v0); acc4(acc, v1); acc4(acc, v2); acc4(acc, v3);
        acc4(acc, v4); acc4(acc, v5); acc4(acc, v6); acc4(acc, v7);
    }
    for (; i + 4 <= e; i += 4) {
        uint2 v0 = *(const uint2*)(src + (size_t)lst[i]     * H + lane * 4);
        uint2 v1 = *(const uint2*)(src + (size_t)lst[i + 1] * H + lane * 4);
        uint2 v2 = *(const uint2*)(src + (size_t)lst[i + 2] * H + lane * 4);
        uint2 v3 = *(const uint2*)(src + (size_t)lst[i + 3] * H + lane * 4);
        acc4(acc, v0); acc4(acc, v1); acc4(acc, v2); acc4(acc, v3);
    }
    for (; i < e; i++) {
        uint2 v0 = *(const uint2*)(src + (size_t)lst[i] * H + lane * 4);
        acc4(acc, v0);
    }
    float inv = (e > s) ? 1.0f / (float)(e - s) : 0.0f;
    __half2 o0 = __floats2half2_rn(acc.x * inv, acc.y * inv);
    __half2 o1 = __floats2half2_rn(acc.z * inv, acc.w * inv);
    uint2 o; o.x = *(unsigned*)&o0; o.y = *(unsigned*)&o1;
    *(uint2*)(dst + lane * 4) = o;
}

// Layer-0 aggregation, pruned: only needed items/users (compact lists).
__global__ void agg_l0_kernel(const __half* __restrict__ eu,
                              const __half* __restrict__ ei) {
    int warp = (blockIdx.x * blockDim.x + threadIdx.x) >> 5;
    int lane = threadIdx.x & 31;
    if (warp < N_ITEM) {
        int nI = __ldg(&g_off[4][N_ITEM]);
        if (warp >= nI) return;
        int node = g_cmpI[warp];
        agg_one(0, node, lane, eu, g_aggI + (size_t)node * H);
    } else {
        int w2 = warp - N_ITEM;
        int nU = __ldg(&g_off[3][N_USER]);
        if (w2 < N_USER) {
            if (w2 >= nU) return;
            int node = g_cmpU[w2];
            agg_one(1, node, lane, ei, g_aggU + (size_t)node * 256);
        } else {
            w2 -= N_USER;
            if (w2 >= N_USER || w2 >= nU) return;
            int node = g_cmpU[w2];
            agg_one(2, node, lane, eu, g_aggU + (size_t)node * 256 + 128);
        }
    }
}

// Layer-1 aggregation: ONLY target users (compact rows 0..N_TGT-1).
__global__ void agg_tgt_kernel(const __half* __restrict__ xi0,
                               const __half* __restrict__ xu0,
                               const int* __restrict__ tgt) {
    int warp = (blockIdx.x * blockDim.x + threadIdx.x) >> 5;
    int lane = threadIdx.x & 31;
    if (warp >= 2 * N_TGT) return;
    int pos = warp & (N_TGT - 1);
    int node = tgt[pos];
    if (warp < N_TGT)
        agg_one(1, node, lane, xi0, g_aggU + (size_t)pos * 256);
    else
        agg_one(2, node, lane, xu0, g_aggU + (size_t)pos * 256 + 128);
}

// ---------------------------------------------------------------------------
// FP16 tensor-core GEMM (cp.async 3-stage) + fused LayerNorm + ReLU, fp16 out.
// ---------------------------------------------------------------------------
#define ASTRIDE 36
#define WSTRIDE 136
#define OSTRIDE 132
#define STAGEB  35840

extern __shared__ char g_smraw[];

struct GemmJob {
    __half* out;
    const __half* A0;
    const __half* A1;
    const int* ridx0;
    const int* ridx1;
    const int* ridxo;
    const int* cnt;
    const unsigned* Wt;
    const float* bias;
    const float* gam;
    const float* bet;
    int lda0, lda1, k0c, nchunk, nrows;
};

__device__ __forceinline__ void mma_f16(float c[4], const unsigned a[4], const unsigned b[2]) {
    asm volatile(
        "mma.sync.aligned.m16n8k16.row.col.f32.f16.f16.f32 "
        "{%0,%1,%2,%3}, {%4,%5,%6,%7}, {%8,%9}, {%0,%1,%2,%3};"
        : "+f"(c[0]), "+f"(c[1]), "+f"(c[2]), "+f"(c[3])
        : "r"(a[0]), "r"(a[1]), "r"(a[2]), "r"(a[3]), "r"(b[0]), "r"(b[1]));
}

__global__ void __launch_bounds__(256, 2) gemm_ln_kernel(GemmJob j0, GemmJob j1, int split) {
    GemmJob J = (blockIdx.x < (unsigned)split) ? j0 : j1;
    int bid = (blockIdx.x < (unsigned)split) ? blockIdx.x : blockIdx.x - split;
    int row0 = bid * 128;

    int nrows = J.cnt ? __ldg(J.cnt) : J.nrows;
    if (row0 >= nrows) return;

    int t = threadIdx.x;
    int lane = t & 31;
    int wid = t >> 5;
    int warp_m = wid & 3;
    int warp_n = wid >> 2;
    int gid = lane >> 2;
    int tig = lane & 3;

    float c[2][8][4];
    #pragma unroll
    for (int nt = 0; nt < 8; nt++) {
        int col = warp_n * 64 + nt * 8 + 2 * tig;
        float b0 = J.bias[col], b1 = J.bias[col + 1];
        #pragma unroll
        for (int mt = 0; mt < 2; mt++) {
            c[mt][nt][0] = b0; c[mt][nt][1] = b1;
            c[mt][nt][2] = b0; c[mt][nt][3] = b1;
        }
    }

    auto load_chunk = [&](int ck, int st) {
        if (ck < J.nchunk) {
            const __half* A; int lda, cb; const int* ridx;
            if (ck < J.k0c) { A = J.A0; lda = J.lda0; cb = ck * 64; ridx = J.ridx0; }
            else            { A = J.A1; lda = J.lda1; cb = (ck - J.k0c) * 64; ridx = J.ridx1; }
            unsigned* As = (unsigned*)(g_smraw + st * STAGEB);
            #pragma unroll
            for (int i2 = 0; i2 < 4; i2++) {
                int idx = t + 256 * i2;
                int r = idx >> 3, u = idx & 7;
                int base = row0 + r;
                int ok = (base < nrows);
                if (!ok) base = row0;
                int row = ridx ? __ldg(ridx + base) : base;
                const __half* src = A + (size_t)row * lda + cb + u * 8;
                CP16(smem_u32(As + r * ASTRIDE + u * 4), src, ok ? 16 : 0);
            }
            unsigned* Ws = (unsigned*)(g_smraw + st * STAGEB + 128 * ASTRIDE * 4);
            #pragma unroll
            for (int i2 = 0; i2 < 4; i2++) {
                int idx = t + 256 * i2;
                int rr = idx >> 5, u = idx & 31;
                const unsigned* src = J.Wt + (size_t)(ck * 32 + rr) * H + u * 4;
                CP16(smem_u32(Ws + rr * WSTRIDE + u * 4), src, 16);
            }
        }
        asm volatile("cp.async.commit_group;\n" ::);
    };

    load_chunk(0, 0);
    load_chunk(1, 1);

    for (int ck = 0; ck < J.nchunk; ck++) {
        asm volatile("cp.async.wait_group 1;\n" ::);
        __syncthreads();
        load_chunk(ck + 2, (ck + 2) % 3);

        int st = ck % 3;
        const unsigned* As = (const unsigned*)(g_smraw + st * STAGEB);
        const unsigned* Ws = (const unsigned*)(g_smraw + st * STAGEB + 128 * ASTRIDE * 4);
        #pragma unroll
        for (int ks = 0; ks < 4; ks++) {
            int k2 = ks * 8;
            unsigned a[2][4];
            #pragma unroll
            for (int mt = 0; mt < 2; mt++) {
                int r = warp_m * 32 + mt * 16 + gid;
                a[mt][0] = As[r * ASTRIDE + k2 + tig];
                a[mt][1] = As[(r + 8) * ASTRIDE + k2 + tig];
                a[mt][2] = As[r * ASTRIDE + k2 + tig + 4];
                a[mt][3] = As[(r + 8) * ASTRIDE + k2 + tig + 4];
            }
            unsigned b[8][2];
            #pragma unroll
            for (int nt = 0; nt < 8; nt++) {
                int cc = warp_n * 64 + nt * 8 + gid;
                b[nt][0] = Ws[(k2 + tig) * WSTRIDE + cc];
                b[nt][1] = Ws[(k2 + tig + 4) * WSTRIDE + cc];
            }
            #pragma unroll
            for (int mt = 0; mt < 2; mt++)
                #pragma unroll
                for (int nt = 0; nt < 8; nt++)
                    mma_f16(c[mt][nt], a[mt], b[nt]);
        }
    }

    // ---- epilogue: stage fp32 to smem, fused LayerNorm + ReLU, fp16 out ----
    asm volatile("cp.async.wait_group 0;\n" ::);
    __syncthreads();
    float* Osm = (float*)g_smraw;
    #pragma unroll
    for (int mt = 0; mt < 2; mt++) {
        #pragma unroll
        for (int nt = 0; nt < 8; nt++) {
            int col = warp_n * 64 + nt * 8 + 2 * tig;
            int r = warp_m * 32 + mt * 16 + gid;
            *(float2*)(Osm + r * OSTRIDE + col)       = make_float2(c[mt][nt][0], c[mt][nt][1]);
            *(float2*)(Osm + (r + 8) * OSTRIDE + col) = make_float2(c[mt][nt][2], c[mt][nt][3]);
        }
    }
    __syncthreads();

    float4 gg = *(const float4*)(J.gam + lane * 4);
    float4 bb = *(const float4*)(J.bet + lane * 4);
    #pragma unroll
    for (int i = 0; i < 16; i++) {
        int r = wid * 16 + i;
        int base = row0 + r;
        if (base >= nrows) break;
        float4 v = *(float4*)(Osm + r * OSTRIDE + lane * 4);
        float s1 = v.x + v.y + v.z + v.w;
        float s2 = v.x * v.x + v.y * v.y + v.z * v.z + v.w * v.w;
        #pragma unroll
        for (int o = 16; o; o >>= 1) {
            s1 += __shfl_xor_sync(0xffffffffu, s1, o);
            s2 += __shfl_xor_sync(0xffffffffu, s2, o);
        }
        float mu = s1 * (1.0f / H);
        float var = s2 * (1.0f / H) - mu * mu;
        float rs = rsqrtf(var + 1e-5f);
        float ox = fmaxf((v.x - mu) * rs * gg.x + bb.x, 0.f);
        float oy = fmaxf((v.y - mu) * rs * gg.y + bb.y, 0.f);
        float oz = fmaxf((v.z - mu) * rs * gg.z + bb.z, 0.f);
        float ow = fmaxf((v.w - mu) * rs * gg.w + bb.w, 0.f);
        __half2 h0 = __floats2half2_rn(ox, oy);
        __half2 h1 = __floats2half2_rn(oz, ow);
        uint2 o; o.x = *(unsigned*)&h0; o.y = *(unsigned*)&h1;
        int orow = J.ridxo ? __ldg(J.ridxo + base) : base;
        *(uint2*)(J.out + (size_t)orow * H + lane * 4) = o;
    }
}

// ---------------------------------------------------------------------------
// K-last: MLP head (W1/b1/W2 staged in smem; 2 targets per warp)
//         + tail blocks re-zero g_cnt/g_bflag/g_ticket for the next call,
//         + epoch bump.
// ---------------------------------------------------------------------------
#define MLP_BLK (N_TGT / 16)              // 512 blocks, 8 warps x 2 targets
#define ZCNT  (3 * (N_USER + 1))
#define ZTOT  (ZCNT + 5 * 128 + 1)
#define ZBLK  ((ZTOT + 255) / 256)

__global__ void mlp_kernel(const __half* __restrict__ xuc,
                           const float* __restrict__ W1, const float* __restrict__ b1,
                           const float* __restrict__ W2, const float* __restrict__ b2,
                           float* __restrict__ out) {
    if (blockIdx.x >= MLP_BLK) {
        // tail: restore the zero-invariant for the next call
        int i = (blockIdx.x - MLP_BLK) * blockDim.x + threadIdx.x;
        if (i < ZCNT) { ((int*)g_cnt)[i] = 0; return; }
        int j = i - ZCNT;
        if (j < 5 * 128) { g_bflag[j] = 0; return; }
        if (j == 5 * 128) g_ticket = 0;
        return;
    }

    __shared__ float sW1[64 * H];
    __shared__ float sC[128];             // [0:64) b1, [64:128) W2
    int t = threadIdx.x;
    #pragma unroll
    for (int i = 0; i < 8; i++)
        ((float4*)sW1)[t + 256 * i] = ((const float4*)W1)[t + 256 * i];
    if (t < 64) { sC[t] = b1[t]; sC[64 + t] = W2[t]; }
    __syncthreads();

    int lane = t & 31;
    int warp = blockIdx.x * 8 + (t >> 5);
    int t0 = warp * 2;
    uint2 xra = *(const uint2*)(xuc + (size_t)t0 * H + lane * 4);
    uint2 xrb = *(const uint2*)(xuc + (size_t)(t0 + 1) * H + lane * 4);
    float2 a0 = __half22float2(*(__half2*)&xra.x);
    float2 a1 = __half22float2(*(__half2*)&xra.y);
    float2 c0 = __half22float2(*(__half2*)&xrb.x);
    float2 c1 = __half22float2(*(__half2*)&xrb.y);
    float accA = 0.f, accB = 0.f;
    #pragma unroll 4
    for (int j = 0; j < 64; j++) {
        float4 w = *(const float4*)(sW1 + j * H + lane * 4);
        float pA = a0.x * w.x + a0.y * w.y + a1.x * w.z + a1.y * w.w;
        float pB = c0.x * w.x + c0.y * w.y + c1.x * w.z + c1.y * w.w;
        #pragma unroll
        for (int o = 16; o; o >>= 1) {
            pA += __shfl_xor_sync(0xffffffffu, pA, o);
            pB += __shfl_xor_sync(0xffffffffu, pB, o);
        }
        float bj = sC[j], wj = sC[64 + j];
        accA += fmaxf(pA + bj, 0.f) * wj;
        accB += fmaxf(pB + bj, 0.f) * wj;
    }
    if (lane == 0) {
        float bb2 = b2[0];
        out[t0]     = accA + bb2;
        out[t0 + 1] = accB + bb2;
    }
    if (blockIdx.x == 0 && t == 0) g_epoch = g_epoch + 1;
}

// ---------------------------------------------------------------------------
// Launch
// ---------------------------------------------------------------------------
extern "C" void kernel_launch(void* const* d_in, const int* in_sizes, int n_in,
                              void* d_out, int out_size) {
    const float* emb_user = (const float*)d_in[0];
    const float* emb_item = (const float*)d_in[1];
    const float* Wl       = (const float*)d_in[2];
    const float* bl       = (const float*)d_in[3];
    const float* Wr       = (const float*)d_in[4];
    const float* ln_g     = (const float*)d_in[5];
    const float* ln_b     = (const float*)d_in[6];
    const float* W1       = (const float*)d_in[7];
    const float* b1       = (const float*)d_in[8];
    const float* W2       = (const float*)d_in[9];
    const float* b2       = (const float*)d_in[10];
    const int* src_buys   = (const int*)d_in[11];
    const int* dst_buys   = (const int*)d_in[12];
    const int* src_rev    = (const int*)d_in[13];
    const int* dst_rev    = (const int*)d_in[14];
    const int* src_fol    = (const int*)d_in[15];
    const int* dst_fol    = (const int*)d_in[16];
    const int* target_ids = (const int*)d_in[17];
    float* out = (float*)d_out;

    __half *p_eu16, *p_ei16, *p_xu0h, *p_xi0h, *p_xufh, *p_aggU, *p_aggI;
    unsigned* p_wth;
    float* p_bias;
    int *p_off, *p_cmpU, *p_cmpI;
    cudaGetSymbolAddress((void**)&p_eu16, g_eu16);
    cudaGetSymbolAddress((void**)&p_ei16, g_ei16);
    cudaGetSymbolAddress((void**)&p_xu0h, g_xu0h);
    cudaGetSymbolAddress((void**)&p_xi0h, g_xi0h);
    cudaGetSymbolAddress((void**)&p_xufh, g_xufh);
    cudaGetSymbolAddress((void**)&p_aggU, g_aggU);
    cudaGetSymbolAddress((void**)&p_aggI, g_aggI);
    cudaGetSymbolAddress((void**)&p_wth,  g_wth);
    cudaGetSymbolAddress((void**)&p_bias, g_bias);
    cudaGetSymbolAddress((void**)&p_off,  g_off);
    cudaGetSymbolAddress((void**)&p_cmpU, g_cmpU);
    cudaGetSymbolAddress((void**)&p_cmpI, g_cmpI);

    const int* p_cntU = p_off + 3 * (N_USER + 1) + N_USER;   // g_off[3][N_USER]
    const int* p_cntI = p_off + 4 * (N_USER + 1) + N_ITEM;   // g_off[4][N_ITEM]

    const int smem_bytes = 3 * STAGEB;   // 107520
    cudaFuncSetAttribute(gemm_ln_kernel,
                         cudaFuncAttributeMaxDynamicSharedMemorySize, smem_bytes);

    // --- CSR + pruning chain (counts/bflag/ticket are pre-zeroed invariantly) ---
    flag_kernel<<<(N_TGT + 255) / 256, 256>>>(target_ids);
    count_prep_kernel<<<CBLK + PBLK, 256>>>(dst_buys,
                                            dst_rev, src_rev,
                                            dst_fol, src_fol,
                                            emb_user, emb_item, Wl, Wr, bl);
    scan_kernel<<<SCAN_BLOCKS, 1024>>>();
    fill_all_kernel<<<(3 * NE4 + 255) / 256, 256>>>(dst_buys, src_buys,
                                                    dst_rev, src_rev,
                                                    dst_fol, src_fol);

    // ===== layer 0 (pruned to needed nodes) =====
    {
        int nwarp = N_ITEM + 2 * N_USER;
        agg_l0_kernel<<<(nwarp * 32 + 255) / 256, 256>>>(p_eu16, p_ei16);

        GemmJob ji, ju;
        ji.out = p_xi0h; ji.A0 = p_ei16; ji.A1 = p_aggI;
        ji.ridx0 = p_cmpI; ji.ridx1 = p_cmpI; ji.ridxo = p_cmpI; ji.cnt = p_cntI;
        ji.Wt = p_wth; ji.bias = p_bias;
        ji.gam = ln_g + 1 * H; ji.bet = ln_b + 1 * H;
        ji.lda0 = H; ji.lda1 = H; ji.k0c = 2; ji.nchunk = 4; ji.nrows = N_ITEM;

        ju.out = p_xu0h; ju.A0 = p_eu16; ju.A1 = p_aggU;
        ju.ridx0 = p_cmpU; ju.ridx1 = p_cmpU; ju.ridxo = p_cmpU; ju.cnt = p_cntU;
        ju.Wt = p_wth + 128 * H; ju.bias = p_bias + 1 * H;
        ju.gam = ln_g + 0 * H; ju.bet = ln_b + 0 * H;
        ju.lda0 = H; ju.lda1 = 256; ju.k0c = 2; ju.nchunk = 6; ju.nrows = N_USER;

        int nbi = (N_ITEM + 127) / 128;
        int nbu = (N_USER + 127) / 128;
        gemm_ln_kernel<<<nbi + nbu, 256, smem_bytes>>>(ji, ju, nbi);
    }
    // ===== layer 1: only target rows =====
    {
        agg_tgt_kernel<<<(2 * N_TGT * 32 + 255) / 256, 256>>>(p_xi0h, p_xu0h, target_ids);

        GemmJob jt;
        jt.out = p_xufh; jt.A0 = p_xu0h; jt.A1 = p_aggU;
        jt.ridx0 = target_ids; jt.ridx1 = nullptr; jt.ridxo = nullptr; jt.cnt = nullptr;
        jt.Wt = p_wth + (128 + 192) * H; jt.bias = p_bias + 2 * H;
        jt.gam = ln_g + 2 * H; jt.bet = ln_b + 2 * H;
        jt.lda0 = H; jt.lda1 = 256; jt.k0c = 2; jt.nchunk = 6; jt.nrows = N_TGT;

        int nbt = N_TGT / 128;
        gemm_ln_kernel<<<nbt, 256, smem_bytes>>>(jt, jt, nbt);
    }

    mlp_kernel<<<MLP_BLK + ZBLK, 256>>>(p_xufh, W1, b1, W2, b2, out);
}

// round 11
// speedup vs baseline: 5.2971x; 1.0292x over previous
#include <cuda_runtime.h>
#include <cuda_fp16.h>
#include <cstdint>

#define N_USER 100000
#define N_ITEM 50000
#define NE     800000
#define NE4    (NE / 4)
#define H      128
#define N_TGT  8192

// ---------------------------------------------------------------------------
// Static device scratch (fp16 feature world)
// ---------------------------------------------------------------------------
__device__ __half g_eu16[N_USER * H];
__device__ __half g_ei16[N_ITEM * H];
__device__ __half g_xu0h[N_USER * H];
__device__ __half g_xi0h[N_ITEM * H];
__device__ __half g_xufh[N_TGT * H];
__device__ __half g_aggU[N_USER * 256];     // layer0: [mrev|mfol]; layer1: compact rows
__device__ __half g_aggI[N_ITEM * H];
__device__ unsigned g_wth[(128 + 192 + 192) * H];
__device__ float g_bias[3 * H];

// CSR + scan scratch. scan rows: 0..2 = graph degree counts, 3 = needU, 4 = needI
// INVARIANT: g_cnt / g_bflag / g_ticket / bit arrays are ZERO at entry of every
// call (zero-initialized at load; re-zeroed by tail blocks of mlp each call).
__device__ int g_cnt[3][N_USER + 1];
__device__ int g_off[5][N_USER + 1];
__device__ int g_cur[3][N_USER];
__device__ int g_csr[3][NE];
__device__ int g_bsum[5][128];
__device__ int g_bflag[5 * 128];
__device__ int g_ticket;

// pruning flags as BITMASKS (L1-resident: 12.5KB / 12.5KB / 6.25KB)
#define TB_W 4096   // words for 100000 user bits (131072 bits)
#define IB_W 2048   // words for 50000 item bits
__device__ int g_tbits[TB_W];
__device__ int g_nUbits[TB_W];
__device__ int g_nIbits[IB_W];

__device__ int g_cmpU[N_USER];
__device__ int g_cmpI[N_ITEM];

// graph ids: 0 = buys (dst=item), 1 = rev (dst=user), 2 = fol (dst=user)

__device__ __forceinline__ int getbit(const int* a, int i) {
    return (a[i >> 5] >> (i & 31)) & 1;
}
__device__ __forceinline__ void setbit(int* a, int i) {
    int w = i >> 5, m = 1 << (i & 31);
    if (!(a[w] & m)) atomicOr(&a[w], m);   // idempotent; stale pre-check harmless
}

__device__ __forceinline__ unsigned smem_u32(const void* p) {
    return (unsigned)__cvta_generic_to_shared(p);
}
#define CP16(dst, src, sz) \
    asm volatile("cp.async.cg.shared.global [%0], [%1], 16, %2;\n" \
                 :: "r"(dst), "l"(src), "r"(sz))

// ---------------------------------------------------------------------------
// K1: flag targets (tiny)
// ---------------------------------------------------------------------------
__global__ void flag_kernel(const int* __restrict__ tgt) {
    int i = blockIdx.x * blockDim.x + threadIdx.x;
    if (i < N_TGT) {
        int t = tgt[i];
        setbit(g_tbits, t);
        setbit(g_nUbits, t);
    }
}

// ---------------------------------------------------------------------------
// K2: fused [degree count + need flags] ++ [emb->fp16 + weight/bias prep]
// ---------------------------------------------------------------------------
#define NU8   (N_USER * H / 8)
#define NI8   (N_ITEM * H / 8)
#define WTOT  ((128 + 192 + 192) * H)
#define PREPN (NU8 + NI8 + WTOT + 3 * H)
#define CBLK  ((3 * NE4 + 255) / 256)
#define PBLK  ((PREPN + 255) / 256)

__device__ __forceinline__ uint4 pack8(float4 a, float4 b) {
    __half2 h0 = __floats2half2_rn(a.x, a.y);
    __half2 h1 = __floats2half2_rn(a.z, a.w);
    __half2 h2 = __floats2half2_rn(b.x, b.y);
    __half2 h3 = __floats2half2_rn(b.z, b.w);
    uint4 u;
    u.x = *(unsigned*)&h0; u.y = *(unsigned*)&h1;
    u.z = *(unsigned*)&h2; u.w = *(unsigned*)&h3;
    return u;
}
__device__ __forceinline__ float wval_item(const float* Wl, const float* Wr, int k, int j) {
    return (k < 128) ? Wr[(0 * H + j) * H + k] : Wl[(0 * H + j) * H + (k - 128)];
}
__device__ __forceinline__ float wval_user(const float* Wl, const float* Wr, int l, int k, int j) {
    if (k < 128) return Wr[((l * 3 + 1) * H + j) * H + k] + Wr[((l * 3 + 2) * H + j) * H + k];
    if (k < 256) return Wl[((l * 3 + 1) * H + j) * H + (k - 128)];
    return Wl[((l * 3 + 2) * H + j) * H + (k - 256)];
}

__global__ void count_prep_kernel(const int* __restrict__ d0,
                                  const int* __restrict__ d1, const int* __restrict__ s1,
                                  const int* __restrict__ d2, const int* __restrict__ s2,
                                  const float* __restrict__ eu, const float* __restrict__ ei,
                                  const float* __restrict__ Wl, const float* __restrict__ Wr,
                                  const float* __restrict__ bl) {
    if (blockIdx.x < CBLK) {
        int i = blockIdx.x * blockDim.x + threadIdx.x;
        if (i >= 3 * NE4) return;
        int g = i / NE4, j = i % NE4;
        if (g == 0) {
            int4 v = ((const int4*)d0)[j];
            atomicAdd(&g_cnt[0][v.x], 1);
            atomicAdd(&g_cnt[0][v.y], 1);
            atomicAdd(&g_cnt[0][v.z], 1);
            atomicAdd(&g_cnt[0][v.w], 1);
        } else if (g == 1) {
            int4 d = ((const int4*)d1)[j];
            int4 s = ((const int4*)s1)[j];
            atomicAdd(&g_cnt[1][d.x], 1);
            atomicAdd(&g_cnt[1][d.y], 1);
            atomicAdd(&g_cnt[1][d.z], 1);
            atomicAdd(&g_cnt[1][d.w], 1);
            if (getbit(g_tbits, d.x)) setbit(g_nIbits, s.x);
            if (getbit(g_tbits, d.y)) setbit(g_nIbits, s.y);
            if (getbit(g_tbits, d.z)) setbit(g_nIbits, s.z);
            if (getbit(g_tbits, d.w)) setbit(g_nIbits, s.w);
        } else {
            int4 d = ((const int4*)d2)[j];
            int4 s = ((const int4*)s2)[j];
            atomicAdd(&g_cnt[2][d.x], 1);
            atomicAdd(&g_cnt[2][d.y], 1);
            atomicAdd(&g_cnt[2][d.z], 1);
            atomicAdd(&g_cnt[2][d.w], 1);
            if (getbit(g_tbits, d.x)) setbit(g_nUbits, s.x);
            if (getbit(g_tbits, d.y)) setbit(g_nUbits, s.y);
            if (getbit(g_tbits, d.z)) setbit(g_nUbits, s.z);
            if (getbit(g_tbits, d.w)) setbit(g_nUbits, s.w);
        }
        return;
    }
    // ---- prep part ----
    int i = (blockIdx.x - CBLK) * blockDim.x + threadIdx.x;
    if (i < NU8) {
        float4 a = ((const float4*)eu)[2 * i], b = ((const float4*)eu)[2 * i + 1];
        ((uint4*)g_eu16)[i] = pack8(a, b);
        return;
    }
    int j = i - NU8;
    if (j < NI8) {
        float4 a = ((const float4*)ei)[2 * j], b = ((const float4*)ei)[2 * j + 1];
        ((uint4*)g_ei16)[j] = pack8(a, b);
        return;
    }
    j -= NI8;
    if (j < WTOT) {
        float v0, v1;
        if (j < 128 * H) {
            int k2 = j >> 7, c = j & 127;
            v0 = wval_item(Wl, Wr, 2 * k2, c);
            v1 = wval_item(Wl, Wr, 2 * k2 + 1, c);
        } else {
            int rel = j - 128 * H;
            int l = (rel < 192 * H) ? 0 : 1;
            if (l == 1) rel -= 192 * H;
            int k2 = rel >> 7, c = rel & 127;
            v0 = wval_user(Wl, Wr, l, 2 * k2, c);
            v1 = wval_user(Wl, Wr, l, 2 * k2 + 1, c);
        }
        __half2 h = __floats2half2_rn(v0, v1);
        g_wth[j] = *(unsigned*)&h;
        return;
    }
    j -= WTOT;
    if (j < 3 * H) {
        int slot = j >> 7, c = j & 127;
        float b;
        if (slot == 0)      b = bl[0 * H + c];
        else if (slot == 1) b = bl[1 * H + c] + bl[2 * H + c];
        else                b = bl[(3 + 1) * H + c] + bl[(3 + 2) * H + c];
        g_bias[j] = b;
    }
}

// ---------------------------------------------------------------------------
// K3: single-pass scan over 5 rows with ticket-ordered parallel lookback.
// ---------------------------------------------------------------------------
#define NB_I 49
#define NB_U 98
#define SCAN_BLOCKS (NB_I + NB_U + NB_U + NB_U + NB_I)

__device__ __forceinline__ int scan_n(int g) {
    return (g == 0 || g == 4) ? N_ITEM : N_USER;
}

__global__ void scan_kernel() {
    __shared__ int s_g, s_b;
    __shared__ int warp_sums[32];
    __shared__ int sw[4];
    __shared__ int s_base;

    if (threadIdx.x == 0) {
        int v = atomicAdd(&g_ticket, 1);
        int g, b;
        if (v < NB_I)                         { g = 0; b = v; }
        else if (v < NB_I + NB_U)             { g = 1; b = v - NB_I; }
        else if (v < NB_I + 2 * NB_U)         { g = 2; b = v - NB_I - NB_U; }
        else if (v < NB_I + 3 * NB_U)         { g = 3; b = v - NB_I - 2 * NB_U; }
        else                                  { g = 4; b = v - NB_I - 3 * NB_U; }
        s_g = g; s_b = b;
    }
    __syncthreads();
    int g = s_g, b = s_b;
    int n = scan_n(g);
    int nb = (g == 0 || g == 4) ? NB_I : NB_U;

    int i = b * 1024 + (int)threadIdx.x;
    int v;
    if (i >= n) v = 0;
    else if (g < 3) v = g_cnt[g][i];
    else if (g == 3) v = getbit(g_nUbits, i);
    else v = getbit(g_nIbits, i);

    int lane = threadIdx.x & 31, wid = threadIdx.x >> 5;
    int x = v;
    #pragma unroll
    for (int s = 1; s < 32; s <<= 1) {
        int y = __shfl_up_sync(0xffffffffu, x, s);
        if (lane >= s) x += y;
    }
    if (lane == 31) warp_sums[wid] = x;
    __syncthreads();
    if (wid == 0) {
        int w = warp_sums[lane];
        int xw = w;
        #pragma unroll
        for (int s = 1; s < 32; s <<= 1) {
            int y = __shfl_up_sync(0xffffffffu, xw, s);
            if (lane >= s) xw += y;
        }
        warp_sums[lane] = xw - w;
    }
    __syncthreads();
    int incl = x + warp_sums[wid];

    if (threadIdx.x == 1023) {
        g_bsum[g][b] = incl;
        __threadfence();
        atomicExch(&g_bflag[g * 128 + b], 1);
    }

    if (threadIdx.x < 128) {
        int j = threadIdx.x;
        int pv = 0;
        if (j < b) {
            while (atomicAdd(&g_bflag[g * 128 + j], 0) == 0) { }
            pv = g_bsum[g][j];
        }
        #pragma unroll
        for (int o = 16; o; o >>= 1) pv += __shfl_xor_sync(0xffffffffu, pv, o);
        if (lane == 0) sw[j >> 5] = pv;
    }
    __syncthreads();
    if (threadIdx.x == 0) s_base = sw[0] + sw[1] + sw[2] + sw[3];
    __syncthreads();
    int base = s_base;

    if (threadIdx.x == 1023 && b == nb - 1) g_off[g][n] = base + incl;
    if (i >= n) return;
    int val = base + incl - v;
    if (g < 3) {
        g_off[g][i] = val;
        g_cur[g][i] = val;
    } else if (g == 3) {
        if (v) g_cmpU[val] = i;
    } else {
        if (v) g_cmpI[val] = i;
    }
}

// ---------------------------------------------------------------------------
// K4: filtered fill — only edges whose dst node is ever read downstream.
// ---------------------------------------------------------------------------
__global__ void fill_all_kernel(const int* __restrict__ d0, const int* __restrict__ s0,
                                const int* __restrict__ d1, const int* __restrict__ s1,
                                const int* __restrict__ d2, const int* __restrict__ s2) {
    int i = blockIdx.x * blockDim.x + threadIdx.x;
    if (i >= 3 * NE4) return;
    int g = i / NE4, j = i % NE4;
    const int* d = (g == 0) ? d0 : (g == 1) ? d1 : d2;
    const int* s = (g == 0) ? s0 : (g == 1) ? s1 : s2;
    const int* need = (g == 0) ? g_nIbits : g_nUbits;
    int4 dv = ((const int4*)d)[j];
    int4 sv = ((const int4*)s)[j];
    if (getbit(need, dv.x)) g_csr[g][atomicAdd(&g_cur[g][dv.x], 1)] = sv.x;
    if (getbit(need, dv.y)) g_csr[g][atomicAdd(&g_cur[g][dv.y], 1)] = sv.y;
    if (getbit(need, dv.z)) g_csr[g][atomicAdd(&g_cur[g][dv.z], 1)] = sv.z;
    if (getbit(need, dv.w)) g_csr[g][atomicAdd(&g_cur[g][dv.w], 1)] = sv.w;
}

// ---------------------------------------------------------------------------
// Gather-mean over fp16 rows (fp32 accumulate, strict index order).
// ---------------------------------------------------------------------------
__device__ __forceinline__ void acc4(float4& a, uint2 u) {
    __half2 h0 = *(__half2*)&u.x, h1 = *(__half2*)&u.y;
    float2 f0 = __half22float2(h0), f1 = __half22float2(h1);
    a.x += f0.x; a.y += f0.y; a.z += f1.x; a.w += f1.y;
}

__device__ __forceinline__ void agg_one(int g, int node, int lane,
                                        const __half* __restrict__ src,
                                        __half* __restrict__ dst) {
    int s = g_off[g][node], e = g_off[g][node + 1];
    const int* lst = g_csr[g];
    float4 acc = make_float4(0.f, 0.f, 0.f, 0.f);
    int i = s;
    for (; i + 8 <= e; i += 8) {
        uint2 v0 = *(const uint2*)(src + (size_t)lst[i]     * H + lane * 4);
        uint2 v1 = *(const uint2*)(src + (size_t)lst[i + 1] * H + lane * 4);
        uint2 v2 = *(const uint2*)(src + (size_t)lst[i + 2] * H + lane * 4);
        uint2 v3 = *(const uint2*)(src + (size_t)lst[i + 3] * H + lane * 4);
        uint2 v4 = *(const uint2*)(src + (size_t)lst[i + 4] * H + lane * 4);
        uint2 v5 = *(const uint2*)(src + (size_t)lst[i + 5] * H + lane * 4);
        uint2 v6 = *(const uint2*)(src + (size_t)lst[i + 6] * H + lane * 4);
        uint2 v7 = *(const uint2*)(src + (size_t)lst[i + 7] * H + lane * 4);
        acc4(acc, v0); acc4(acc, v1); acc4(acc, v2); acc4(acc, v3);
        acc4(acc, v4); acc4(acc, v5); acc4(acc, v6); acc4(acc, v7);
    }
    for (; i + 4 <= e; i += 4) {
        uint2 v0 = *(const uint2*)(src + (size_t)lst[i]     * H + lane * 4);
        uint2 v1 = *(const uint2*)(src + (size_t)lst[i + 1] * H + lane * 4);
        uint2 v2 = *(const uint2*)(src + (size_t)lst[i + 2] * H + lane * 4);
        uint2 v3 = *(const uint2*)(src + (size_t)lst[i + 3] * H + lane * 4);
        acc4(acc, v0); acc4(acc, v1); acc4(acc, v2); acc4(acc, v3);
    }
    for (; i < e; i++) {
        uint2 v0 = *(const uint2*)(src + (size_t)lst[i] * H + lane * 4);
        acc4(acc, v0);
    }
    float inv = (e > s) ? 1.0f / (float)(e - s) : 0.0f;
    __half2 o0 = __floats2half2_rn(acc.x * inv, acc.y * inv);
    __half2 o1 = __floats2half2_rn(acc.z * inv, acc.w * inv);
    uint2 o; o.x = *(unsigned*)&o0; o.y = *(unsigned*)&o1;
    *(uint2*)(dst + lane * 4) = o;
}

// Layer-0 aggregation, pruned: only needed items/users (compact lists).
__global__ void agg_l0_kernel(const __half* __restrict__ eu,
                              const __half* __restrict__ ei) {
    int warp = (blockIdx.x * blockDim.x + threadIdx.x) >> 5;
    int lane = threadIdx.x & 31;
    if (warp < N_ITEM) {
        int nI = __ldg(&g_off[4][N_ITEM]);
        if (warp >= nI) return;
        int node = g_cmpI[warp];
        agg_one(0, node, lane, eu, g_aggI + (size_t)node * H);
    } else {
        int w2 = warp - N_ITEM;
        int nU = __ldg(&g_off[3][N_USER]);
        if (w2 < N_USER) {
            if (w2 >= nU) return;
            int node = g_cmpU[w2];
            agg_one(1, node, lane, ei, g_aggU + (size_t)node * 256);
        } else {
            w2 -= N_USER;
            if (w2 >= N_USER || w2 >= nU) return;
            int node = g_cmpU[w2];
            agg_one(2, node, lane, eu, g_aggU + (size_t)node * 256 + 128);
        }
    }
}

// Layer-1 aggregation: ONLY target users (compact rows 0..N_TGT-1).
__global__ void agg_tgt_kernel(const __half* __restrict__ xi0,
                               const __half* __restrict__ xu0,
                               const int* __restrict__ tgt) {
    int warp = (blockIdx.x * blockDim.x + threadIdx.x) >> 5;
    int lane = threadIdx.x & 31;
    if (warp >= 2 * N_TGT) return;
    int pos = warp & (N_TGT - 1);
    int node = tgt[pos];
    if (warp < N_TGT)
        agg_one(1, node, lane, xi0, g_aggU + (size_t)pos * 256);
    else
        agg_one(2, node, lane, xu0, g_aggU + (size_t)pos * 256 + 128);
}

// ---------------------------------------------------------------------------
// FP16 tensor-core GEMM (cp.async 3-stage) + fused LayerNorm + ReLU, fp16 out.
// ---------------------------------------------------------------------------
#define ASTRIDE 36
#define WSTRIDE 136
#define OSTRIDE 132
#define STAGEB  35840

extern __shared__ char g_smraw[];

struct GemmJob {
    __half* out;
    const __half* A0;
    const __half* A1;
    const int* ridx0;
    const int* ridx1;
    const int* ridxo;
    const int* cnt;
    const unsigned* Wt;
    const float* bias;
    const float* gam;
    const float* bet;
    int lda0, lda1, k0c, nchunk, nrows;
};

__device__ __forceinline__ void mma_f16(float c[4], const unsigned a[4], const unsigned b[2]) {
    asm volatile(
        "mma.sync.aligned.m16n8k16.row.col.f32.f16.f16.f32 "
        "{%0,%1,%2,%3}, {%4,%5,%6,%7}, {%8,%9}, {%0,%1,%2,%3};"
        : "+f"(c[0]), "+f"(c[1]), "+f"(c[2]), "+f"(c[3])
        : "r"(a[0]), "r"(a[1]), "r"(a[2]), "r"(a[3]), "r"(b[0]), "r"(b[1]));
}

__global__ void __launch_bounds__(256, 2) gemm_ln_kernel(GemmJob j0, GemmJob j1, int split) {
    GemmJob J = (blockIdx.x < (unsigned)split) ? j0 : j1;
    int bid = (blockIdx.x < (unsigned)split) ? blockIdx.x : blockIdx.x - split;
    int row0 = bid * 128;

    int nrows = J.cnt ? __ldg(J.cnt) : J.nrows;
    if (row0 >= nrows) return;

    int t = threadIdx.x;
    int lane = t & 31;
    int wid = t >> 5;
    int warp_m = wid & 3;
    int warp_n = wid >> 2;
    int gid = lane >> 2;
    int tig = lane & 3;

    float c[2][8][4];
    #pragma unroll
    for (int nt = 0; nt < 8; nt++) {
        int col = warp_n * 64 + nt * 8 + 2 * tig;
        float b0 = J.bias[col], b1 = J.bias[col + 1];
        #pragma unroll
        for (int mt = 0; mt < 2; mt++) {
            c[mt][nt][0] = b0; c[mt][nt][1] = b1;
            c[mt][nt][2] = b0; c[mt][nt][3] = b1;
        }
    }

    auto load_chunk = [&](int ck, int st) {
        if (ck < J.nchunk) {
            const __half* A; int lda, cb; const int* ridx;
            if (ck < J.k0c) { A = J.A0; lda = J.lda0; cb = ck * 64; ridx = J.ridx0; }
            else            { A = J.A1; lda = J.lda1; cb = (ck - J.k0c) * 64; ridx = J.ridx1; }
            unsigned* As = (unsigned*)(g_smraw + st * STAGEB);
            #pragma unroll
            for (int i2 = 0; i2 < 4; i2++) {
                int idx = t + 256 * i2;
                int r = idx >> 3, u = idx & 7;
                int base = row0 + r;
                int ok = (base < nrows);
                if (!ok) base = row0;
                int row = ridx ? __ldg(ridx + base) : base;
                const __half* src = A + (size_t)row * lda + cb + u * 8;
                CP16(smem_u32(As + r * ASTRIDE + u * 4), src, ok ? 16 : 0);
            }
            unsigned* Ws = (unsigned*)(g_smraw + st * STAGEB + 128 * ASTRIDE * 4);
            #pragma unroll
            for (int i2 = 0; i2 < 4; i2++) {
                int idx = t + 256 * i2;
                int rr = idx >> 5, u = idx & 31;
                const unsigned* src = J.Wt + (size_t)(ck * 32 + rr) * H + u * 4;
                CP16(smem_u32(Ws + rr * WSTRIDE + u * 4), src, 16);
            }
        }
        asm volatile("cp.async.commit_group;\n" ::);
    };

    load_chunk(0, 0);
    load_chunk(1, 1);

    for (int ck = 0; ck < J.nchunk; ck++) {
        asm volatile("cp.async.wait_group 1;\n" ::);
        __syncthreads();
        load_chunk(ck + 2, (ck + 2) % 3);

        int st = ck % 3;
        const unsigned* As = (const unsigned*)(g_smraw + st * STAGEB);
        const unsigned* Ws = (const unsigned*)(g_smraw + st * STAGEB + 128 * ASTRIDE * 4);
        #pragma unroll
        for (int ks = 0; ks < 4; ks++) {
            int k2 = ks * 8;
            unsigned a[2][4];
            #pragma unroll
            for (int mt = 0; mt < 2; mt++) {
                int r = warp_m * 32 + mt * 16 + gid;
                a[mt][0] = As[r * ASTRIDE + k2 + tig];
                a[mt][1] = As[(r + 8) * ASTRIDE + k2 + tig];
                a[mt][2] = As[r * ASTRIDE + k2 + tig + 4];
                a[mt][3] = As[(r + 8) * ASTRIDE + k2 + tig + 4];
            }
            unsigned b[8][2];
            #pragma unroll
            for (int nt = 0; nt < 8; nt++) {
                int cc = warp_n * 64 + nt * 8 + gid;
                b[nt][0] = Ws[(k2 + tig) * WSTRIDE + cc];
                b[nt][1] = Ws[(k2 + tig + 4) * WSTRIDE + cc];
            }
            #pragma unroll
            for (int mt = 0; mt < 2; mt++)
                #pragma unroll
                for (int nt = 0; nt < 8; nt++)
                    mma_f16(c[mt][nt], a[mt], b[nt]);
        }
    }

    // ---- epilogue: stage fp32 to smem, fused LayerNorm + ReLU, fp16 out ----
    asm volatile("cp.async.wait_group 0;\n" ::);
    __syncthreads();
    float* Osm = (float*)g_smraw;
    #pragma unroll
    for (int mt = 0; mt < 2; mt++) {
        #pragma unroll
        for (int nt = 0; nt < 8; nt++) {
            int col = warp_n * 64 + nt * 8 + 2 * tig;
            int r = warp_m * 32 + mt * 16 + gid;
            *(float2*)(Osm + r * OSTRIDE + col)       = make_float2(c[mt][nt][0], c[mt][nt][1]);
            *(float2*)(Osm + (r + 8) * OSTRIDE + col) = make_float2(c[mt][nt][2], c[mt][nt][3]);
        }
    }
    __syncthreads();

    float4 gg = *(const float4*)(J.gam + lane * 4);
    float4 bb = *(const float4*)(J.bet + lane * 4);
    #pragma unroll
    for (int i = 0; i < 16; i++) {
        int r = wid * 16 + i;
        int base = row0 + r;
        if (base >= nrows) break;
        float4 v = *(float4*)(Osm + r * OSTRIDE + lane * 4);
        float s1 = v.x + v.y + v.z + v.w;
        float s2 = v.x * v.x + v.y * v.y + v.z * v.z + v.w * v.w;
        #pragma unroll
        for (int o = 16; o; o >>= 1) {
            s1 += __shfl_xor_sync(0xffffffffu, s1, o);
            s2 += __shfl_xor_sync(0xffffffffu, s2, o);
        }
        float mu = s1 * (1.0f / H);
        float var = s2 * (1.0f / H) - mu * mu;
        float rs = rsqrtf(var + 1e-5f);
        float ox = fmaxf((v.x - mu) * rs * gg.x + bb.x, 0.f);
        float oy = fmaxf((v.y - mu) * rs * gg.y + bb.y, 0.f);
        float oz = fmaxf((v.z - mu) * rs * gg.z + bb.z, 0.f);
        float ow = fmaxf((v.w - mu) * rs * gg.w + bb.w, 0.f);
        __half2 h0 = __floats2half2_rn(ox, oy);
        __half2 h1 = __floats2half2_rn(oz, ow);
        uint2 o; o.x = *(unsigned*)&h0; o.y = *(unsigned*)&h1;
        int orow = J.ridxo ? __ldg(J.ridxo + base) : base;
        *(uint2*)(J.out + (size_t)orow * H + lane * 4) = o;
    }
}

// ---------------------------------------------------------------------------
// K-last: MLP head (W1/b1/W2 staged in smem; 2 targets per warp)
//         + tail blocks re-zero g_cnt/g_bflag/g_ticket/bit arrays.
// ---------------------------------------------------------------------------
#define MLP_BLK (N_TGT / 16)              // 512 blocks, 8 warps x 2 targets
#define ZCNT  (3 * (N_USER + 1))
#define ZTOT  (ZCNT + 5 * 128 + 1 + TB_W + TB_W + IB_W)
#define ZBLK  ((ZTOT + 255) / 256)

__global__ void mlp_kernel(const __half* __restrict__ xuc,
                           const float* __restrict__ W1, const float* __restrict__ b1,
                           const float* __restrict__ W2, const float* __restrict__ b2,
                           float* __restrict__ out) {
    if (blockIdx.x >= MLP_BLK) {
        // tail: restore the zero-invariant for the next call
        int i = (blockIdx.x - MLP_BLK) * blockDim.x + threadIdx.x;
        if (i < ZCNT) { ((int*)g_cnt)[i] = 0; return; }
        int j = i - ZCNT;
        if (j < 5 * 128) { g_bflag[j] = 0; return; }
        j -= 5 * 128;
        if (j < 1) { g_ticket = 0; return; }
        j -= 1;
        if (j < TB_W) { g_tbits[j] = 0; return; }
        j -= TB_W;
        if (j < TB_W) { g_nUbits[j] = 0; return; }
        j -= TB_W;
        if (j < IB_W) g_nIbits[j] = 0;
        return;
    }

    __shared__ float sW1[64 * H];
    __shared__ float sC[128];             // [0:64) b1, [64:128) W2
    int t = threadIdx.x;
    #pragma unroll
    for (int i = 0; i < 8; i++)
        ((float4*)sW1)[t + 256 * i] = ((const float4*)W1)[t + 256 * i];
    if (t < 64) { sC[t] = b1[t]; sC[64 + t] = W2[t]; }
    __syncthreads();

    int lane = t & 31;
    int warp = blockIdx.x * 8 + (t >> 5);
    int t0 = warp * 2;
    uint2 xra = *(const uint2*)(xuc + (size_t)t0 * H + lane * 4);
    uint2 xrb = *(const uint2*)(xuc + (size_t)(t0 + 1) * H + lane * 4);
    float2 a0 = __half22float2(*(__half2*)&xra.x);
    float2 a1 = __half22float2(*(__half2*)&xra.y);
    float2 c0 = __half22float2(*(__half2*)&xrb.x);
    float2 c1 = __half22float2(*(__half2*)&xrb.y);
    float accA = 0.f, accB = 0.f;
    #pragma unroll 4
    for (int j = 0; j < 64; j++) {
        float4 w = *(const float4*)(sW1 + j * H + lane * 4);
        float pA = a0.x * w.x + a0.y * w.y + a1.x * w.z + a1.y * w.w;
        float pB = c0.x * w.x + c0.y * w.y + c1.x * w.z + c1.y * w.w;
        #pragma unroll
        for (int o = 16; o; o >>= 1) {
            pA += __shfl_xor_sync(0xffffffffu, pA, o);
            pB += __shfl_xor_sync(0xffffffffu, pB, o);
        }
        float bj = sC[j], wj = sC[64 + j];
        accA += fmaxf(pA + bj, 0.f) * wj;
        accB += fmaxf(pB + bj, 0.f) * wj;
    }
    if (lane == 0) {
        float bb2 = b2[0];
        out[t0]     = accA + bb2;
        out[t0 + 1] = accB + bb2;
    }
}

// ---------------------------------------------------------------------------
// Launch
// ---------------------------------------------------------------------------
extern "C" void kernel_launch(void* const* d_in, const int* in_sizes, int n_in,
                              void* d_out, int out_size) {
    const float* emb_user = (const float*)d_in[0];
    const float* emb_item = (const float*)d_in[1];
    const float* Wl       = (const float*)d_in[2];
    const float* bl       = (const float*)d_in[3];
    const float* Wr       = (const float*)d_in[4];
    const float* ln_g     = (const float*)d_in[5];
    const float* ln_b     = (const float*)d_in[6];
    const float* W1       = (const float*)d_in[7];
    const float* b1       = (const float*)d_in[8];
    const float* W2       = (const float*)d_in[9];
    const float* b2       = (const float*)d_in[10];
    const int* src_buys   = (const int*)d_in[11];
    const int* dst_buys   = (const int*)d_in[12];
    const int* src_rev    = (const int*)d_in[13];
    const int* dst_rev    = (const int*)d_in[14];
    const int* src_fol    = (const int*)d_in[15];
    const int* dst_fol    = (const int*)d_in[16];
    const int* target_ids = (const int*)d_in[17];
    float* out = (float*)d_out;

    __half *p_eu16, *p_ei16, *p_xu0h, *p_xi0h, *p_xufh, *p_aggU, *p_aggI;
    unsigned* p_wth;
    float* p_bias;
    int *p_off, *p_cmpU, *p_cmpI;
    cudaGetSymbolAddress((void**)&p_eu16, g_eu16);
    cudaGetSymbolAddress((void**)&p_ei16, g_ei16);
    cudaGetSymbolAddress((void**)&p_xu0h, g_xu0h);
    cudaGetSymbolAddress((void**)&p_xi0h, g_xi0h);
    cudaGetSymbolAddress((void**)&p_xufh, g_xufh);
    cudaGetSymbolAddress((void**)&p_aggU, g_aggU);
    cudaGetSymbolAddress((void**)&p_aggI, g_aggI);
    cudaGetSymbolAddress((void**)&p_wth,  g_wth);
    cudaGetSymbolAddress((void**)&p_bias, g_bias);
    cudaGetSymbolAddress((void**)&p_off,  g_off);
    cudaGetSymbolAddress((void**)&p_cmpU, g_cmpU);
    cudaGetSymbolAddress((void**)&p_cmpI, g_cmpI);

    const int* p_cntU = p_off + 3 * (N_USER + 1) + N_USER;   // g_off[3][N_USER]
    const int* p_cntI = p_off + 4 * (N_USER + 1) + N_ITEM;   // g_off[4][N_ITEM]

    const int smem_bytes = 3 * STAGEB;   // 107520
    cudaFuncSetAttribute(gemm_ln_kernel,
                         cudaFuncAttributeMaxDynamicSharedMemorySize, smem_bytes);

    // --- CSR + pruning chain (scratch pre-zeroed invariantly) ---
    flag_kernel<<<(N_TGT + 255) / 256, 256>>>(target_ids);
    count_prep_kernel<<<CBLK + PBLK, 256>>>(dst_buys,
                                            dst_rev, src_rev,
                                            dst_fol, src_fol,
                                            emb_user, emb_item, Wl, Wr, bl);
    scan_kernel<<<SCAN_BLOCKS, 1024>>>();
    fill_all_kernel<<<(3 * NE4 + 255) / 256, 256>>>(dst_buys, src_buys,
                                                    dst_rev, src_rev,
                                                    dst_fol, src_fol);

    // ===== layer 0 (pruned to needed nodes) =====
    {
        int nwarp = N_ITEM + 2 * N_USER;
        agg_l0_kernel<<<(nwarp * 32 + 255) / 256, 256>>>(p_eu16, p_ei16);

        GemmJob ji, ju;
        ji.out = p_xi0h; ji.A0 = p_ei16; ji.A1 = p_aggI;
        ji.ridx0 = p_cmpI; ji.ridx1 = p_cmpI; ji.ridxo = p_cmpI; ji.cnt = p_cntI;
        ji.Wt = p_wth; ji.bias = p_bias;
        ji.gam = ln_g + 1 * H; ji.bet = ln_b + 1 * H;
        ji.lda0 = H; ji.lda1 = H; ji.k0c = 2; ji.nchunk = 4; ji.nrows = N_ITEM;

        ju.out = p_xu0h; ju.A0 = p_eu16; ju.A1 = p_aggU;
        ju.ridx0 = p_cmpU; ju.ridx1 = p_cmpU; ju.ridxo = p_cmpU; ju.cnt = p_cntU;
        ju.Wt = p_wth + 128 * H; ju.bias = p_bias + 1 * H;
        ju.gam = ln_g + 0 * H; ju.bet = ln_b + 0 * H;
        ju.lda0 = H; ju.lda1 = 256; ju.k0c = 2; ju.nchunk = 6; ju.nrows = N_USER;

        int nbi = (N_ITEM + 127) / 128;
        int nbu = (N_USER + 127) / 128;
        gemm_ln_kernel<<<nbi + nbu, 256, smem_bytes>>>(ji, ju, nbi);
    }
    // ===== layer 1: only target rows =====
    {
        agg_tgt_kernel<<<(2 * N_TGT * 32 + 255) / 256, 256>>>(p_xi0h, p_xu0h, target_ids);

        GemmJob jt;
        jt.out = p_xufh; jt.A0 = p_xu0h; jt.A1 = p_aggU;
        jt.ridx0 = target_ids; jt.ridx1 = nullptr; jt.ridxo = nullptr; jt.cnt = nullptr;
        jt.Wt = p_wth + (128 + 192) * H; jt.bias = p_bias + 2 * H;
        jt.gam = ln_g + 2 * H; jt.bet = ln_b + 2 * H;
        jt.lda0 = H; jt.lda1 = 256; jt.k0c = 2; jt.nchunk = 6; jt.nrows = N_TGT;

        int nbt = N_TGT / 128;
        gemm_ln_kernel<<<nbt, 256, smem_bytes>>>(jt, jt, nbt);
    }

    mlp_kernel<<<MLP_BLK + ZBLK, 256>>>(p_xufh, W1, b1, W2, b2, out);
}